// round 8
// baseline (speedup 1.0000x reference)
#include <cuda_runtime.h>
#include <cuda_bf16.h>

#define DIM 128
#define N_TOTAL 299593
#define NTOP 37449
#define NLEAF 262144

static const int H_SIZES[7] = {1, 8, 64, 512, 4096, 32768, 262144};
static const int H_OFFS[8]  = {0, 1, 9, 73, 585, 4681, 37449, 299593};

// ---------------- scratch: intermediates as bf16 hi/lo planes ----------------
__device__ __nv_bfloat16 g_agg_hi[NTOP * DIM],    g_agg_lo[NTOP * DIM];
__device__ __nv_bfloat16 g_ctx_hi[N_TOTAL * DIM], g_ctx_lo[N_TOTAL * DIM];
__device__ __nv_bfloat16 g_t2_hi [65536 * DIM],   g_t2_lo [65536 * DIM];
__device__ __nv_bfloat16 g_leaf_hi[NLEAF * DIM],  g_leaf_lo[NLEAF * DIM];
__device__ float g_cth[32768 * DIM];              // down-pass parent ctx-h (fp32, scalar reads only)

// ================= common =================
#define SPITCH 136                 // bf16 elems per smem row (272 B, 17*16)
#define STILE  (128 * SPITCH)
#define XTILE  (256 * SPITCH)
#define EPITCH 132

__device__ __forceinline__ void mma16816(float* c, const unsigned* a,
                                         unsigned b0, unsigned b1)
{
    asm volatile(
        "mma.sync.aligned.m16n8k16.row.col.f32.bf16.bf16.f32 "
        "{%0,%1,%2,%3},{%4,%5,%6,%7},{%8,%9},{%0,%1,%2,%3};\n"
        : "+f"(c[0]), "+f"(c[1]), "+f"(c[2]), "+f"(c[3])
        : "r"(a[0]), "r"(a[1]), "r"(a[2]), "r"(a[3]), "r"(b0), "r"(b1));
}

__device__ __forceinline__ void ldsm4(unsigned* r, unsigned addr)
{
    asm volatile("ldmatrix.sync.aligned.m8n8.x4.shared.b16 {%0,%1,%2,%3}, [%4];"
                 : "=r"(r[0]), "=r"(r[1]), "=r"(r[2]), "=r"(r[3]) : "r"(addr));
}

__device__ __forceinline__ void split1(float f, __nv_bfloat16& h, __nv_bfloat16& l)
{
    h = __float2bfloat16(f);
    l = __float2bfloat16(f - __bfloat162float(h));
}

__device__ __forceinline__ void split4(float4 v, uint2& hv, uint2& lv)
{
    __nv_bfloat16 h0, h1, h2, h3, l0, l1, l2, l3;
    split1(v.x, h0, l0); split1(v.y, h1, l1);
    split1(v.z, h2, l2); split1(v.w, h3, l3);
    hv.x = ((unsigned)__bfloat16_as_ushort(h1) << 16) | __bfloat16_as_ushort(h0);
    hv.y = ((unsigned)__bfloat16_as_ushort(h3) << 16) | __bfloat16_as_ushort(h2);
    lv.x = ((unsigned)__bfloat16_as_ushort(l1) << 16) | __bfloat16_as_ushort(l0);
    lv.y = ((unsigned)__bfloat16_as_ushort(l3) << 16) | __bfloat16_as_ushort(l2);
}

// ---- W staging: fp32 global -> hi/lo smem (register path, batch 8) ----
__device__ __forceinline__ void stage_w(
    const float* __restrict__ G, int gstride,
    __nv_bfloat16* sWhi, __nv_bfloat16* sWlo, int tid)
{
#pragma unroll
    for (int b = 0; b < 16; b += 8) {
        float4 v[8];
#pragma unroll
        for (int j = 0; j < 8; j++) {
            int idx = tid + (b + j) * 256;
            v[j] = *(const float4*)(G + (size_t)(idx >> 5) * gstride + (idx & 31) * 4);
        }
#pragma unroll
        for (int j = 0; j < 8; j++) {
            int idx = tid + (b + j) * 256;
            int r = idx >> 5, c4 = (idx & 31) * 4;
            uint2 hv, lv; split4(v[j], hv, lv);
            *(uint2*)(sWhi + (size_t)r * SPITCH + c4) = hv;
            *(uint2*)(sWlo + (size_t)r * SPITCH + c4) = lv;
        }
    }
}

// ---- X staging: bf16 planes -> smem via cp.async (16B chunks, zfill OOB) ----
__device__ __forceinline__ void cp16(unsigned saddr, const void* gptr, int sz)
{
    asm volatile("cp.async.cg.shared.global [%0], [%1], 16, %2;"
                 :: "r"(saddr), "l"(gptr), "r"(sz));
}

template <int NROWS>
__device__ __forceinline__ void stage_planes(
    const __nv_bfloat16* __restrict__ Ghi, const __nv_bfloat16* __restrict__ Glo,
    int rows_valid, __nv_bfloat16* sXhi, __nv_bfloat16* sXlo, int tid)
{
    unsigned shi = (unsigned)__cvta_generic_to_shared(sXhi);
    unsigned slo = (unsigned)__cvta_generic_to_shared(sXlo);
#pragma unroll
    for (int i = tid; i < NROWS * 16; i += 256) {
        int r = i >> 4, c = i & 15;
        unsigned so = (unsigned)r * (SPITCH * 2) + c * 16;
        size_t go = (size_t)r * 128 + c * 8;
        int sz = (r < rows_valid) ? 16 : 0;
        const __nv_bfloat16* ph = (r < rows_valid) ? Ghi + go : Ghi;
        const __nv_bfloat16* pl = (r < rows_valid) ? Glo + go : Glo;
        cp16(shi + so, ph, sz);
        cp16(slo + so, pl, sz);
    }
    asm volatile("cp.async.commit_group;");
    asm volatile("cp.async.wait_group 0;" ::: "memory");
}

// per-row select across two plane pairs (row<bnd -> A, else B indexed from 0)
__device__ __forceinline__ void stage_planes_sel(
    const __nv_bfloat16* __restrict__ Ahi, const __nv_bfloat16* __restrict__ Alo,
    const __nv_bfloat16* __restrict__ Bhi, const __nv_bfloat16* __restrict__ Blo,
    int bnd, int grow0, int M,
    __nv_bfloat16* sXhi, __nv_bfloat16* sXlo, int tid)
{
    unsigned shi = (unsigned)__cvta_generic_to_shared(sXhi);
    unsigned slo = (unsigned)__cvta_generic_to_shared(sXlo);
#pragma unroll
    for (int i = tid; i < 256 * 16; i += 256) {
        int r = i >> 4, c = i & 15;
        int gr = grow0 + r;
        unsigned so = (unsigned)r * (SPITCH * 2) + c * 16;
        const __nv_bfloat16 *ph = Ahi, *pl = Alo;
        int sz = 0;
        if (gr < M) {
            sz = 16;
            if (gr < bnd) {
                size_t go = (size_t)gr * 128 + c * 8;
                ph = Ahi + go; pl = Alo + go;
            } else {
                size_t go = (size_t)(gr - bnd) * 128 + c * 8;
                ph = Bhi + go; pl = Blo + go;
            }
        }
        cp16(shi + so, ph, sz);
        cp16(slo + so, pl, sz);
    }
    asm volatile("cp.async.commit_group;");
    asm volatile("cp.async.wait_group 0;" ::: "memory");
}

// sync (non-async) plane staging for intra-kernel round trips
__device__ __forceinline__ void stage_planes_sync(
    const __nv_bfloat16* __restrict__ Ghi, const __nv_bfloat16* __restrict__ Glo,
    int rows_valid, __nv_bfloat16* sXhi, __nv_bfloat16* sXlo, int tid)
{
#pragma unroll
    for (int i = tid; i < 128 * 32; i += 256) {
        int r = i >> 5, c4 = (i & 31) * 4;
        uint2 hv = make_uint2(0, 0), lv = make_uint2(0, 0);
        if (r < rows_valid) {
            hv = *(const uint2*)(Ghi + (size_t)r * 128 + c4);
            lv = *(const uint2*)(Glo + (size_t)r * 128 + c4);
        }
        *(uint2*)(sXhi + (size_t)r * SPITCH + c4) = hv;
        *(uint2*)(sXlo + (size_t)r * SPITCH + c4) = lv;
    }
}

// ---- mainloops (unchanged, verified) ----
__device__ __forceinline__ void panel_mma2_v2(
    const __nv_bfloat16* sWhi, const __nv_bfloat16* sWlo,
    const __nv_bfloat16* sXhi, const __nv_bfloat16* sXlo,
    int warp, int lane, float C[2][16][4])
{
    const unsigned wh = (unsigned)__cvta_generic_to_shared(sWhi);
    const unsigned wl = (unsigned)__cvta_generic_to_shared(sWlo);
    const unsigned xh = (unsigned)__cvta_generic_to_shared(sXhi);
    const unsigned xl = (unsigned)__cvta_generic_to_shared(sXlo);
    const unsigned PB = SPITCH * 2;
    const unsigned aoff0 = (unsigned)(warp * 32 + (lane & 15)) * PB
                         + (unsigned)((lane >> 4) & 1) * 16u;
    const unsigned boff0 = (unsigned)((lane & 7) + ((lane & 16) >> 1)) * PB
                         + ((lane & 8) ? 16u : 0u);

    for (int kc = 0; kc < 8; kc++) {
        const unsigned ka = kc * 32;
        unsigned ah0[4], ah1[4], al0[4], al1[4];
        ldsm4(ah0, xh + aoff0 + ka);
        ldsm4(ah1, xh + aoff0 + 16 * PB + ka);
        ldsm4(al0, xl + aoff0 + ka);
        ldsm4(al1, xl + aoff0 + 16 * PB + ka);

        unsigned bhi[8][4];
#pragma unroll
        for (int p = 0; p < 8; p++)
            ldsm4(bhi[p], wh + boff0 + (unsigned)p * 16 * PB + ka);
#pragma unroll
        for (int p = 0; p < 8; p++) {
            mma16816(C[0][2 * p],     ah0, bhi[p][0], bhi[p][1]);
            mma16816(C[1][2 * p],     ah1, bhi[p][0], bhi[p][1]);
            mma16816(C[0][2 * p + 1], ah0, bhi[p][2], bhi[p][3]);
            mma16816(C[1][2 * p + 1], ah1, bhi[p][2], bhi[p][3]);
        }
#pragma unroll
        for (int p = 0; p < 8; p++) {
            unsigned bl[4];
            ldsm4(bl, wl + boff0 + (unsigned)p * 16 * PB + ka);
            mma16816(C[0][2 * p],     ah0, bl[0], bl[1]);
            mma16816(C[1][2 * p],     ah1, bl[0], bl[1]);
            mma16816(C[0][2 * p + 1], ah0, bl[2], bl[3]);
            mma16816(C[1][2 * p + 1], ah1, bl[2], bl[3]);
        }
#pragma unroll
        for (int p = 0; p < 8; p++) {
            mma16816(C[0][2 * p],     al0, bhi[p][0], bhi[p][1]);
            mma16816(C[1][2 * p],     al1, bhi[p][0], bhi[p][1]);
            mma16816(C[0][2 * p + 1], al0, bhi[p][2], bhi[p][3]);
            mma16816(C[1][2 * p + 1], al1, bhi[p][2], bhi[p][3]);
        }
    }
}

__device__ __forceinline__ void panel_mma1_v2(
    const __nv_bfloat16* sWhi, const __nv_bfloat16* sWlo,
    const __nv_bfloat16* sXhi, const __nv_bfloat16* sXlo,
    int warp, int lane, float C[16][4])
{
    const unsigned wh = (unsigned)__cvta_generic_to_shared(sWhi);
    const unsigned wl = (unsigned)__cvta_generic_to_shared(sWlo);
    const unsigned xh = (unsigned)__cvta_generic_to_shared(sXhi);
    const unsigned xl = (unsigned)__cvta_generic_to_shared(sXlo);
    const unsigned PB = SPITCH * 2;
    const unsigned aoff0 = (unsigned)(warp * 16 + (lane & 15)) * PB
                         + (unsigned)((lane >> 4) & 1) * 16u;
    const unsigned boff0 = (unsigned)((lane & 7) + ((lane & 16) >> 1)) * PB
                         + ((lane & 8) ? 16u : 0u);

    for (int kc = 0; kc < 8; kc++) {
        const unsigned ka = kc * 32;
        unsigned ah[4], al[4];
        ldsm4(ah, xh + aoff0 + ka);
        ldsm4(al, xl + aoff0 + ka);

        unsigned bhi[8][4];
#pragma unroll
        for (int p = 0; p < 8; p++)
            ldsm4(bhi[p], wh + boff0 + (unsigned)p * 16 * PB + ka);
#pragma unroll
        for (int p = 0; p < 8; p++) {
            mma16816(C[2 * p],     ah, bhi[p][0], bhi[p][1]);
            mma16816(C[2 * p + 1], ah, bhi[p][2], bhi[p][3]);
        }
#pragma unroll
        for (int p = 0; p < 8; p++) {
            unsigned bl[4];
            ldsm4(bl, wl + boff0 + (unsigned)p * 16 * PB + ka);
            mma16816(C[2 * p],     ah, bl[0], bl[1]);
            mma16816(C[2 * p + 1], ah, bl[2], bl[3]);
        }
#pragma unroll
        for (int p = 0; p < 8; p++) {
            mma16816(C[2 * p],     al, bhi[p][0], bhi[p][1]);
            mma16816(C[2 * p + 1], al, bhi[p][2], bhi[p][3]);
        }
    }
}

__device__ __forceinline__ void zero_C(float C[16][4])
{
#pragma unroll
    for (int t = 0; t < 16; t++) C[t][0] = C[t][1] = C[t][2] = C[t][3] = 0.f;
}

__device__ __forceinline__ void epilogue_to_smem(
    const float C[16][4], const float* __restrict__ bias,
    float* sE, int warp, int g, int tg)
{
    const int r0 = warp * 16 + g, r1 = r0 + 8;
#pragma unroll
    for (int t = 0; t < 16; t++) {
        int c = t * 8 + tg * 2;
        float2 bv = *(const float2*)(bias + c);
        sE[r0 * EPITCH + c]     = fmaxf(C[t][0] + bv.x, 0.f);
        sE[r0 * EPITCH + c + 1] = fmaxf(C[t][1] + bv.y, 0.f);
        sE[r1 * EPITCH + c]     = fmaxf(C[t][2] + bv.x, 0.f);
        sE[r1 * EPITCH + c + 1] = fmaxf(C[t][3] + bv.y, 0.f);
    }
}

__device__ __forceinline__ void epilogue_to_smem2(
    const float C[2][16][4], const float* __restrict__ bias,
    float* sE, int warp, int g, int tg)
{
#pragma unroll
    for (int rt = 0; rt < 2; rt++) {
        const int r0 = warp * 32 + rt * 16 + g, r1 = r0 + 8;
#pragma unroll
        for (int t = 0; t < 16; t++) {
            int c = t * 8 + tg * 2;
            float2 bv = *(const float2*)(bias + c);
            sE[r0 * EPITCH + c]     = fmaxf(C[rt][t][0] + bv.x, 0.f);
            sE[r0 * EPITCH + c + 1] = fmaxf(C[rt][t][1] + bv.y, 0.f);
            sE[r1 * EPITCH + c]     = fmaxf(C[rt][t][2] + bv.x, 0.f);
            sE[r1 * EPITCH + c + 1] = fmaxf(C[rt][t][3] + bv.y, 0.f);
        }
    }
}

// ---- reduce epilogues writing bf16 planes ----
__device__ __forceinline__ void store_plane(
    __nv_bfloat16* __restrict__ Phi, __nv_bfloat16* __restrict__ Plo,
    size_t off, float f)
{
    __nv_bfloat16 h, l; split1(f, h, l);
    Phi[off] = h; Plo[off] = l;
}

__device__ __forceinline__ void mean4_red_p(
    const float* sE, __nv_bfloat16* __restrict__ Thi, __nv_bfloat16* __restrict__ Tlo,
    int og0, int G, int nrows, int tid)
{
    int col = tid & 127;
    for (int q = tid >> 7; q < (nrows >> 2); q += 2) {
        int og = og0 + q;
        if (og < G) {
            float v = sE[(4 * q) * EPITCH + col] + sE[(4 * q + 1) * EPITCH + col]
                    + sE[(4 * q + 2) * EPITCH + col] + sE[(4 * q + 3) * EPITCH + col];
            store_plane(Thi, Tlo, (size_t)og * 128 + col, 0.25f * v);
        }
    }
}

__device__ __forceinline__ void pairadd_red_p(
    const float* sE, const float* __restrict__ init,
    __nv_bfloat16* __restrict__ Ahi, __nv_bfloat16* __restrict__ Alo,
    int og0, int Mout, int nrows, int tid)
{
    int col = tid & 127;
    for (int q = tid >> 7; q < (nrows >> 1); q += 2) {
        int og = og0 + q;
        if (og < Mout) {
            float v = sE[(2 * q) * EPITCH + col] + sE[(2 * q + 1) * EPITCH + col];
            store_plane(Ahi, Alo, (size_t)og * 128 + col,
                        init[(size_t)og * 128 + col] + 0.5f * v);
        }
    }
}

__device__ __forceinline__ void combine_red_p(
    const float* sE, const float* __restrict__ CTH,
    __nv_bfloat16* __restrict__ Ohi, __nv_bfloat16* __restrict__ Olo,
    int row0, int M1, int nrows, int tid)
{
    int col = tid & 127;
    for (int q = tid >> 7; q < (nrows >> 2); q += 2) {
        int base = row0 + 4 * q;
        if (base < M1) {
            float s = sE[(4 * q) * EPITCH + col] + sE[(4 * q + 1) * EPITCH + col]
                    + sE[(4 * q + 2) * EPITCH + col] + sE[(4 * q + 3) * EPITCH + col];
            float tot = CTH[(size_t)(base >> 3) * 128 + col] + s;
#pragma unroll
            for (int s4 = 0; s4 < 4; s4++)
                store_plane(Ohi, Olo, (size_t)(base + s4) * 128 + col,
                            0.25f * (tot - sE[(4 * q + s4) * EPITCH + col]));
        }
    }
}

// ================= big kernels (256-row X tiles) =================
#define SMEM_BIG ((2 * STILE + 2 * XTILE) * (int)sizeof(__nv_bfloat16))

__global__ void __launch_bounds__(256, 1) up_mean4_big(
    const __nv_bfloat16* __restrict__ Xhi, const __nv_bfloat16* __restrict__ Xlo,
    const float* __restrict__ W, const float* __restrict__ bias,
    __nv_bfloat16* __restrict__ Thi, __nv_bfloat16* __restrict__ Tlo, int M1)
{
    extern __shared__ __nv_bfloat16 sm[];
    __nv_bfloat16 *sWhi = sm, *sWlo = sm + STILE;
    __nv_bfloat16 *sXhi = sm + 2 * STILE, *sXlo = sm + 2 * STILE + XTILE;
    float* sE = (float*)(sm + 2 * STILE);
    const int tid = threadIdx.x, lane = tid & 31, warp = tid >> 5;
    const int g = lane >> 2, tg = lane & 3;
    const int row0 = blockIdx.x * 256;

    stage_w(W, 128, sWhi, sWlo, tid);
    stage_planes<256>(Xhi + (size_t)row0 * 128, Xlo + (size_t)row0 * 128,
                      M1 - row0, sXhi, sXlo, tid);
    __syncthreads();
    float C[2][16][4]; zero_C(C[0]); zero_C(C[1]);
    panel_mma2_v2(sWhi, sWlo, sXhi, sXlo, warp, lane, C);
    __syncthreads();
    epilogue_to_smem2(C, bias, sE, warp, g, tg);
    __syncthreads();
    mean4_red_p(sE, Thi, Tlo, row0 >> 2, M1 >> 2, 256, tid);
}

__global__ void __launch_bounds__(256, 1) up_pairadd_big(
    const __nv_bfloat16* __restrict__ Xhi, const __nv_bfloat16* __restrict__ Xlo,
    const float* __restrict__ W, const float* __restrict__ bias,
    const float* __restrict__ init,
    __nv_bfloat16* __restrict__ Ahi, __nv_bfloat16* __restrict__ Alo, int G)
{
    extern __shared__ __nv_bfloat16 sm[];
    __nv_bfloat16 *sWhi = sm, *sWlo = sm + STILE;
    __nv_bfloat16 *sXhi = sm + 2 * STILE, *sXlo = sm + 2 * STILE + XTILE;
    float* sE = (float*)(sm + 2 * STILE);
    const int tid = threadIdx.x, lane = tid & 31, warp = tid >> 5;
    const int g = lane >> 2, tg = lane & 3;
    const int row0 = blockIdx.x * 256;

    stage_w(W, 128, sWhi, sWlo, tid);
    stage_planes<256>(Xhi + (size_t)row0 * 128, Xlo + (size_t)row0 * 128,
                      G - row0, sXhi, sXlo, tid);
    __syncthreads();
    float C[2][16][4]; zero_C(C[0]); zero_C(C[1]);
    panel_mma2_v2(sWhi, sWlo, sXhi, sXlo, warp, lane, C);
    __syncthreads();
    epilogue_to_smem2(C, bias, sE, warp, g, tg);
    __syncthreads();
    pairadd_red_p(sE, init, Ahi, Alo, row0 >> 1, G >> 1, 256, tid);
}

// cth = relu(ctx @ Wx^T + bx), fp32 out
__global__ void __launch_bounds__(256, 1) cth_gemm_big(
    const __nv_bfloat16* __restrict__ Xhi, const __nv_bfloat16* __restrict__ Xlo,
    const float* __restrict__ W, const float* __restrict__ bias,
    float* __restrict__ Y, int M)
{
    extern __shared__ __nv_bfloat16 sm[];
    __nv_bfloat16 *sWhi = sm, *sWlo = sm + STILE;
    __nv_bfloat16 *sXhi = sm + 2 * STILE, *sXlo = sm + 2 * STILE + XTILE;
    const int tid = threadIdx.x, lane = tid & 31, warp = tid >> 5;
    const int g = lane >> 2, tg = lane & 3;
    const int row0 = blockIdx.x * 256;

    stage_w(W, 128, sWhi, sWlo, tid);
    stage_planes<256>(Xhi + (size_t)row0 * 128, Xlo + (size_t)row0 * 128,
                      M - row0, sXhi, sXlo, tid);
    __syncthreads();
    float C[2][16][4]; zero_C(C[0]); zero_C(C[1]);
    panel_mma2_v2(sWhi, sWlo, sXhi, sXlo, warp, lane, C);

#pragma unroll
    for (int rt = 0; rt < 2; rt++) {
        const int r0 = row0 + warp * 32 + rt * 16 + g, r1 = r0 + 8;
#pragma unroll
        for (int t = 0; t < 16; t++) {
            int c = t * 8 + tg * 2;
            float2 bv = *(const float2*)(bias + c);
            if (r0 < M) *(float2*)(Y + (size_t)r0 * 128 + c) =
                make_float2(fmaxf(C[rt][t][0] + bv.x, 0.f), fmaxf(C[rt][t][1] + bv.y, 0.f));
            if (r1 < M) *(float2*)(Y + (size_t)r1 * 128 + c) =
                make_float2(fmaxf(C[rt][t][2] + bv.x, 0.f), fmaxf(C[rt][t][3] + bv.y, 0.f));
        }
    }
}

__global__ void __launch_bounds__(256, 1) down_combine_big(
    const __nv_bfloat16* __restrict__ Xhi, const __nv_bfloat16* __restrict__ Xlo,
    const float* __restrict__ W, const float* __restrict__ bias,
    const float* __restrict__ CTH,
    __nv_bfloat16* __restrict__ Ohi, __nv_bfloat16* __restrict__ Olo, int M1)
{
    extern __shared__ __nv_bfloat16 sm[];
    __nv_bfloat16 *sWhi = sm, *sWlo = sm + STILE;
    __nv_bfloat16 *sXhi = sm + 2 * STILE, *sXlo = sm + 2 * STILE + XTILE;
    float* sE = (float*)(sm + 2 * STILE);
    const int tid = threadIdx.x, lane = tid & 31, warp = tid >> 5;
    const int g = lane >> 2, tg = lane & 3;
    const int row0 = blockIdx.x * 256;

    stage_w(W, 128, sWhi, sWlo, tid);
    stage_planes<256>(Xhi + (size_t)row0 * 128, Xlo + (size_t)row0 * 128,
                      M1 - row0, sXhi, sXlo, tid);
    __syncthreads();
    float C[2][16][4]; zero_C(C[0]); zero_C(C[1]);
    panel_mma2_v2(sWhi, sWlo, sXhi, sXlo, warp, lane, C);
    __syncthreads();
    epilogue_to_smem2(C, bias, sE, warp, g, tg);
    __syncthreads();
    combine_red_p(sE, CTH, Ohi, Olo, row0, M1, 256, tid);
}

__global__ void __launch_bounds__(256, 1) final_big(
    const __nv_bfloat16* __restrict__ CTXhi, const __nv_bfloat16* __restrict__ CTXlo,
    const __nv_bfloat16* __restrict__ Ahi, const __nv_bfloat16* __restrict__ Alo,
    const __nv_bfloat16* __restrict__ Lhi, const __nv_bfloat16* __restrict__ Llo,
    int bnd,
    const float* __restrict__ Wf, const float* __restrict__ bf,
    const float* __restrict__ Wh, const float* __restrict__ bh,
    float* __restrict__ out, int M)
{
    extern __shared__ __nv_bfloat16 sm[];
    __nv_bfloat16 *sWhi = sm, *sWlo = sm + STILE;
    __nv_bfloat16 *sXhi = sm + 2 * STILE, *sXlo = sm + 2 * STILE + XTILE;
    const int tid = threadIdx.x, lane = tid & 31, warp = tid >> 5;
    const int g = lane >> 2, tg = lane & 3;
    const int row0 = blockIdx.x * 256;

    float C[2][16][4]; zero_C(C[0]); zero_C(C[1]);
    for (int p = 0; p < 2; p++) {
        __syncthreads();
        stage_w(Wf + p * 128, 256, sWhi, sWlo, tid);
        if (p == 0)
            stage_planes<256>(CTXhi + (size_t)row0 * 128, CTXlo + (size_t)row0 * 128,
                              M - row0, sXhi, sXlo, tid);
        else
            stage_planes_sel(Ahi, Alo, Lhi, Llo, bnd, row0, M, sXhi, sXlo, tid);
        __syncthreads();
        panel_mma2_v2(sWhi, sWlo, sXhi, sXlo, warp, lane, C);
    }

#pragma unroll
    for (int rt = 0; rt < 2; rt++) {
        float s0 = 0.f, s1 = 0.f;
#pragma unroll
        for (int t = 0; t < 16; t++) {
            int c = t * 8 + tg * 2;
            float2 bv = *(const float2*)(bf + c);
            float2 wv = *(const float2*)(Wh + c);
            s0 += fmaxf(C[rt][t][0] + bv.x, 0.f) * wv.x + fmaxf(C[rt][t][1] + bv.y, 0.f) * wv.y;
            s1 += fmaxf(C[rt][t][2] + bv.x, 0.f) * wv.x + fmaxf(C[rt][t][3] + bv.y, 0.f) * wv.y;
        }
        s0 += __shfl_xor_sync(0xffffffffu, s0, 1);
        s0 += __shfl_xor_sync(0xffffffffu, s0, 2);
        s1 += __shfl_xor_sync(0xffffffffu, s1, 1);
        s1 += __shfl_xor_sync(0xffffffffu, s1, 2);
        if (tg == 0) {
            const int r0 = row0 + warp * 32 + rt * 16 + g, r1 = r0 + 8;
            float bhv = bh[0];
            if (r0 < M) out[r0] = s0 + bhv;
            if (r1 < M) out[r1] = s1 + bhv;
        }
    }
}

// ================= tiny-level kernels =================
#define SMEM_SMALL (4 * STILE * (int)sizeof(__nv_bfloat16))

__global__ void __launch_bounds__(256) up_small(
    const __nv_bfloat16* __restrict__ Xchi, const __nv_bfloat16* __restrict__ Xclo,
    const float* __restrict__ init_l,
    __nv_bfloat16* __restrict__ Ahi, __nv_bfloat16* __restrict__ Alo,
    const float* __restrict__ Ws, const float* __restrict__ bs,
    const float* __restrict__ Wc, const float* __restrict__ bc,
    __nv_bfloat16* __restrict__ Thi, __nv_bfloat16* __restrict__ Tlo, int M1)
{
    extern __shared__ __nv_bfloat16 sm[];
    __nv_bfloat16 *sWhi = sm, *sWlo = sm + STILE, *sXhi = sm + 2 * STILE, *sXlo = sm + 3 * STILE;
    float* sE = (float*)(sm + 2 * STILE);
    const int tid = threadIdx.x, lane = tid & 31, warp = tid >> 5;
    const int g = lane >> 2, tg = lane & 3;
    const int G = M1 >> 2, Mout = M1 >> 3;

    stage_w(Ws, 128, sWhi, sWlo, tid);
    stage_planes<128>(Xchi, Xclo, M1, sXhi, sXlo, tid);
    __syncthreads();
    {
        float C[16][4]; zero_C(C);
        panel_mma1_v2(sWhi, sWlo, sXhi, sXlo, warp, lane, C);
        __syncthreads();
        epilogue_to_smem(C, bs, sE, warp, g, tg);
        __syncthreads();
        mean4_red_p(sE, Thi, Tlo, 0, G, 128, tid);
    }
    __syncthreads();
    stage_w(Wc, 128, sWhi, sWlo, tid);
    stage_planes_sync(Thi, Tlo, G, sXhi, sXlo, tid);
    __syncthreads();
    {
        float C[16][4]; zero_C(C);
        panel_mma1_v2(sWhi, sWlo, sXhi, sXlo, warp, lane, C);
        __syncthreads();
        epilogue_to_smem(C, bc, sE, warp, g, tg);
        __syncthreads();
        pairadd_red_p(sE, init_l, Ahi, Alo, 0, Mout, 128, tid);
    }
}

__global__ void __launch_bounds__(256) down_small(
    const __nv_bfloat16* __restrict__ CTXhi, const __nv_bfloat16* __restrict__ CTXlo,
    const __nv_bfloat16* __restrict__ AChi, const __nv_bfloat16* __restrict__ AClo,
    const float* __restrict__ Wx, const float* __restrict__ bx,
    float* __restrict__ CTH,
    __nv_bfloat16* __restrict__ Ohi, __nv_bfloat16* __restrict__ Olo, int Ml, int M1)
{
    extern __shared__ __nv_bfloat16 sm[];
    __nv_bfloat16 *sWhi = sm, *sWlo = sm + STILE, *sXhi = sm + 2 * STILE, *sXlo = sm + 3 * STILE;
    float* sE = (float*)(sm + 2 * STILE);
    const int tid = threadIdx.x, lane = tid & 31, warp = tid >> 5;
    const int g = lane >> 2, tg = lane & 3;

    stage_w(Wx, 128, sWhi, sWlo, tid);
    stage_planes<128>(CTXhi, CTXlo, Ml, sXhi, sXlo, tid);
    __syncthreads();
    {
        float C[16][4]; zero_C(C);
        panel_mma1_v2(sWhi, sWlo, sXhi, sXlo, warp, lane, C);
        const int r0 = warp * 16 + g, r1 = r0 + 8;
#pragma unroll
        for (int t = 0; t < 16; t++) {
            int c = t * 8 + tg * 2;
            float2 bv = *(const float2*)(bx + c);
            if (r0 < Ml) *(float2*)(CTH + (size_t)r0 * 128 + c) =
                make_float2(fmaxf(C[t][0] + bv.x, 0.f), fmaxf(C[t][1] + bv.y, 0.f));
            if (r1 < Ml) *(float2*)(CTH + (size_t)r1 * 128 + c) =
                make_float2(fmaxf(C[t][2] + bv.x, 0.f), fmaxf(C[t][3] + bv.y, 0.f));
        }
    }
    __syncthreads();
    stage_planes<128>(AChi, AClo, M1, sXhi, sXlo, tid);
    __syncthreads();
    {
        float C[16][4]; zero_C(C);
        panel_mma1_v2(sWhi, sWlo, sXhi, sXlo, warp, lane, C);
        __syncthreads();
        epilogue_to_smem(C, bx, sE, warp, g, tg);
        __syncthreads();
        combine_red_p(sE, CTH, Ohi, Olo, 0, M1, 128, tid);
    }
}

// ================= utility kernels =================
__global__ void leaf_convert(const float4* __restrict__ in,
                             uint2* __restrict__ hi, uint2* __restrict__ lo, int n4)
{
    int i = blockIdx.x * blockDim.x + threadIdx.x;
    int stride = gridDim.x * blockDim.x;
    for (; i < n4; i += stride) {
        uint2 hv, lv;
        split4(in[i], hv, lv);
        hi[i] = hv; lo[i] = lv;
    }
}

__global__ void set_ones_planes(__nv_bfloat16* hi, __nv_bfloat16* lo)
{
    int i = threadIdx.x;
    hi[i] = __float2bfloat16(1.0f);
    lo[i] = __float2bfloat16(0.0f);
}

// ---------------- launch ----------------
extern "C" void kernel_launch(void* const* d_in, const int* in_sizes, int n_in,
                              void* d_out, int out_size)
{
    const float* initial = (const float*)d_in[0];
    const float* Ws = (const float*)d_in[1];
    const float* bs = (const float*)d_in[2];
    const float* Wc = (const float*)d_in[3];
    const float* bc = (const float*)d_in[4];
    const float* Wx = (const float*)d_in[5];
    const float* bx = (const float*)d_in[6];
    const float* Wf = (const float*)d_in[7];
    const float* bf = (const float*)d_in[8];
    const float* Wh = (const float*)d_in[9];
    const float* bh = (const float*)d_in[10];
    float* out = (float*)d_out;

    __nv_bfloat16 *aggh, *aggl, *ctxh, *ctxl, *t2h, *t2l, *lfh, *lfl;
    float* cth;
    cudaGetSymbolAddress((void**)&aggh, g_agg_hi);
    cudaGetSymbolAddress((void**)&aggl, g_agg_lo);
    cudaGetSymbolAddress((void**)&ctxh, g_ctx_hi);
    cudaGetSymbolAddress((void**)&ctxl, g_ctx_lo);
    cudaGetSymbolAddress((void**)&t2h,  g_t2_hi);
    cudaGetSymbolAddress((void**)&t2l,  g_t2_lo);
    cudaGetSymbolAddress((void**)&lfh,  g_leaf_hi);
    cudaGetSymbolAddress((void**)&lfl,  g_leaf_lo);
    cudaGetSymbolAddress((void**)&cth,  g_cth);

    cudaFuncSetAttribute(up_mean4_big,     cudaFuncAttributeMaxDynamicSharedMemorySize, SMEM_BIG);
    cudaFuncSetAttribute(up_pairadd_big,   cudaFuncAttributeMaxDynamicSharedMemorySize, SMEM_BIG);
    cudaFuncSetAttribute(cth_gemm_big,     cudaFuncAttributeMaxDynamicSharedMemorySize, SMEM_BIG);
    cudaFuncSetAttribute(down_combine_big, cudaFuncAttributeMaxDynamicSharedMemorySize, SMEM_BIG);
    cudaFuncSetAttribute(final_big,        cudaFuncAttributeMaxDynamicSharedMemorySize, SMEM_BIG);
    cudaFuncSetAttribute(up_small,         cudaFuncAttributeMaxDynamicSharedMemorySize, SMEM_SMALL);
    cudaFuncSetAttribute(down_small,       cudaFuncAttributeMaxDynamicSharedMemorySize, SMEM_SMALL);

    // materialize leaf planes once (bandwidth-bound)
    leaf_convert<<<4096, 256>>>(
        (const float4*)(initial + (size_t)H_OFFS[6] * DIM),
        (uint2*)lfh, (uint2*)lfl, NLEAF * DIM / 4);

    // ---- up pass: levels 5..2 ----
    for (int l = 5; l >= 2; l--) {
        int M1 = H_SIZES[l + 1];
        int G  = M1 >> 2;
        const __nv_bfloat16* xh = (l == 5) ? lfh : aggh + (size_t)H_OFFS[l + 1] * DIM;
        const __nv_bfloat16* xl = (l == 5) ? lfl : aggl + (size_t)H_OFFS[l + 1] * DIM;

        up_mean4_big<<<(M1 + 255) / 256, 256, SMEM_BIG>>>(xh, xl, Ws, bs, t2h, t2l, M1);
        up_pairadd_big<<<(G + 255) / 256, 256, SMEM_BIG>>>(
            t2h, t2l, Wc, bc,
            initial + (size_t)H_OFFS[l] * DIM,
            aggh + (size_t)H_OFFS[l] * DIM, aggl + (size_t)H_OFFS[l] * DIM, G);
    }
    for (int l = 1; l >= 0; l--) {
        up_small<<<1, 256, SMEM_SMALL>>>(
            aggh + (size_t)H_OFFS[l + 1] * DIM, aggl + (size_t)H_OFFS[l + 1] * DIM,
            initial + (size_t)H_OFFS[l] * DIM,
            aggh + (size_t)H_OFFS[l] * DIM, aggl + (size_t)H_OFFS[l] * DIM,
            Ws, bs, Wc, bc, t2h, t2l, H_SIZES[l + 1]);
    }

    // ---- down pass ----
    set_ones_planes<<<1, 128>>>(ctxh, ctxl);
    for (int l = 0; l < 2; l++) {
        down_small<<<1, 256, SMEM_SMALL>>>(
            ctxh + (size_t)H_OFFS[l] * DIM, ctxl + (size_t)H_OFFS[l] * DIM,
            aggh + (size_t)H_OFFS[l + 1] * DIM, aggl + (size_t)H_OFFS[l + 1] * DIM,
            Wx, bx, cth,
            ctxh + (size_t)H_OFFS[l + 1] * DIM, ctxl + (size_t)H_OFFS[l + 1] * DIM,
            H_SIZES[l], H_SIZES[l + 1]);
    }
    for (int l = 2; l < 6; l++) {
        int Ml = H_SIZES[l], M1 = H_SIZES[l + 1];
        const __nv_bfloat16* xh = (l == 5) ? lfh : aggh + (size_t)H_OFFS[l + 1] * DIM;
        const __nv_bfloat16* xl = (l == 5) ? lfl : aggl + (size_t)H_OFFS[l + 1] * DIM;

        cth_gemm_big<<<(Ml + 255) / 256, 256, SMEM_BIG>>>(
            ctxh + (size_t)H_OFFS[l] * DIM, ctxl + (size_t)H_OFFS[l] * DIM,
            Wx, bx, cth, Ml);
        down_combine_big<<<(M1 + 255) / 256, 256, SMEM_BIG>>>(
            xh, xl, Wx, bx, cth,
            ctxh + (size_t)H_OFFS[l + 1] * DIM, ctxl + (size_t)H_OFFS[l + 1] * DIM, M1);
    }

    // ---- final ----
    final_big<<<(N_TOTAL + 255) / 256, 256, SMEM_BIG>>>(
        ctxh, ctxl, aggh, aggl, lfh, lfl, NTOP,
        Wf, bf, Wh, bh, out, N_TOTAL);
}

// round 10
// speedup vs baseline: 1.0604x; 1.0604x over previous
#include <cuda_runtime.h>
#include <cuda_bf16.h>
#include <cstdint>

#define DIM 128
#define N_TOTAL 299593
#define NTOP 37449

static const int H_SIZES[7] = {1, 8, 64, 512, 4096, 32768, 262144};
static const int H_OFFS[8]  = {0, 1, 9, 73, 585, 4681, 37449, 299593};

// ---------------- scratch: intermediates as bf16 hi/lo planes ----------------
__device__ __nv_bfloat16 g_agg_hi[NTOP * DIM],    g_agg_lo[NTOP * DIM];
__device__ __nv_bfloat16 g_ctx_hi[N_TOTAL * DIM], g_ctx_lo[N_TOTAL * DIM];
__device__ __nv_bfloat16 g_t2_hi [65536 * DIM],   g_t2_lo [65536 * DIM];
__device__ float g_cth[32768 * DIM];

// ================= common =================
#define SPITCH 136
#define STILE  (128 * SPITCH)
#define WBYTES (STILE * 2)               // 34816 B, one 128x128 bf16 plane tile
#define XBUF(i) (2 * WBYTES + (i) * 2 * WBYTES)
#define SMEM_PERS (6 * WBYTES)           // 208896 B
#define SMEM_SMALL (4 * WBYTES)          // 139264 B
#define EPITCH 132

__device__ __forceinline__ uint32_t smem_u32(const void* p) {
    return (uint32_t)__cvta_generic_to_shared(p);
}
__device__ __forceinline__ void split1(float f, __nv_bfloat16& h, __nv_bfloat16& l) {
    h = __float2bfloat16(f);
    l = __float2bfloat16(f - __bfloat162float(h));
}
__device__ __forceinline__ void split4(float4 v, uint2& hv, uint2& lv) {
    __nv_bfloat16 h0,h1,h2,h3,l0,l1,l2,l3;
    split1(v.x,h0,l0); split1(v.y,h1,l1); split1(v.z,h2,l2); split1(v.w,h3,l3);
    hv.x = ((unsigned)__bfloat16_as_ushort(h1)<<16) | __bfloat16_as_ushort(h0);
    hv.y = ((unsigned)__bfloat16_as_ushort(h3)<<16) | __bfloat16_as_ushort(h2);
    lv.x = ((unsigned)__bfloat16_as_ushort(l1)<<16) | __bfloat16_as_ushort(l0);
    lv.y = ((unsigned)__bfloat16_as_ushort(l3)<<16) | __bfloat16_as_ushort(l2);
}
__device__ __forceinline__ void cp16(unsigned saddr, const void* gptr, int sz) {
    asm volatile("cp.async.cg.shared.global [%0], [%1], 16, %2;"
                 :: "r"(saddr), "l"(gptr), "r"(sz));
}
template<int N>
__device__ __forceinline__ void cp_wait() {
    asm volatile("cp.async.wait_group %0;" :: "n"(N) : "memory");
}
__device__ __forceinline__ void cp_commit() {
    asm volatile("cp.async.commit_group;");
}

__device__ __forceinline__ void mma16816(float* c, const unsigned* a, unsigned b0, unsigned b1)
{
    asm volatile(
        "mma.sync.aligned.m16n8k16.row.col.f32.bf16.bf16.f32 "
        "{%0,%1,%2,%3},{%4,%5,%6,%7},{%8,%9},{%0,%1,%2,%3};\n"
        : "+f"(c[0]), "+f"(c[1]), "+f"(c[2]), "+f"(c[3])
        : "r"(a[0]), "r"(a[1]), "r"(a[2]), "r"(a[3]), "r"(b0), "r"(b1));
}
__device__ __forceinline__ void ldsm4(unsigned* r, unsigned addr)
{
    asm volatile("ldmatrix.sync.aligned.m8n8.x4.shared.b16 {%0,%1,%2,%3}, [%4];"
                 : "=r"(r[0]), "=r"(r[1]), "=r"(r[2]), "=r"(r[3]) : "r"(addr));
}

// ---- W staging: fp32 -> hi/lo pitch smem, batched loads ----
__device__ __forceinline__ void stage_w(
    const float* __restrict__ G, int gstride,
    __nv_bfloat16* sWhi, __nv_bfloat16* sWlo, int tid)
{
#pragma unroll
    for (int b = 0; b < 16; b += 8) {
        float4 v[8];
#pragma unroll
        for (int j = 0; j < 8; j++) {
            int idx = tid + (b + j) * 256;
            v[j] = *(const float4*)(G + (size_t)(idx >> 5) * gstride + (idx & 31) * 4);
        }
#pragma unroll
        for (int j = 0; j < 8; j++) {
            int idx = tid + (b + j) * 256;
            int r = idx >> 5, c4 = (idx & 31) * 4;
            uint2 hv, lv; split4(v[j], hv, lv);
            *(uint2*)(sWhi + (size_t)r * SPITCH + c4) = hv;
            *(uint2*)(sWlo + (size_t)r * SPITCH + c4) = lv;
        }
    }
}

// ---- X staging: bf16 planes -> pitch smem via cp.async; commits one group ----
__device__ __forceinline__ void stage_plane_tile(
    const __nv_bfloat16* __restrict__ Ghi, const __nv_bfloat16* __restrict__ Glo,
    int rows_valid, char* buf, int tid)
{
    unsigned hB = smem_u32(buf), lB = hB + WBYTES;
#pragma unroll
    for (int i = tid; i < 2048; i += 256) {
        int r = i >> 4, c = i & 15;
        unsigned so = (unsigned)r * 272 + c * 16;
        int sz = (r < rows_valid) ? 16 : 0;
        cp16(hB + so, Ghi + (size_t)r * 128 + c * 8, sz);
        cp16(lB + so, Glo + (size_t)r * 128 + c * 8, sz);
    }
    cp_commit();
}

// ---- leaf staging: fp32 -> hi/lo pitch smem (register split, synchronous) ----
__device__ __forceinline__ void stage_leaf_tile(
    const float* __restrict__ F32, int grow0, int M, char* buf, int tid)
{
    char* hB = buf; char* lB = buf + WBYTES;
#pragma unroll
    for (int b = 0; b < 16; b += 8) {
        float4 v[8];
#pragma unroll
        for (int j = 0; j < 8; j++) {
            int idx = tid + (b + j) * 256;
            int gr = grow0 + (idx >> 5);
            v[j] = make_float4(0.f, 0.f, 0.f, 0.f);
            if (gr < M) v[j] = *(const float4*)(F32 + (size_t)gr * 128 + (idx & 31) * 4);
        }
#pragma unroll
        for (int j = 0; j < 8; j++) {
            int idx = tid + (b + j) * 256;
            int r = idx >> 5, c4 = (idx & 31) * 4;
            uint2 hv, lv; split4(v[j], hv, lv);
            *(uint2*)(hB + (size_t)r * 272 + c4 * 2) = hv;
            *(uint2*)(lB + (size_t)r * 272 + c4 * 2) = lv;
        }
    }
}

// final agg-panel: rows<bnd from planes (cp.async), else leaf fp32 rows (register split)
__device__ __forceinline__ void stage_sel_tile(
    const __nv_bfloat16* __restrict__ Ahi, const __nv_bfloat16* __restrict__ Alo,
    const float* __restrict__ INIT, int bnd, int grow0, int M, char* buf, int tid)
{
    unsigned hB = smem_u32(buf), lB = hB + WBYTES;
    char* hP = buf; char* lP = buf + WBYTES;
    for (int i = tid; i < 2048; i += 256) {
        int r = i >> 4, c = i & 15;
        int gr = grow0 + r;
        unsigned so = (unsigned)r * 272 + c * 16;
        if (gr < bnd) {
            cp16(hB + so, Ahi + (size_t)gr * 128 + c * 8, 16);
            cp16(lB + so, Alo + (size_t)gr * 128 + c * 8, 16);
        } else {
            uint2 h0 = make_uint2(0,0), l0 = make_uint2(0,0);
            uint2 h1 = make_uint2(0,0), l1 = make_uint2(0,0);
            if (gr < M) {
                float4 a = *(const float4*)(INIT + (size_t)gr * 128 + c * 8);
                float4 b = *(const float4*)(INIT + (size_t)gr * 128 + c * 8 + 4);
                split4(a, h0, l0); split4(b, h1, l1);
            }
            *(uint2*)(hP + so) = h0; *(uint2*)(hP + so + 8) = h1;
            *(uint2*)(lP + so) = l0; *(uint2*)(lP + so + 8) = l1;
        }
    }
    cp_commit();
}

// ---- mainloop: ldmatrix + accumulator-independent ordering (verified) ----
__device__ __forceinline__ void panel_mma1_v2(
    const __nv_bfloat16* sWhi, const __nv_bfloat16* sWlo,
    const __nv_bfloat16* sXhi, const __nv_bfloat16* sXlo,
    int warp, int lane, float C[16][4])
{
    const unsigned wh = smem_u32(sWhi), wl = smem_u32(sWlo);
    const unsigned xh = smem_u32(sXhi), xl = smem_u32(sXlo);
    const unsigned PB = SPITCH * 2;
    const unsigned aoff0 = (unsigned)(warp * 16 + (lane & 15)) * PB + (unsigned)((lane >> 4) & 1) * 16u;
    const unsigned boff0 = (unsigned)((lane & 7) + ((lane & 16) >> 1)) * PB + ((lane & 8) ? 16u : 0u);

    for (int kc = 0; kc < 8; kc++) {
        const unsigned ka = kc * 32;
        unsigned ah[4], al[4];
        ldsm4(ah, xh + aoff0 + ka);
        ldsm4(al, xl + aoff0 + ka);
        unsigned bhi[8][4];
#pragma unroll
        for (int p = 0; p < 8; p++) ldsm4(bhi[p], wh + boff0 + (unsigned)p * 16 * PB + ka);
#pragma unroll
        for (int p = 0; p < 8; p++) {
            mma16816(C[2*p],   ah, bhi[p][0], bhi[p][1]);
            mma16816(C[2*p+1], ah, bhi[p][2], bhi[p][3]);
        }
#pragma unroll
        for (int p = 0; p < 8; p++) {
            unsigned bl[4];
            ldsm4(bl, wl + boff0 + (unsigned)p * 16 * PB + ka);
            mma16816(C[2*p],   ah, bl[0], bl[1]);
            mma16816(C[2*p+1], ah, bl[2], bl[3]);
        }
#pragma unroll
        for (int p = 0; p < 8; p++) {
            mma16816(C[2*p],   al, bhi[p][0], bhi[p][1]);
            mma16816(C[2*p+1], al, bhi[p][2], bhi[p][3]);
        }
    }
}

__device__ __forceinline__ void zero_C(float C[16][4])
{
#pragma unroll
    for (int t = 0; t < 16; t++) C[t][0] = C[t][1] = C[t][2] = C[t][3] = 0.f;
}

__device__ __forceinline__ void epilogue_to_smem(
    const float C[16][4], const float* __restrict__ bias, float* sE, int warp, int g, int tg)
{
    const int r0 = warp * 16 + g, r1 = r0 + 8;
#pragma unroll
    for (int t = 0; t < 16; t++) {
        int c = t * 8 + tg * 2;
        float2 bv = *(const float2*)(bias + c);
        sE[r0 * EPITCH + c]     = fmaxf(C[t][0] + bv.x, 0.f);
        sE[r0 * EPITCH + c + 1] = fmaxf(C[t][1] + bv.y, 0.f);
        sE[r1 * EPITCH + c]     = fmaxf(C[t][2] + bv.x, 0.f);
        sE[r1 * EPITCH + c + 1] = fmaxf(C[t][3] + bv.y, 0.f);
    }
}

// ---- reduce epilogues writing bf16 planes (verified in R8) ----
__device__ __forceinline__ void mean4_red_p(
    const float* sE, __nv_bfloat16* __restrict__ Thi, __nv_bfloat16* __restrict__ Tlo,
    int og0, int G, int tid)
{
    int col = tid & 127;
    for (int q = tid >> 7; q < 32; q += 2) {
        int og = og0 + q;
        if (og < G) {
            float v = sE[(4*q)*EPITCH + col] + sE[(4*q+1)*EPITCH + col]
                    + sE[(4*q+2)*EPITCH + col] + sE[(4*q+3)*EPITCH + col];
            __nv_bfloat16 h, l; split1(0.25f * v, h, l);
            Thi[(size_t)og * 128 + col] = h;
            Tlo[(size_t)og * 128 + col] = l;
        }
    }
}
__device__ __forceinline__ void pairadd_red_p(
    const float* sE, const float* __restrict__ init,
    __nv_bfloat16* __restrict__ Ahi, __nv_bfloat16* __restrict__ Alo,
    int og0, int Mout, int tid)
{
    int col = tid & 127;
    for (int q = tid >> 7; q < 64; q += 2) {
        int og = og0 + q;
        if (og < Mout) {
            float v = sE[(2*q)*EPITCH + col] + sE[(2*q+1)*EPITCH + col];
            __nv_bfloat16 h, l;
            split1(init[(size_t)og * 128 + col] + 0.5f * v, h, l);
            Ahi[(size_t)og * 128 + col] = h;
            Alo[(size_t)og * 128 + col] = l;
        }
    }
}
__device__ __forceinline__ void combine_red_p(
    const float* sE, const float* __restrict__ CTH,
    __nv_bfloat16* __restrict__ Ohi, __nv_bfloat16* __restrict__ Olo,
    int row0, int M1, int tid)
{
    int col = tid & 127;
    for (int q = tid >> 7; q < 32; q += 2) {
        int base = row0 + 4 * q;
        if (base < M1) {
            float s = sE[(4*q)*EPITCH + col] + sE[(4*q+1)*EPITCH + col]
                    + sE[(4*q+2)*EPITCH + col] + sE[(4*q+3)*EPITCH + col];
            float tot = CTH[(size_t)(base >> 3) * 128 + col] + s;
#pragma unroll
            for (int s4 = 0; s4 < 4; s4++) {
                __nv_bfloat16 h, l;
                split1(0.25f * (tot - sE[(4*q+s4)*EPITCH + col]), h, l);
                Ohi[(size_t)(base + s4) * 128 + col] = h;
                Olo[(size_t)(base + s4) * 128 + col] = l;
            }
        }
    }
}

// ================= persistent big kernels (128-row tiles, double-buffered) =================

__global__ void __launch_bounds__(256, 1) up_mean4_pers(
    const __nv_bfloat16* __restrict__ Xhi, const __nv_bfloat16* __restrict__ Xlo,
    const float* __restrict__ Xf32, int leaf,
    const float* __restrict__ W, const float* __restrict__ bias,
    __nv_bfloat16* __restrict__ Thi, __nv_bfloat16* __restrict__ Tlo, int M1)
{
    extern __shared__ __align__(1024) char sm[];
    const int tid = threadIdx.x, lane = tid & 31, warp = tid >> 5;
    const int g = lane >> 2, tg = lane & 3;
    __nv_bfloat16* sWhi = (__nv_bfloat16*)sm;
    __nv_bfloat16* sWlo = (__nv_bfloat16*)(sm + WBYTES);
    stage_w(W, 128, sWhi, sWlo, tid);

    const int ntiles = (M1 + 127) >> 7;
    const int t0 = blockIdx.x;
    if (!leaf && t0 < ntiles)
        stage_plane_tile(Xhi + (size_t)t0 * 16384, Xlo + (size_t)t0 * 16384,
                         M1 - t0 * 128, sm + XBUF(0), tid);
    int phase = 0;
    for (int t = t0; t < ntiles; t += gridDim.x, phase++) {
        int cur = 0;
        if (leaf) {
            stage_leaf_tile(Xf32, t * 128, M1, sm + XBUF(0), tid);
        } else {
            cur = phase & 1;
            int tn = t + gridDim.x;
            if (tn < ntiles) {
                stage_plane_tile(Xhi + (size_t)tn * 16384, Xlo + (size_t)tn * 16384,
                                 M1 - tn * 128, sm + XBUF(1 - cur), tid);
                cp_wait<1>();
            } else cp_wait<0>();
        }
        __syncthreads();
        float C[16][4]; zero_C(C);
        panel_mma1_v2(sWhi, sWlo,
                      (__nv_bfloat16*)(sm + XBUF(cur)),
                      (__nv_bfloat16*)(sm + XBUF(cur) + WBYTES), warp, lane, C);
        __syncthreads();
        float* sE = (float*)(sm + XBUF(leaf ? 1 : cur));
        epilogue_to_smem(C, bias, sE, warp, g, tg);
        __syncthreads();
        mean4_red_p(sE, Thi, Tlo, t * 32, M1 >> 2, tid);
        __syncthreads();
    }
}

__global__ void __launch_bounds__(256, 1) up_pairadd_pers(
    const __nv_bfloat16* __restrict__ Xhi, const __nv_bfloat16* __restrict__ Xlo,
    const float* __restrict__ W, const float* __restrict__ bias,
    const float* __restrict__ init,
    __nv_bfloat16* __restrict__ Ahi, __nv_bfloat16* __restrict__ Alo, int G)
{
    extern __shared__ __align__(1024) char sm[];
    const int tid = threadIdx.x, lane = tid & 31, warp = tid >> 5;
    const int g = lane >> 2, tg = lane & 3;
    __nv_bfloat16* sWhi = (__nv_bfloat16*)sm;
    __nv_bfloat16* sWlo = (__nv_bfloat16*)(sm + WBYTES);
    stage_w(W, 128, sWhi, sWlo, tid);

    const int ntiles = (G + 127) >> 7;
    const int t0 = blockIdx.x;
    if (t0 < ntiles)
        stage_plane_tile(Xhi + (size_t)t0 * 16384, Xlo + (size_t)t0 * 16384,
                         G - t0 * 128, sm + XBUF(0), tid);
    int phase = 0;
    for (int t = t0; t < ntiles; t += gridDim.x, phase++) {
        int cur = phase & 1;
        int tn = t + gridDim.x;
        if (tn < ntiles) {
            stage_plane_tile(Xhi + (size_t)tn * 16384, Xlo + (size_t)tn * 16384,
                             G - tn * 128, sm + XBUF(1 - cur), tid);
            cp_wait<1>();
        } else cp_wait<0>();
        __syncthreads();
        float C[16][4]; zero_C(C);
        panel_mma1_v2(sWhi, sWlo,
                      (__nv_bfloat16*)(sm + XBUF(cur)),
                      (__nv_bfloat16*)(sm + XBUF(cur) + WBYTES), warp, lane, C);
        __syncthreads();
        float* sE = (float*)(sm + XBUF(cur));
        epilogue_to_smem(C, bias, sE, warp, g, tg);
        __syncthreads();
        pairadd_red_p(sE, init, Ahi, Alo, t * 64, G >> 1, tid);
        __syncthreads();
    }
}

__global__ void __launch_bounds__(256, 1) cth_pers(
    const __nv_bfloat16* __restrict__ Xhi, const __nv_bfloat16* __restrict__ Xlo,
    const float* __restrict__ W, const float* __restrict__ bias,
    float* __restrict__ Y, int M)
{
    extern __shared__ __align__(1024) char sm[];
    const int tid = threadIdx.x, lane = tid & 31, warp = tid >> 5;
    const int g = lane >> 2, tg = lane & 3;
    __nv_bfloat16* sWhi = (__nv_bfloat16*)sm;
    __nv_bfloat16* sWlo = (__nv_bfloat16*)(sm + WBYTES);
    stage_w(W, 128, sWhi, sWlo, tid);

    const int ntiles = (M + 127) >> 7;
    const int t0 = blockIdx.x;
    if (t0 < ntiles) {
        int rv = M - t0 * 128; if (rv > 128) rv = 128;
        stage_plane_tile(Xhi + (size_t)t0 * 16384, Xlo + (size_t)t0 * 16384, rv, sm + XBUF(0), tid);
    }
    int phase = 0;
    for (int t = t0; t < ntiles; t += gridDim.x, phase++) {
        int cur = phase & 1;
        int tn = t + gridDim.x;
        if (tn < ntiles) {
            int rv = M - tn * 128; if (rv > 128) rv = 128;
            stage_plane_tile(Xhi + (size_t)tn * 16384, Xlo + (size_t)tn * 16384, rv, sm + XBUF(1 - cur), tid);
            cp_wait<1>();
        } else cp_wait<0>();
        __syncthreads();
        float C[16][4]; zero_C(C);
        panel_mma1_v2(sWhi, sWlo,
                      (__nv_bfloat16*)(sm + XBUF(cur)),
                      (__nv_bfloat16*)(sm + XBUF(cur) + WBYTES), warp, lane, C);
        const int r0g = t * 128 + warp * 16 + g, r1g = r0g + 8;
#pragma unroll
        for (int tt = 0; tt < 16; tt++) {
            int c = tt * 8 + tg * 2;
            float2 bv = *(const float2*)(bias + c);
            if (r0g < M) *(float2*)(Y + (size_t)r0g * 128 + c) =
                make_float2(fmaxf(C[tt][0] + bv.x, 0.f), fmaxf(C[tt][1] + bv.y, 0.f));
            if (r1g < M) *(float2*)(Y + (size_t)r1g * 128 + c) =
                make_float2(fmaxf(C[tt][2] + bv.x, 0.f), fmaxf(C[tt][3] + bv.y, 0.f));
        }
        __syncthreads();
    }
}

__global__ void __launch_bounds__(256, 1) down_combine_pers(
    const __nv_bfloat16* __restrict__ Xhi, const __nv_bfloat16* __restrict__ Xlo,
    const float* __restrict__ Xf32, int leaf,
    const float* __restrict__ W, const float* __restrict__ bias,
    const float* __restrict__ CTH,
    __nv_bfloat16* __restrict__ Ohi, __nv_bfloat16* __restrict__ Olo, int M1)
{
    extern __shared__ __align__(1024) char sm[];
    const int tid = threadIdx.x, lane = tid & 31, warp = tid >> 5;
    const int g = lane >> 2, tg = lane & 3;
    __nv_bfloat16* sWhi = (__nv_bfloat16*)sm;
    __nv_bfloat16* sWlo = (__nv_bfloat16*)(sm + WBYTES);
    stage_w(W, 128, sWhi, sWlo, tid);

    const int ntiles = (M1 + 127) >> 7;
    const int t0 = blockIdx.x;
    if (!leaf && t0 < ntiles)
        stage_plane_tile(Xhi + (size_t)t0 * 16384, Xlo + (size_t)t0 * 16384,
                         M1 - t0 * 128, sm + XBUF(0), tid);
    int phase = 0;
    for (int t = t0; t < ntiles; t += gridDim.x, phase++) {
        int cur = 0;
        if (leaf) {
            stage_leaf_tile(Xf32, t * 128, M1, sm + XBUF(0), tid);
        } else {
            cur = phase & 1;
            int tn = t + gridDim.x;
            if (tn < ntiles) {
                stage_plane_tile(Xhi + (size_t)tn * 16384, Xlo + (size_t)tn * 16384,
                                 M1 - tn * 128, sm + XBUF(1 - cur), tid);
                cp_wait<1>();
            } else cp_wait<0>();
        }
        __syncthreads();
        float C[16][4]; zero_C(C);
        panel_mma1_v2(sWhi, sWlo,
                      (__nv_bfloat16*)(sm + XBUF(cur)),
                      (__nv_bfloat16*)(sm + XBUF(cur) + WBYTES), warp, lane, C);
        __syncthreads();
        float* sE = (float*)(sm + XBUF(leaf ? 1 : cur));
        epilogue_to_smem(C, bias, sE, warp, g, tg);
        __syncthreads();
        combine_red_p(sE, CTH, Ohi, Olo, t * 128, M1, tid);
        __syncthreads();
    }
}

// final: both Wf panels resident; per tile 2 accumulating passes; dot with Wh.
__global__ void __launch_bounds__(256, 1) final_pers(
    const __nv_bfloat16* __restrict__ CTXhi, const __nv_bfloat16* __restrict__ CTXlo,
    const __nv_bfloat16* __restrict__ Ahi, const __nv_bfloat16* __restrict__ Alo,
    const float* __restrict__ INIT, int bnd,
    const float* __restrict__ Wf, const float* __restrict__ bf,
    const float* __restrict__ Wh, const float* __restrict__ bh,
    float* __restrict__ out, int M)
{
    extern __shared__ __align__(1024) char sm[];
    const int tid = threadIdx.x, lane = tid & 31, warp = tid >> 5;
    const int g = lane >> 2, tg = lane & 3;
    // W panels: p at sm + p*2*WBYTES
    stage_w(Wf,       256, (__nv_bfloat16*)sm,                 (__nv_bfloat16*)(sm + WBYTES),     tid);
    stage_w(Wf + 128, 256, (__nv_bfloat16*)(sm + 2 * WBYTES),  (__nv_bfloat16*)(sm + 3 * WBYTES), tid);
    char* xb = sm + 4 * WBYTES;
    __nv_bfloat16* sXhi = (__nv_bfloat16*)xb;
    __nv_bfloat16* sXlo = (__nv_bfloat16*)(xb + WBYTES);

    const int ntiles = (M + 127) >> 7;
    for (int t = blockIdx.x; t < ntiles; t += gridDim.x) {
        int row0 = t * 128;
        int rv = M - row0; if (rv > 128) rv = 128;
        stage_plane_tile(CTXhi + (size_t)row0 * 128, CTXlo + (size_t)row0 * 128, rv, xb, tid);
        cp_wait<0>();
        __syncthreads();
        float C[16][4]; zero_C(C);
        panel_mma1_v2((__nv_bfloat16*)sm, (__nv_bfloat16*)(sm + WBYTES), sXhi, sXlo, warp, lane, C);
        __syncthreads();
        stage_sel_tile(Ahi, Alo, INIT, bnd, row0, M, xb, tid);
        cp_wait<0>();
        __syncthreads();
        panel_mma1_v2((__nv_bfloat16*)(sm + 2 * WBYTES), (__nv_bfloat16*)(sm + 3 * WBYTES),
                      sXhi, sXlo, warp, lane, C);
        // dot epilogue
        float s0 = 0.f, s1 = 0.f;
#pragma unroll
        for (int tt = 0; tt < 16; tt++) {
            int c = tt * 8 + tg * 2;
            float2 bv = *(const float2*)(bf + c);
            float2 wv = *(const float2*)(Wh + c);
            s0 += fmaxf(C[tt][0] + bv.x, 0.f) * wv.x + fmaxf(C[tt][1] + bv.y, 0.f) * wv.y;
            s1 += fmaxf(C[tt][2] + bv.x, 0.f) * wv.x + fmaxf(C[tt][3] + bv.y, 0.f) * wv.y;
        }
        s0 += __shfl_xor_sync(0xffffffffu, s0, 1);
        s0 += __shfl_xor_sync(0xffffffffu, s0, 2);
        s1 += __shfl_xor_sync(0xffffffffu, s1, 1);
        s1 += __shfl_xor_sync(0xffffffffu, s1, 2);
        if (tg == 0) {
            int r0g = row0 + warp * 16 + g, r1g = r0g + 8;
            float bhv = bh[0];
            if (r0g < M) out[r0g] = s0 + bhv;
            if (r1g < M) out[r1g] = s1 + bhv;
        }
        __syncthreads();
    }
}

// ================= tiny-level kernels (from R8, verified) =================
__device__ __forceinline__ void stage_planes_pitch(
    const __nv_bfloat16* __restrict__ Ghi, const __nv_bfloat16* __restrict__ Glo,
    int rows_valid, __nv_bfloat16* sXhi, __nv_bfloat16* sXlo, int tid)
{
    unsigned shi = smem_u32(sXhi), slo = smem_u32(sXlo);
#pragma unroll
    for (int i = tid; i < 128 * 16; i += 256) {
        int r = i >> 4, c = i & 15;
        unsigned so = (unsigned)r * 272 + c * 16;
        int sz = (r < rows_valid) ? 16 : 0;
        cp16(shi + so, Ghi + (size_t)r * 128 + c * 8, sz);
        cp16(slo + so, Glo + (size_t)r * 128 + c * 8, sz);
    }
    cp_commit();
    cp_wait<0>();
}

__global__ void __launch_bounds__(256) up_small(
    const __nv_bfloat16* __restrict__ Xchi, const __nv_bfloat16* __restrict__ Xclo,
    const float* __restrict__ init_l,
    __nv_bfloat16* __restrict__ Ahi, __nv_bfloat16* __restrict__ Alo,
    const float* __restrict__ Ws, const float* __restrict__ bs,
    const float* __restrict__ Wc, const float* __restrict__ bc,
    __nv_bfloat16* __restrict__ Thi, __nv_bfloat16* __restrict__ Tlo, int M1)
{
    extern __shared__ __align__(1024) char sm[];
    __nv_bfloat16 *sWhi = (__nv_bfloat16*)sm, *sWlo = (__nv_bfloat16*)(sm + WBYTES);
    __nv_bfloat16 *sXhi = (__nv_bfloat16*)(sm + 2 * WBYTES), *sXlo = (__nv_bfloat16*)(sm + 3 * WBYTES);
    float* sE = (float*)(sm + 2 * WBYTES);
    const int tid = threadIdx.x, lane = tid & 31, warp = tid >> 5;
    const int g = lane >> 2, tg = lane & 3;
    const int G = M1 >> 2, Mout = M1 >> 3;

    stage_w(Ws, 128, sWhi, sWlo, tid);
    stage_planes_pitch(Xchi, Xclo, M1, sXhi, sXlo, tid);
    __syncthreads();
    {
        float C[16][4]; zero_C(C);
        panel_mma1_v2(sWhi, sWlo, sXhi, sXlo, warp, lane, C);
        __syncthreads();
        epilogue_to_smem(C, bs, sE, warp, g, tg);
        __syncthreads();
        mean4_red_p(sE, Thi, Tlo, 0, G, tid);
    }
    __syncthreads();
    stage_w(Wc, 128, sWhi, sWlo, tid);
#pragma unroll
    for (int i = tid; i < 128 * 32; i += 256) {
        int r = i >> 5, c4 = (i & 31) * 4;
        uint2 hv = make_uint2(0,0), lv = make_uint2(0,0);
        if (r < G) {
            hv = *(const uint2*)(Thi + (size_t)r * 128 + c4);
            lv = *(const uint2*)(Tlo + (size_t)r * 128 + c4);
        }
        *(uint2*)(sXhi + (size_t)r * SPITCH + c4) = hv;
        *(uint2*)(sXlo + (size_t)r * SPITCH + c4) = lv;
    }
    __syncthreads();
    {
        float C[16][4]; zero_C(C);
        panel_mma1_v2(sWhi, sWlo, sXhi, sXlo, warp, lane, C);
        __syncthreads();
        epilogue_to_smem(C, bc, sE, warp, g, tg);
        __syncthreads();
        pairadd_red_p(sE, init_l, Ahi, Alo, 0, Mout, tid);
    }
}

__global__ void __launch_bounds__(256) down_small(
    const __nv_bfloat16* __restrict__ CTXhi, const __nv_bfloat16* __restrict__ CTXlo,
    const __nv_bfloat16* __restrict__ AChi, const __nv_bfloat16* __restrict__ AClo,
    const float* __restrict__ Wx, const float* __restrict__ bx,
    float* __restrict__ CTH,
    __nv_bfloat16* __restrict__ Ohi, __nv_bfloat16* __restrict__ Olo, int Ml, int M1)
{
    extern __shared__ __align__(1024) char sm[];
    __nv_bfloat16 *sWhi = (__nv_bfloat16*)sm, *sWlo = (__nv_bfloat16*)(sm + WBYTES);
    __nv_bfloat16 *sXhi = (__nv_bfloat16*)(sm + 2 * WBYTES), *sXlo = (__nv_bfloat16*)(sm + 3 * WBYTES);
    float* sE = (float*)(sm + 2 * WBYTES);
    const int tid = threadIdx.x, lane = tid & 31, warp = tid >> 5;
    const int g = lane >> 2, tg = lane & 3;

    stage_w(Wx, 128, sWhi, sWlo, tid);
    stage_planes_pitch(CTXhi, CTXlo, Ml, sXhi, sXlo, tid);
    __syncthreads();
    {
        float C[16][4]; zero_C(C);
        panel_mma1_v2(sWhi, sWlo, sXhi, sXlo, warp, lane, C);
        const int r0 = warp * 16 + g, r1 = r0 + 8;
#pragma unroll
        for (int t = 0; t < 16; t++) {
            int c = t * 8 + tg * 2;
            float2 bv = *(const float2*)(bx + c);
            if (r0 < Ml) *(float2*)(CTH + (size_t)r0 * 128 + c) =
                make_float2(fmaxf(C[t][0] + bv.x, 0.f), fmaxf(C[t][1] + bv.y, 0.f));
            if (r1 < Ml) *(float2*)(CTH + (size_t)r1 * 128 + c) =
                make_float2(fmaxf(C[t][2] + bv.x, 0.f), fmaxf(C[t][3] + bv.y, 0.f));
        }
    }
    __syncthreads();
    stage_planes_pitch(AChi, AClo, M1, sXhi, sXlo, tid);
    __syncthreads();
    {
        float C[16][4]; zero_C(C);
        panel_mma1_v2(sWhi, sWlo, sXhi, sXlo, warp, lane, C);
        __syncthreads();
        epilogue_to_smem(C, bx, sE, warp, g, tg);
        __syncthreads();
        combine_red_p(sE, CTH, Ohi, Olo, 0, M1, tid);
    }
}

__global__ void set_ones_planes(__nv_bfloat16* hi, __nv_bfloat16* lo)
{
    int i = threadIdx.x;
    hi[i] = __float2bfloat16(1.0f);
    lo[i] = __float2bfloat16(0.0f);
}

// ---------------- launch ----------------
static inline int grid_for(int rows) {
    int nt = (rows + 127) >> 7;
    return nt < 148 ? nt : 148;
}

extern "C" void kernel_launch(void* const* d_in, const int* in_sizes, int n_in,
                              void* d_out, int out_size)
{
    const float* initial = (const float*)d_in[0];
    const float* Ws = (const float*)d_in[1];
    const float* bs = (const float*)d_in[2];
    const float* Wc = (const float*)d_in[3];
    const float* bc = (const float*)d_in[4];
    const float* Wx = (const float*)d_in[5];
    const float* bx = (const float*)d_in[6];
    const float* Wf = (const float*)d_in[7];
    const float* bf = (const float*)d_in[8];
    const float* Wh = (const float*)d_in[9];
    const float* bh = (const float*)d_in[10];
    float* out = (float*)d_out;

    __nv_bfloat16 *aggh, *aggl, *ctxh, *ctxl, *t2h, *t2l;
    float* cth;
    cudaGetSymbolAddress((void**)&aggh, g_agg_hi);
    cudaGetSymbolAddress((void**)&aggl, g_agg_lo);
    cudaGetSymbolAddress((void**)&ctxh, g_ctx_hi);
    cudaGetSymbolAddress((void**)&ctxl, g_ctx_lo);
    cudaGetSymbolAddress((void**)&t2h,  g_t2_hi);
    cudaGetSymbolAddress((void**)&t2l,  g_t2_lo);
    cudaGetSymbolAddress((void**)&cth,  g_cth);

    cudaFuncSetAttribute(up_mean4_pers,     cudaFuncAttributeMaxDynamicSharedMemorySize, SMEM_PERS);
    cudaFuncSetAttribute(up_pairadd_pers,   cudaFuncAttributeMaxDynamicSharedMemorySize, SMEM_PERS);
    cudaFuncSetAttribute(cth_pers,          cudaFuncAttributeMaxDynamicSharedMemorySize, SMEM_PERS);
    cudaFuncSetAttribute(down_combine_pers, cudaFuncAttributeMaxDynamicSharedMemorySize, SMEM_PERS);
    cudaFuncSetAttribute(final_pers,        cudaFuncAttributeMaxDynamicSharedMemorySize, SMEM_PERS);
    cudaFuncSetAttribute(up_small,          cudaFuncAttributeMaxDynamicSharedMemorySize, SMEM_SMALL);
    cudaFuncSetAttribute(down_small,        cudaFuncAttributeMaxDynamicSharedMemorySize, SMEM_SMALL);

    const float* leaf_f32 = initial + (size_t)H_OFFS[6] * DIM;

    // ---- up pass: levels 5..2 (persistent) ----
    for (int l = 5; l >= 2; l--) {
        int M1 = H_SIZES[l + 1];
        int G  = M1 >> 2;
        if (l == 5)
            up_mean4_pers<<<grid_for(M1), 256, SMEM_PERS>>>(
                nullptr, nullptr, leaf_f32, 1, Ws, bs, t2h, t2l, M1);
        else
            up_mean4_pers<<<grid_for(M1), 256, SMEM_PERS>>>(
                aggh + (size_t)H_OFFS[l + 1] * DIM, aggl + (size_t)H_OFFS[l + 1] * DIM,
                nullptr, 0, Ws, bs, t2h, t2l, M1);
        up_pairadd_pers<<<grid_for(G), 256, SMEM_PERS>>>(
            t2h, t2l, Wc, bc,
            initial + (size_t)H_OFFS[l] * DIM,
            aggh + (size_t)H_OFFS[l] * DIM, aggl + (size_t)H_OFFS[l] * DIM, G);
    }
    for (int l = 1; l >= 0; l--) {
        up_small<<<1, 256, SMEM_SMALL>>>(
            aggh + (size_t)H_OFFS[l + 1] * DIM, aggl + (size_t)H_OFFS[l + 1] * DIM,
            initial + (size_t)H_OFFS[l] * DIM,
            aggh + (size_t)H_OFFS[l] * DIM, aggl + (size_t)H_OFFS[l] * DIM,
            Ws, bs, Wc, bc, t2h, t2l, H_SIZES[l + 1]);
    }

    // ---- down pass ----
    set_ones_planes<<<1, 128>>>(ctxh, ctxl);
    for (int l = 0; l < 2; l++) {
        down_small<<<1, 256, SMEM_SMALL>>>(
            ctxh + (size_t)H_OFFS[l] * DIM, ctxl + (size_t)H_OFFS[l] * DIM,
            aggh + (size_t)H_OFFS[l + 1] * DIM, aggl + (size_t)H_OFFS[l + 1] * DIM,
            Wx, bx, cth,
            ctxh + (size_t)H_OFFS[l + 1] * DIM, ctxl + (size_t)H_OFFS[l + 1] * DIM,
            H_SIZES[l], H_SIZES[l + 1]);
    }
    for (int l = 2; l < 6; l++) {
        int Ml = H_SIZES[l], M1 = H_SIZES[l + 1];
        cth_pers<<<grid_for(Ml), 256, SMEM_PERS>>>(
            ctxh + (size_t)H_OFFS[l] * DIM, ctxl + (size_t)H_OFFS[l] * DIM,
            Wx, bx, cth, Ml);
        if (l == 5)
            down_combine_pers<<<grid_for(M1), 256, SMEM_PERS>>>(
                nullptr, nullptr, leaf_f32, 1, Wx, bx, cth,
                ctxh + (size_t)H_OFFS[l + 1] * DIM, ctxl + (size_t)H_OFFS[l + 1] * DIM, M1);
        else
            down_combine_pers<<<grid_for(M1), 256, SMEM_PERS>>>(
                aggh + (size_t)H_OFFS[l + 1] * DIM, aggl + (size_t)H_OFFS[l + 1] * DIM,
                nullptr, 0, Wx, bx, cth,
                ctxh + (size_t)H_OFFS[l + 1] * DIM, ctxl + (size_t)H_OFFS[l + 1] * DIM, M1);
    }

    // ---- final ----
    final_pers<<<148, 256, SMEM_PERS>>>(
        ctxh, ctxl, aggh, aggl, initial, NTOP,
        Wf, bf, Wh, bh, out, N_TOTAL);
}

// round 11
// speedup vs baseline: 1.1706x; 1.1039x over previous
#include <cuda_runtime.h>
#include <cuda_bf16.h>
#include <cstdint>

#define DIM 128
#define N_TOTAL 299593
#define NTOP 37449

static const int H_SIZES[7] = {1, 8, 64, 512, 4096, 32768, 262144};
static const int H_OFFS[8]  = {0, 1, 9, 73, 585, 4681, 37449, 299593};

// ---------------- scratch: intermediates as bf16 hi/lo planes ----------------
__device__ __nv_bfloat16 g_agg_hi[NTOP * DIM],    g_agg_lo[NTOP * DIM];
__device__ __nv_bfloat16 g_ctx_hi[N_TOTAL * DIM], g_ctx_lo[N_TOTAL * DIM];
__device__ __nv_bfloat16 g_t2_hi [65536 * DIM],   g_t2_lo [65536 * DIM];
__device__ float g_cth[32768 * DIM];

// ================= common =================
#define SPITCH 136
#define STILE  (128 * SPITCH)
#define WBYTES (STILE * 2)                 // 34816 B per 128-row plane
#define XBYTES64 17408                     // 64-row plane (64*272)
#define EPITCH 132

// 64-row-tile kernels: W hi/lo + X hi/lo
#define SMEM_64 (2 * WBYTES + 2 * XBYTES64)          // 104448 -> 2 blocks/SM
// final kernel: 2 W panels hi/lo + X hi/lo (128-row)
#define SMEM_FIN (6 * WBYTES)                        // 208896
#define SMEM_SMALL (4 * WBYTES)                      // 139264

__device__ __forceinline__ uint32_t smem_u32(const void* p) {
    return (uint32_t)__cvta_generic_to_shared(p);
}
__device__ __forceinline__ void split1(float f, __nv_bfloat16& h, __nv_bfloat16& l) {
    h = __float2bfloat16(f);
    l = __float2bfloat16(f - __bfloat162float(h));
}
__device__ __forceinline__ void split4(float4 v, uint2& hv, uint2& lv) {
    __nv_bfloat16 h0,h1,h2,h3,l0,l1,l2,l3;
    split1(v.x,h0,l0); split1(v.y,h1,l1); split1(v.z,h2,l2); split1(v.w,h3,l3);
    hv.x = ((unsigned)__bfloat16_as_ushort(h1)<<16) | __bfloat16_as_ushort(h0);
    hv.y = ((unsigned)__bfloat16_as_ushort(h3)<<16) | __bfloat16_as_ushort(h2);
    lv.x = ((unsigned)__bfloat16_as_ushort(l1)<<16) | __bfloat16_as_ushort(l0);
    lv.y = ((unsigned)__bfloat16_as_ushort(l3)<<16) | __bfloat16_as_ushort(l2);
}
__device__ __forceinline__ void cp16(unsigned saddr, const void* gptr, int sz) {
    asm volatile("cp.async.cg.shared.global [%0], [%1], 16, %2;"
                 :: "r"(saddr), "l"(gptr), "r"(sz));
}
template<int N>
__device__ __forceinline__ void cp_wait() {
    asm volatile("cp.async.wait_group %0;" :: "n"(N) : "memory");
}
__device__ __forceinline__ void cp_commit() {
    asm volatile("cp.async.commit_group;");
}

__device__ __forceinline__ void mma16816(float* c, const unsigned* a, unsigned b0, unsigned b1)
{
    asm volatile(
        "mma.sync.aligned.m16n8k16.row.col.f32.bf16.bf16.f32 "
        "{%0,%1,%2,%3},{%4,%5,%6,%7},{%8,%9},{%0,%1,%2,%3};\n"
        : "+f"(c[0]), "+f"(c[1]), "+f"(c[2]), "+f"(c[3])
        : "r"(a[0]), "r"(a[1]), "r"(a[2]), "r"(a[3]), "r"(b0), "r"(b1));
}
__device__ __forceinline__ void ldsm4(unsigned* r, unsigned addr)
{
    asm volatile("ldmatrix.sync.aligned.m8n8.x4.shared.b16 {%0,%1,%2,%3}, [%4];"
                 : "=r"(r[0]), "=r"(r[1]), "=r"(r[2]), "=r"(r[3]) : "r"(addr));
}

// ---- W staging: fp32 -> hi/lo pitch smem; NTHR = block size ----
template <int NTHR>
__device__ __forceinline__ void stage_w(
    const float* __restrict__ G, int gstride,
    __nv_bfloat16* sWhi, __nv_bfloat16* sWlo, int tid)
{
    constexpr int ITERS = 4096 / NTHR;     // 128*32 float4
#pragma unroll
    for (int b = 0; b < ITERS; b += 8) {
        float4 v[8];
#pragma unroll
        for (int j = 0; j < 8; j++) {
            int idx = tid + (b + j) * NTHR;
            v[j] = *(const float4*)(G + (size_t)(idx >> 5) * gstride + (idx & 31) * 4);
        }
#pragma unroll
        for (int j = 0; j < 8; j++) {
            int idx = tid + (b + j) * NTHR;
            int r = idx >> 5, c4 = (idx & 31) * 4;
            uint2 hv, lv; split4(v[j], hv, lv);
            *(uint2*)(sWhi + (size_t)r * SPITCH + c4) = hv;
            *(uint2*)(sWlo + (size_t)r * SPITCH + c4) = lv;
        }
    }
}

// ---- X staging (64-row tile, 128 threads): bf16 planes via cp.async ----
__device__ __forceinline__ void stage_plane64(
    const __nv_bfloat16* __restrict__ Ghi, const __nv_bfloat16* __restrict__ Glo,
    int rows_valid, char* buf, int tid)
{
    unsigned hB = smem_u32(buf), lB = hB + XBYTES64;
#pragma unroll
    for (int i = tid; i < 1024; i += 128) {
        int r = i >> 4, c = i & 15;
        unsigned so = (unsigned)r * 272 + c * 16;
        int sz = (r < rows_valid) ? 16 : 0;
        cp16(hB + so, Ghi + (size_t)r * 128 + c * 8, sz);
        cp16(lB + so, Glo + (size_t)r * 128 + c * 8, sz);
    }
    cp_commit();
}

// ---- leaf staging (64-row tile, 128 threads): fp32 register split ----
__device__ __forceinline__ void stage_leaf64(
    const float* __restrict__ F32, int grow0, int M, char* buf, int tid)
{
    char* hB = buf; char* lB = buf + XBYTES64;
#pragma unroll
    for (int b = 0; b < 16; b += 8) {
        float4 v[8];
#pragma unroll
        for (int j = 0; j < 8; j++) {
            int idx = tid + (b + j) * 128;
            int gr = grow0 + (idx >> 5);
            v[j] = make_float4(0.f, 0.f, 0.f, 0.f);
            if (gr < M) v[j] = *(const float4*)(F32 + (size_t)gr * 128 + (idx & 31) * 4);
        }
#pragma unroll
        for (int j = 0; j < 8; j++) {
            int idx = tid + (b + j) * 128;
            int r = idx >> 5, c4 = (idx & 31) * 4;
            uint2 hv, lv; split4(v[j], hv, lv);
            *(uint2*)(hB + (size_t)r * 272 + c4 * 2) = hv;
            *(uint2*)(lB + (size_t)r * 272 + c4 * 2) = lv;
        }
    }
}

// ---- mainloop v3: all B fragments preloaded per pass (no ldsm->mma RAW chains) ----
__device__ __forceinline__ void panel_mma_v3(
    const __nv_bfloat16* sWhi, const __nv_bfloat16* sWlo,
    const __nv_bfloat16* sXhi, const __nv_bfloat16* sXlo,
    int warp, int lane, float C[16][4])
{
    const unsigned wh = smem_u32(sWhi), wl = smem_u32(sWlo);
    const unsigned xh = smem_u32(sXhi), xl = smem_u32(sXlo);
    const unsigned PB = SPITCH * 2;
    const unsigned aoff0 = (unsigned)(warp * 16 + (lane & 15)) * PB + (unsigned)((lane >> 4) & 1) * 16u;
    const unsigned boff0 = (unsigned)((lane & 7) + ((lane & 16) >> 1)) * PB + ((lane & 8) ? 16u : 0u);

    for (int kc = 0; kc < 8; kc++) {
        const unsigned ka = kc * 32;
        unsigned ah[4], al[4];
        ldsm4(ah, xh + aoff0 + ka);
        ldsm4(al, xl + aoff0 + ka);
        unsigned bhi[8][4];
#pragma unroll
        for (int p = 0; p < 8; p++) ldsm4(bhi[p], wh + boff0 + (unsigned)p * 16 * PB + ka);
#pragma unroll
        for (int p = 0; p < 8; p++) {
            mma16816(C[2*p],   ah, bhi[p][0], bhi[p][1]);
            mma16816(C[2*p+1], ah, bhi[p][2], bhi[p][3]);
        }
        unsigned blo[8][4];
#pragma unroll
        for (int p = 0; p < 8; p++) ldsm4(blo[p], wl + boff0 + (unsigned)p * 16 * PB + ka);
#pragma unroll
        for (int p = 0; p < 8; p++) {
            mma16816(C[2*p],   ah, blo[p][0], blo[p][1]);
            mma16816(C[2*p+1], ah, blo[p][2], blo[p][3]);
        }
#pragma unroll
        for (int p = 0; p < 8; p++) {
            mma16816(C[2*p],   al, bhi[p][0], bhi[p][1]);
            mma16816(C[2*p+1], al, bhi[p][2], bhi[p][3]);
        }
    }
}

__device__ __forceinline__ void zero_C(float C[16][4])
{
#pragma unroll
    for (int t = 0; t < 16; t++) C[t][0] = C[t][1] = C[t][2] = C[t][3] = 0.f;
}

// epilogue: relu(C+bias) -> sE rows [warp*16, +16)
__device__ __forceinline__ void epilogue_to_smem(
    const float C[16][4], const float* __restrict__ bias, float* sE, int warp, int g, int tg)
{
    const int r0 = warp * 16 + g, r1 = r0 + 8;
#pragma unroll
    for (int t = 0; t < 16; t++) {
        int c = t * 8 + tg * 2;
        float2 bv = *(const float2*)(bias + c);
        sE[r0 * EPITCH + c]     = fmaxf(C[t][0] + bv.x, 0.f);
        sE[r0 * EPITCH + c + 1] = fmaxf(C[t][1] + bv.y, 0.f);
        sE[r1 * EPITCH + c]     = fmaxf(C[t][2] + bv.x, 0.f);
        sE[r1 * EPITCH + c + 1] = fmaxf(C[t][3] + bv.y, 0.f);
    }
}

// ---- reduce epilogues over sE (64-row tiles, 128 threads; col = tid) ----
__device__ __forceinline__ void mean4_red64(
    const float* sE, __nv_bfloat16* __restrict__ Thi, __nv_bfloat16* __restrict__ Tlo,
    int og0, int G, int col)
{
#pragma unroll 4
    for (int q = 0; q < 16; q++) {
        int og = og0 + q;
        if (og < G) {
            float v = sE[(4*q)*EPITCH + col] + sE[(4*q+1)*EPITCH + col]
                    + sE[(4*q+2)*EPITCH + col] + sE[(4*q+3)*EPITCH + col];
            __nv_bfloat16 h, l; split1(0.25f * v, h, l);
            Thi[(size_t)og * 128 + col] = h;
            Tlo[(size_t)og * 128 + col] = l;
        }
    }
}
__device__ __forceinline__ void pairadd_red64(
    const float* sE, const float* __restrict__ init,
    __nv_bfloat16* __restrict__ Ahi, __nv_bfloat16* __restrict__ Alo,
    int og0, int Mout, int col)
{
#pragma unroll 4
    for (int q = 0; q < 32; q++) {
        int og = og0 + q;
        if (og < Mout) {
            float v = sE[(2*q)*EPITCH + col] + sE[(2*q+1)*EPITCH + col];
            __nv_bfloat16 h, l;
            split1(init[(size_t)og * 128 + col] + 0.5f * v, h, l);
            Ahi[(size_t)og * 128 + col] = h;
            Alo[(size_t)og * 128 + col] = l;
        }
    }
}
__device__ __forceinline__ void combine_red64(
    const float* sE, const float* __restrict__ CTH,
    __nv_bfloat16* __restrict__ Ohi, __nv_bfloat16* __restrict__ Olo,
    int row0, int M1, int col)
{
#pragma unroll 2
    for (int q = 0; q < 16; q++) {
        int base = row0 + 4 * q;
        if (base < M1) {
            float s = sE[(4*q)*EPITCH + col] + sE[(4*q+1)*EPITCH + col]
                    + sE[(4*q+2)*EPITCH + col] + sE[(4*q+3)*EPITCH + col];
            float tot = CTH[(size_t)(base >> 3) * 128 + col] + s;
#pragma unroll
            for (int s4 = 0; s4 < 4; s4++) {
                __nv_bfloat16 h, l;
                split1(0.25f * (tot - sE[(4*q+s4)*EPITCH + col]), h, l);
                Ohi[(size_t)(base + s4) * 128 + col] = h;
                Olo[(size_t)(base + s4) * 128 + col] = l;
            }
        }
    }
}

// ================= 64-row-tile kernels: 128 threads, 2 blocks/SM =================

__global__ void __launch_bounds__(128, 2) up_mean4_64(
    const __nv_bfloat16* __restrict__ Xhi, const __nv_bfloat16* __restrict__ Xlo,
    const float* __restrict__ Xf32, int leaf,
    const float* __restrict__ W, const float* __restrict__ bias,
    __nv_bfloat16* __restrict__ Thi, __nv_bfloat16* __restrict__ Tlo, int M1)
{
    extern __shared__ __align__(1024) char sm[];
    const int tid = threadIdx.x, lane = tid & 31, warp = tid >> 5;
    const int g = lane >> 2, tg = lane & 3;
    __nv_bfloat16* sWhi = (__nv_bfloat16*)sm;
    __nv_bfloat16* sWlo = (__nv_bfloat16*)(sm + WBYTES);
    char* xb = sm + 2 * WBYTES;
    stage_w<128>(W, 128, sWhi, sWlo, tid);

    const int ntiles = (M1 + 63) >> 6;
    for (int t = blockIdx.x; t < ntiles; t += gridDim.x) {
        if (leaf) stage_leaf64(Xf32, t * 64, M1, xb, tid);
        else {
            stage_plane64(Xhi + (size_t)t * 8192, Xlo + (size_t)t * 8192, M1 - t * 64, xb, tid);
            cp_wait<0>();
        }
        __syncthreads();
        float C[16][4]; zero_C(C);
        panel_mma_v3(sWhi, sWlo, (__nv_bfloat16*)xb, (__nv_bfloat16*)(xb + XBYTES64), warp, lane, C);
        __syncthreads();
        float* sE = (float*)xb;
        epilogue_to_smem(C, bias, sE, warp, g, tg);
        __syncthreads();
        mean4_red64(sE, Thi, Tlo, t * 16, M1 >> 2, tid);
        __syncthreads();
    }
}

__global__ void __launch_bounds__(128, 2) up_pairadd_64(
    const __nv_bfloat16* __restrict__ Xhi, const __nv_bfloat16* __restrict__ Xlo,
    const float* __restrict__ W, const float* __restrict__ bias,
    const float* __restrict__ init,
    __nv_bfloat16* __restrict__ Ahi, __nv_bfloat16* __restrict__ Alo, int G)
{
    extern __shared__ __align__(1024) char sm[];
    const int tid = threadIdx.x, lane = tid & 31, warp = tid >> 5;
    const int g = lane >> 2, tg = lane & 3;
    __nv_bfloat16* sWhi = (__nv_bfloat16*)sm;
    __nv_bfloat16* sWlo = (__nv_bfloat16*)(sm + WBYTES);
    char* xb = sm + 2 * WBYTES;
    stage_w<128>(W, 128, sWhi, sWlo, tid);

    const int ntiles = (G + 63) >> 6;
    for (int t = blockIdx.x; t < ntiles; t += gridDim.x) {
        stage_plane64(Xhi + (size_t)t * 8192, Xlo + (size_t)t * 8192, G - t * 64, xb, tid);
        cp_wait<0>();
        __syncthreads();
        float C[16][4]; zero_C(C);
        panel_mma_v3(sWhi, sWlo, (__nv_bfloat16*)xb, (__nv_bfloat16*)(xb + XBYTES64), warp, lane, C);
        __syncthreads();
        float* sE = (float*)xb;
        epilogue_to_smem(C, bias, sE, warp, g, tg);
        __syncthreads();
        pairadd_red64(sE, init, Ahi, Alo, t * 32, G >> 1, tid);
        __syncthreads();
    }
}

__global__ void __launch_bounds__(128, 2) cth_64(
    const __nv_bfloat16* __restrict__ Xhi, const __nv_bfloat16* __restrict__ Xlo,
    const float* __restrict__ W, const float* __restrict__ bias,
    float* __restrict__ Y, int M)
{
    extern __shared__ __align__(1024) char sm[];
    const int tid = threadIdx.x, lane = tid & 31, warp = tid >> 5;
    const int g = lane >> 2, tg = lane & 3;
    __nv_bfloat16* sWhi = (__nv_bfloat16*)sm;
    __nv_bfloat16* sWlo = (__nv_bfloat16*)(sm + WBYTES);
    char* xb = sm + 2 * WBYTES;
    stage_w<128>(W, 128, sWhi, sWlo, tid);

    const int ntiles = (M + 63) >> 6;
    for (int t = blockIdx.x; t < ntiles; t += gridDim.x) {
        int rv = M - t * 64; if (rv > 64) rv = 64;
        stage_plane64(Xhi + (size_t)t * 8192, Xlo + (size_t)t * 8192, rv, xb, tid);
        cp_wait<0>();
        __syncthreads();
        float C[16][4]; zero_C(C);
        panel_mma_v3(sWhi, sWlo, (__nv_bfloat16*)xb, (__nv_bfloat16*)(xb + XBYTES64), warp, lane, C);
        const int r0g = t * 64 + warp * 16 + g, r1g = r0g + 8;
#pragma unroll
        for (int tt = 0; tt < 16; tt++) {
            int c = tt * 8 + tg * 2;
            float2 bv = *(const float2*)(bias + c);
            if (r0g < M) *(float2*)(Y + (size_t)r0g * 128 + c) =
                make_float2(fmaxf(C[tt][0] + bv.x, 0.f), fmaxf(C[tt][1] + bv.y, 0.f));
            if (r1g < M) *(float2*)(Y + (size_t)r1g * 128 + c) =
                make_float2(fmaxf(C[tt][2] + bv.x, 0.f), fmaxf(C[tt][3] + bv.y, 0.f));
        }
        __syncthreads();
    }
}

__global__ void __launch_bounds__(128, 2) down_combine_64(
    const __nv_bfloat16* __restrict__ Xhi, const __nv_bfloat16* __restrict__ Xlo,
    const float* __restrict__ Xf32, int leaf,
    const float* __restrict__ W, const float* __restrict__ bias,
    const float* __restrict__ CTH,
    __nv_bfloat16* __restrict__ Ohi, __nv_bfloat16* __restrict__ Olo, int M1)
{
    extern __shared__ __align__(1024) char sm[];
    const int tid = threadIdx.x, lane = tid & 31, warp = tid >> 5;
    const int g = lane >> 2, tg = lane & 3;
    __nv_bfloat16* sWhi = (__nv_bfloat16*)sm;
    __nv_bfloat16* sWlo = (__nv_bfloat16*)(sm + WBYTES);
    char* xb = sm + 2 * WBYTES;
    stage_w<128>(W, 128, sWhi, sWlo, tid);

    const int ntiles = (M1 + 63) >> 6;
    for (int t = blockIdx.x; t < ntiles; t += gridDim.x) {
        if (leaf) stage_leaf64(Xf32, t * 64, M1, xb, tid);
        else {
            stage_plane64(Xhi + (size_t)t * 8192, Xlo + (size_t)t * 8192, M1 - t * 64, xb, tid);
            cp_wait<0>();
        }
        __syncthreads();
        float C[16][4]; zero_C(C);
        panel_mma_v3(sWhi, sWlo, (__nv_bfloat16*)xb, (__nv_bfloat16*)(xb + XBYTES64), warp, lane, C);
        __syncthreads();
        float* sE = (float*)xb;
        epilogue_to_smem(C, bias, sE, warp, g, tg);
        __syncthreads();
        combine_red64(sE, CTH, Ohi, Olo, t * 64, M1, tid);
        __syncthreads();
    }
}

// ================= final kernel (256 threads, 128-row tiles, 1 block/SM) =================
__device__ __forceinline__ void stage_plane128(
    const __nv_bfloat16* __restrict__ Ghi, const __nv_bfloat16* __restrict__ Glo,
    int rows_valid, char* buf, int tid)
{
    unsigned hB = smem_u32(buf), lB = hB + WBYTES;
#pragma unroll
    for (int i = tid; i < 2048; i += 256) {
        int r = i >> 4, c = i & 15;
        unsigned so = (unsigned)r * 272 + c * 16;
        int sz = (r < rows_valid) ? 16 : 0;
        cp16(hB + so, Ghi + (size_t)r * 128 + c * 8, sz);
        cp16(lB + so, Glo + (size_t)r * 128 + c * 8, sz);
    }
    cp_commit();
}

__device__ __forceinline__ void stage_sel128(
    const __nv_bfloat16* __restrict__ Ahi, const __nv_bfloat16* __restrict__ Alo,
    const float* __restrict__ INIT, int bnd, int grow0, int M, char* buf, int tid)
{
    unsigned hB = smem_u32(buf), lB = hB + WBYTES;
    char* hP = buf; char* lP = buf + WBYTES;
    for (int i = tid; i < 2048; i += 256) {
        int r = i >> 4, c = i & 15;
        int gr = grow0 + r;
        unsigned so = (unsigned)r * 272 + c * 16;
        if (gr < bnd) {
            cp16(hB + so, Ahi + (size_t)gr * 128 + c * 8, 16);
            cp16(lB + so, Alo + (size_t)gr * 128 + c * 8, 16);
        } else {
            uint2 h0 = make_uint2(0,0), l0 = make_uint2(0,0);
            uint2 h1 = make_uint2(0,0), l1 = make_uint2(0,0);
            if (gr < M) {
                float4 a = *(const float4*)(INIT + (size_t)gr * 128 + c * 8);
                float4 b = *(const float4*)(INIT + (size_t)gr * 128 + c * 8 + 4);
                split4(a, h0, l0); split4(b, h1, l1);
            }
            *(uint2*)(hP + so) = h0; *(uint2*)(hP + so + 8) = h1;
            *(uint2*)(lP + so) = l0; *(uint2*)(lP + so + 8) = l1;
        }
    }
    cp_commit();
}

__global__ void __launch_bounds__(256, 1) final_pers(
    const __nv_bfloat16* __restrict__ CTXhi, const __nv_bfloat16* __restrict__ CTXlo,
    const __nv_bfloat16* __restrict__ Ahi, const __nv_bfloat16* __restrict__ Alo,
    const float* __restrict__ INIT, int bnd,
    const float* __restrict__ Wf, const float* __restrict__ bf,
    const float* __restrict__ Wh, const float* __restrict__ bh,
    float* __restrict__ out, int M)
{
    extern __shared__ __align__(1024) char sm[];
    const int tid = threadIdx.x, lane = tid & 31, warp = tid >> 5;
    const int g = lane >> 2, tg = lane & 3;
    stage_w<256>(Wf,       256, (__nv_bfloat16*)sm,                (__nv_bfloat16*)(sm + WBYTES),     tid);
    stage_w<256>(Wf + 128, 256, (__nv_bfloat16*)(sm + 2 * WBYTES), (__nv_bfloat16*)(sm + 3 * WBYTES), tid);
    char* xb = sm + 4 * WBYTES;
    __nv_bfloat16* sXhi = (__nv_bfloat16*)xb;
    __nv_bfloat16* sXlo = (__nv_bfloat16*)(xb + WBYTES);

    const int ntiles = (M + 127) >> 7;
    for (int t = blockIdx.x; t < ntiles; t += gridDim.x) {
        int row0 = t * 128;
        int rv = M - row0; if (rv > 128) rv = 128;
        stage_plane128(CTXhi + (size_t)row0 * 128, CTXlo + (size_t)row0 * 128, rv, xb, tid);
        cp_wait<0>();
        __syncthreads();
        float C[16][4]; zero_C(C);
        panel_mma_v3((__nv_bfloat16*)sm, (__nv_bfloat16*)(sm + WBYTES), sXhi, sXlo, warp, lane, C);
        __syncthreads();
        stage_sel128(Ahi, Alo, INIT, bnd, row0, M, xb, tid);
        cp_wait<0>();
        __syncthreads();
        panel_mma_v3((__nv_bfloat16*)(sm + 2 * WBYTES), (__nv_bfloat16*)(sm + 3 * WBYTES),
                     sXhi, sXlo, warp, lane, C);
        float s0 = 0.f, s1 = 0.f;
#pragma unroll
        for (int tt = 0; tt < 16; tt++) {
            int c = tt * 8 + tg * 2;
            float2 bv = *(const float2*)(bf + c);
            float2 wv = *(const float2*)(Wh + c);
            s0 += fmaxf(C[tt][0] + bv.x, 0.f) * wv.x + fmaxf(C[tt][1] + bv.y, 0.f) * wv.y;
            s1 += fmaxf(C[tt][2] + bv.x, 0.f) * wv.x + fmaxf(C[tt][3] + bv.y, 0.f) * wv.y;
        }
        s0 += __shfl_xor_sync(0xffffffffu, s0, 1);
        s0 += __shfl_xor_sync(0xffffffffu, s0, 2);
        s1 += __shfl_xor_sync(0xffffffffu, s1, 1);
        s1 += __shfl_xor_sync(0xffffffffu, s1, 2);
        if (tg == 0) {
            int r0g = row0 + warp * 16 + g, r1g = r0g + 8;
            float bhv = bh[0];
            if (r0g < M) out[r0g] = s0 + bhv;
            if (r1g < M) out[r1g] = s1 + bhv;
        }
        __syncthreads();
    }
}

// ================= tiny-level kernels (verified, 256 threads) =================
__device__ __forceinline__ void stage_planes_pitch(
    const __nv_bfloat16* __restrict__ Ghi, const __nv_bfloat16* __restrict__ Glo,
    int rows_valid, __nv_bfloat16* sXhi, __nv_bfloat16* sXlo, int tid)
{
    unsigned shi = smem_u32(sXhi), slo = smem_u32(sXlo);
#pragma unroll
    for (int i = tid; i < 128 * 16; i += 256) {
        int r = i >> 4, c = i & 15;
        unsigned so = (unsigned)r * 272 + c * 16;
        int sz = (r < rows_valid) ? 16 : 0;
        cp16(shi + so, Ghi + (size_t)r * 128 + c * 8, sz);
        cp16(slo + so, Glo + (size_t)r * 128 + c * 8, sz);
    }
    cp_commit();
    cp_wait<0>();
}

__device__ __forceinline__ void mean4_red_p(
    const float* sE, __nv_bfloat16* __restrict__ Thi, __nv_bfloat16* __restrict__ Tlo,
    int og0, int G, int tid)
{
    int col = tid & 127;
    for (int q = tid >> 7; q < 32; q += 2) {
        int og = og0 + q;
        if (og < G) {
            float v = sE[(4*q)*EPITCH + col] + sE[(4*q+1)*EPITCH + col]
                    + sE[(4*q+2)*EPITCH + col] + sE[(4*q+3)*EPITCH + col];
            __nv_bfloat16 h, l; split1(0.25f * v, h, l);
            Thi[(size_t)og * 128 + col] = h;
            Tlo[(size_t)og * 128 + col] = l;
        }
    }
}
__device__ __forceinline__ void pairadd_red_p(
    const float* sE, const float* __restrict__ init,
    __nv_bfloat16* __restrict__ Ahi, __nv_bfloat16* __restrict__ Alo,
    int og0, int Mout, int tid)
{
    int col = tid & 127;
    for (int q = tid >> 7; q < 64; q += 2) {
        int og = og0 + q;
        if (og < Mout) {
            float v = sE[(2*q)*EPITCH + col] + sE[(2*q+1)*EPITCH + col];
            __nv_bfloat16 h, l;
            split1(init[(size_t)og * 128 + col] + 0.5f * v, h, l);
            Ahi[(size_t)og * 128 + col] = h;
            Alo[(size_t)og * 128 + col] = l;
        }
    }
}
__device__ __forceinline__ void combine_red_p(
    const float* sE, const float* __restrict__ CTH,
    __nv_bfloat16* __restrict__ Ohi, __nv_bfloat16* __restrict__ Olo,
    int row0, int M1, int tid)
{
    int col = tid & 127;
    for (int q = tid >> 7; q < 32; q += 2) {
        int base = row0 + 4 * q;
        if (base < M1) {
            float s = sE[(4*q)*EPITCH + col] + sE[(4*q+1)*EPITCH + col]
                    + sE[(4*q+2)*EPITCH + col] + sE[(4*q+3)*EPITCH + col];
            float tot = CTH[(size_t)(base >> 3) * 128 + col] + s;
#pragma unroll
            for (int s4 = 0; s4 < 4; s4++) {
                __nv_bfloat16 h, l;
                split1(0.25f * (tot - sE[(4*q+s4)*EPITCH + col]), h, l);
                Ohi[(size_t)(base + s4) * 128 + col] = h;
                Olo[(size_t)(base + s4) * 128 + col] = l;
            }
        }
    }
}

__global__ void __launch_bounds__(256) up_small(
    const __nv_bfloat16* __restrict__ Xchi, const __nv_bfloat16* __restrict__ Xclo,
    const float* __restrict__ init_l,
    __nv_bfloat16* __restrict__ Ahi, __nv_bfloat16* __restrict__ Alo,
    const float* __restrict__ Ws, const float* __restrict__ bs,
    const float* __restrict__ Wc, const float* __restrict__ bc,
    __nv_bfloat16* __restrict__ Thi, __nv_bfloat16* __restrict__ Tlo, int M1)
{
    extern __shared__ __align__(1024) char sm[];
    __nv_bfloat16 *sWhi = (__nv_bfloat16*)sm, *sWlo = (__nv_bfloat16*)(sm + WBYTES);
    __nv_bfloat16 *sXhi = (__nv_bfloat16*)(sm + 2 * WBYTES), *sXlo = (__nv_bfloat16*)(sm + 3 * WBYTES);
    float* sE = (float*)(sm + 2 * WBYTES);
    const int tid = threadIdx.x, lane = tid & 31, warp = tid >> 5;
    const int g = lane >> 2, tg = lane & 3;
    const int G = M1 >> 2, Mout = M1 >> 3;

    stage_w<256>(Ws, 128, sWhi, sWlo, tid);
    stage_planes_pitch(Xchi, Xclo, M1, sXhi, sXlo, tid);
    __syncthreads();
    {
        float C[16][4]; zero_C(C);
        panel_mma_v3(sWhi, sWlo, sXhi, sXlo, warp, lane, C);
        __syncthreads();
        epilogue_to_smem(C, bs, sE, warp, g, tg);
        __syncthreads();
        mean4_red_p(sE, Thi, Tlo, 0, G, tid);
    }
    __syncthreads();
    stage_w<256>(Wc, 128, sWhi, sWlo, tid);
#pragma unroll
    for (int i = tid; i < 128 * 32; i += 256) {
        int r = i >> 5, c4 = (i & 31) * 4;
        uint2 hv = make_uint2(0,0), lv = make_uint2(0,0);
        if (r < G) {
            hv = *(const uint2*)(Thi + (size_t)r * 128 + c4);
            lv = *(const uint2*)(Tlo + (size_t)r * 128 + c4);
        }
        *(uint2*)(sXhi + (size_t)r * SPITCH + c4) = hv;
        *(uint2*)(sXlo + (size_t)r * SPITCH + c4) = lv;
    }
    __syncthreads();
    {
        float C[16][4]; zero_C(C);
        panel_mma_v3(sWhi, sWlo, sXhi, sXlo, warp, lane, C);
        __syncthreads();
        epilogue_to_smem(C, bc, sE, warp, g, tg);
        __syncthreads();
        pairadd_red_p(sE, init_l, Ahi, Alo, 0, Mout, tid);
    }
}

__global__ void __launch_bounds__(256) down_small(
    const __nv_bfloat16* __restrict__ CTXhi, const __nv_bfloat16* __restrict__ CTXlo,
    const __nv_bfloat16* __restrict__ AChi, const __nv_bfloat16* __restrict__ AClo,
    const float* __restrict__ Wx, const float* __restrict__ bx,
    float* __restrict__ CTH,
    __nv_bfloat16* __restrict__ Ohi, __nv_bfloat16* __restrict__ Olo, int Ml, int M1)
{
    extern __shared__ __align__(1024) char sm[];
    __nv_bfloat16 *sWhi = (__nv_bfloat16*)sm, *sWlo = (__nv_bfloat16*)(sm + WBYTES);
    __nv_bfloat16 *sXhi = (__nv_bfloat16*)(sm + 2 * WBYTES), *sXlo = (__nv_bfloat16*)(sm + 3 * WBYTES);
    float* sE = (float*)(sm + 2 * WBYTES);
    const int tid = threadIdx.x, lane = tid & 31, warp = tid >> 5;
    const int g = lane >> 2, tg = lane & 3;

    stage_w<256>(Wx, 128, sWhi, sWlo, tid);
    stage_planes_pitch(CTXhi, CTXlo, Ml, sXhi, sXlo, tid);
    __syncthreads();
    {
        float C[16][4]; zero_C(C);
        panel_mma_v3(sWhi, sWlo, sXhi, sXlo, warp, lane, C);
        const int r0 = warp * 16 + g, r1 = r0 + 8;
#pragma unroll
        for (int t = 0; t < 16; t++) {
            int c = t * 8 + tg * 2;
            float2 bv = *(const float2*)(bx + c);
            if (r0 < Ml) *(float2*)(CTH + (size_t)r0 * 128 + c) =
                make_float2(fmaxf(C[t][0] + bv.x, 0.f), fmaxf(C[t][1] + bv.y, 0.f));
            if (r1 < Ml) *(float2*)(CTH + (size_t)r1 * 128 + c) =
                make_float2(fmaxf(C[t][2] + bv.x, 0.f), fmaxf(C[t][3] + bv.y, 0.f));
        }
    }
    __syncthreads();
    stage_planes_pitch(AChi, AClo, M1, sXhi, sXlo, tid);
    __syncthreads();
    {
        float C[16][4]; zero_C(C);
        panel_mma_v3(sWhi, sWlo, sXhi, sXlo, warp, lane, C);
        __syncthreads();
        epilogue_to_smem(C, bx, sE, warp, g, tg);
        __syncthreads();
        combine_red_p(sE, CTH, Ohi, Olo, 0, M1, tid);
    }
}

__global__ void set_ones_planes(__nv_bfloat16* hi, __nv_bfloat16* lo)
{
    int i = threadIdx.x;
    hi[i] = __float2bfloat16(1.0f);
    lo[i] = __float2bfloat16(0.0f);
}

// ---------------- launch ----------------
static inline int grid64(int rows) {
    int nt = (rows + 63) >> 6;
    return nt < 296 ? nt : 296;
}

extern "C" void kernel_launch(void* const* d_in, const int* in_sizes, int n_in,
                              void* d_out, int out_size)
{
    const float* initial = (const float*)d_in[0];
    const float* Ws = (const float*)d_in[1];
    const float* bs = (const float*)d_in[2];
    const float* Wc = (const float*)d_in[3];
    const float* bc = (const float*)d_in[4];
    const float* Wx = (const float*)d_in[5];
    const float* bx = (const float*)d_in[6];
    const float* Wf = (const float*)d_in[7];
    const float* bf = (const float*)d_in[8];
    const float* Wh = (const float*)d_in[9];
    const float* bh = (const float*)d_in[10];
    float* out = (float*)d_out;

    __nv_bfloat16 *aggh, *aggl, *ctxh, *ctxl, *t2h, *t2l;
    float* cth;
    cudaGetSymbolAddress((void**)&aggh, g_agg_hi);
    cudaGetSymbolAddress((void**)&aggl, g_agg_lo);
    cudaGetSymbolAddress((void**)&ctxh, g_ctx_hi);
    cudaGetSymbolAddress((void**)&ctxl, g_ctx_lo);
    cudaGetSymbolAddress((void**)&t2h,  g_t2_hi);
    cudaGetSymbolAddress((void**)&t2l,  g_t2_lo);
    cudaGetSymbolAddress((void**)&cth,  g_cth);

    cudaFuncSetAttribute(up_mean4_64,     cudaFuncAttributeMaxDynamicSharedMemorySize, SMEM_64);
    cudaFuncSetAttribute(up_pairadd_64,   cudaFuncAttributeMaxDynamicSharedMemorySize, SMEM_64);
    cudaFuncSetAttribute(cth_64,          cudaFuncAttributeMaxDynamicSharedMemorySize, SMEM_64);
    cudaFuncSetAttribute(down_combine_64, cudaFuncAttributeMaxDynamicSharedMemorySize, SMEM_64);
    cudaFuncSetAttribute(final_pers,      cudaFuncAttributeMaxDynamicSharedMemorySize, SMEM_FIN);
    cudaFuncSetAttribute(up_small,        cudaFuncAttributeMaxDynamicSharedMemorySize, SMEM_SMALL);
    cudaFuncSetAttribute(down_small,      cudaFuncAttributeMaxDynamicSharedMemorySize, SMEM_SMALL);

    const float* leaf_f32 = initial + (size_t)H_OFFS[6] * DIM;

    // ---- up pass: levels 5..2 ----
    for (int l = 5; l >= 2; l--) {
        int M1 = H_SIZES[l + 1];
        int G  = M1 >> 2;
        if (l == 5)
            up_mean4_64<<<grid64(M1), 128, SMEM_64>>>(
                nullptr, nullptr, leaf_f32, 1, Ws, bs, t2h, t2l, M1);
        else
            up_mean4_64<<<grid64(M1), 128, SMEM_64>>>(
                aggh + (size_t)H_OFFS[l + 1] * DIM, aggl + (size_t)H_OFFS[l + 1] * DIM,
                nullptr, 0, Ws, bs, t2h, t2l, M1);
        up_pairadd_64<<<grid64(G), 128, SMEM_64>>>(
            t2h, t2l, Wc, bc,
            initial + (size_t)H_OFFS[l] * DIM,
            aggh + (size_t)H_OFFS[l] * DIM, aggl + (size_t)H_OFFS[l] * DIM, G);
    }
    for (int l = 1; l >= 0; l--) {
        up_small<<<1, 256, SMEM_SMALL>>>(
            aggh + (size_t)H_OFFS[l + 1] * DIM, aggl + (size_t)H_OFFS[l + 1] * DIM,
            initial + (size_t)H_OFFS[l] * DIM,
            aggh + (size_t)H_OFFS[l] * DIM, aggl + (size_t)H_OFFS[l] * DIM,
            Ws, bs, Wc, bc, t2h, t2l, H_SIZES[l + 1]);
    }

    // ---- down pass ----
    set_ones_planes<<<1, 128>>>(ctxh, ctxl);
    for (int l = 0; l < 2; l++) {
        down_small<<<1, 256, SMEM_SMALL>>>(
            ctxh + (size_t)H_OFFS[l] * DIM, ctxl + (size_t)H_OFFS[l] * DIM,
            aggh + (size_t)H_OFFS[l + 1] * DIM, aggl + (size_t)H_OFFS[l + 1] * DIM,
            Wx, bx, cth,
            ctxh + (size_t)H_OFFS[l + 1] * DIM, ctxl + (size_t)H_OFFS[l + 1] * DIM,
            H_SIZES[l], H_SIZES[l + 1]);
    }
    for (int l = 2; l < 6; l++) {
        int Ml = H_SIZES[l], M1 = H_SIZES[l + 1];
        cth_64<<<grid64(Ml), 128, SMEM_64>>>(
            ctxh + (size_t)H_OFFS[l] * DIM, ctxl + (size_t)H_OFFS[l] * DIM,
            Wx, bx, cth, Ml);
        if (l == 5)
            down_combine_64<<<grid64(M1), 128, SMEM_64>>>(
                nullptr, nullptr, leaf_f32, 1, Wx, bx, cth,
                ctxh + (size_t)H_OFFS[l + 1] * DIM, ctxl + (size_t)H_OFFS[l + 1] * DIM, M1);
        else
            down_combine_64<<<grid64(M1), 128, SMEM_64>>>(
                aggh + (size_t)H_OFFS[l + 1] * DIM, aggl + (size_t)H_OFFS[l + 1] * DIM,
                nullptr, 0, Wx, bx, cth,
                ctxh + (size_t)H_OFFS[l + 1] * DIM, ctxl + (size_t)H_OFFS[l + 1] * DIM, M1);
    }

    // ---- final ----
    final_pers<<<148, 256, SMEM_FIN>>>(
        ctxh, ctxl, aggh, aggl, initial, NTOP,
        Wf, bf, Wh, bh, out, N_TOTAL);
}

// round 12
// speedup vs baseline: 1.5584x; 1.3312x over previous
#include <cuda_runtime.h>
#include <cuda_fp16.h>
#include <cstdint>

#define DIM 128
#define N_TOTAL 299593
#define NTOP 37449

static const int H_SIZES[7] = {1, 8, 64, 512, 4096, 32768, 262144};
static const int H_OFFS[8]  = {0, 1, 9, 73, 585, 4681, 37449, 299593};

// ---------------- scratch: activations as single fp16 planes ----------------
__device__ __half g_agg[NTOP * DIM];
__device__ __half g_ctx[N_TOTAL * DIM];
__device__ __half g_t2 [65536 * DIM];
__device__ float  g_cth[32768 * DIM];

// ================= common =================
#define SPITCH 136                       // fp16 elems per smem row (272 B)
#define WB     34816                     // one 128-row fp16 plane (128*272)
#define XB64   17408                     // 64-row fp16 plane
#define EPITCH 132

#define SMEM_64  (2 * WB + WB)           // Whi,Wlo + X/sE region  = 104448 -> 2 blocks/SM
#define SMEM_FIN (5 * WB)                // 2 W panels hi/lo + X   = 174080
#define SMEM_SMALL (2 * WB + 2 * WB)     // Whi,Wlo + X/sE region  = 139264

__device__ __forceinline__ uint32_t smem_u32(const void* p) {
    return (uint32_t)__cvta_generic_to_shared(p);
}
__device__ __forceinline__ void splith(float f, __half& h, __half& l) {
    h = __float2half_rn(f);
    l = __float2half_rn(f - __half2float(h));
}
// 4 floats -> 4 hi halfs + 4 lo halfs (packed)
__device__ __forceinline__ void splitw4(float4 v, uint2& hv, uint2& lv) {
    __half h0,h1,h2,h3,l0,l1,l2,l3;
    splith(v.x,h0,l0); splith(v.y,h1,l1); splith(v.z,h2,l2); splith(v.w,h3,l3);
    hv.x = ((unsigned)__half_as_ushort(h1)<<16) | __half_as_ushort(h0);
    hv.y = ((unsigned)__half_as_ushort(h3)<<16) | __half_as_ushort(h2);
    lv.x = ((unsigned)__half_as_ushort(l1)<<16) | __half_as_ushort(l0);
    lv.y = ((unsigned)__half_as_ushort(l3)<<16) | __half_as_ushort(l2);
}
// 8 floats -> 8 halfs packed in uint4 (single precision plane)
__device__ __forceinline__ uint4 pack8h(float4 a, float4 b) {
    uint4 r;
    r.x = ((unsigned)__half_as_ushort(__float2half_rn(a.y))<<16) | __half_as_ushort(__float2half_rn(a.x));
    r.y = ((unsigned)__half_as_ushort(__float2half_rn(a.w))<<16) | __half_as_ushort(__float2half_rn(a.z));
    r.z = ((unsigned)__half_as_ushort(__float2half_rn(b.y))<<16) | __half_as_ushort(__float2half_rn(b.x));
    r.w = ((unsigned)__half_as_ushort(__float2half_rn(b.w))<<16) | __half_as_ushort(__float2half_rn(b.z));
    return r;
}
__device__ __forceinline__ void cp16(unsigned saddr, const void* gptr, int sz) {
    asm volatile("cp.async.cg.shared.global [%0], [%1], 16, %2;"
                 :: "r"(saddr), "l"(gptr), "r"(sz));
}
template<int N>
__device__ __forceinline__ void cp_wait() {
    asm volatile("cp.async.wait_group %0;" :: "n"(N) : "memory");
}
__device__ __forceinline__ void cp_commit() {
    asm volatile("cp.async.commit_group;");
}

__device__ __forceinline__ void mma_f16(float* c, const unsigned* a, unsigned b0, unsigned b1)
{
    asm volatile(
        "mma.sync.aligned.m16n8k16.row.col.f32.f16.f16.f32 "
        "{%0,%1,%2,%3},{%4,%5,%6,%7},{%8,%9},{%0,%1,%2,%3};\n"
        : "+f"(c[0]), "+f"(c[1]), "+f"(c[2]), "+f"(c[3])
        : "r"(a[0]), "r"(a[1]), "r"(a[2]), "r"(a[3]), "r"(b0), "r"(b1));
}
__device__ __forceinline__ void ldsm4(unsigned* r, unsigned addr)
{
    asm volatile("ldmatrix.sync.aligned.m8n8.x4.shared.b16 {%0,%1,%2,%3}, [%4];"
                 : "=r"(r[0]), "=r"(r[1]), "=r"(r[2]), "=r"(r[3]) : "r"(addr));
}

// ---- W staging: fp32 -> fp16 hi/lo pitch smem ----
template <int NTHR>
__device__ __forceinline__ void stage_w(
    const float* __restrict__ G, int gstride,
    __half* sWhi, __half* sWlo, int tid)
{
    constexpr int ITERS = 4096 / NTHR;
#pragma unroll
    for (int b = 0; b < ITERS; b += 8) {
        float4 v[8];
#pragma unroll
        for (int j = 0; j < 8; j++) {
            int idx = tid + (b + j) * NTHR;
            v[j] = *(const float4*)(G + (size_t)(idx >> 5) * gstride + (idx & 31) * 4);
        }
#pragma unroll
        for (int j = 0; j < 8; j++) {
            int idx = tid + (b + j) * NTHR;
            int r = idx >> 5, c4 = (idx & 31) * 4;
            uint2 hv, lv; splitw4(v[j], hv, lv);
            *(uint2*)(sWhi + (size_t)r * SPITCH + c4) = hv;
            *(uint2*)(sWlo + (size_t)r * SPITCH + c4) = lv;
        }
    }
}

// ---- X staging (single fp16 plane) via cp.async ----
template <int NROWS, int NTHR>
__device__ __forceinline__ void stage_plane(
    const __half* __restrict__ G, int rows_valid, char* buf, int tid)
{
    unsigned hB = smem_u32(buf);
#pragma unroll
    for (int i = tid; i < NROWS * 16; i += NTHR) {
        int r = i >> 4, c = i & 15;
        unsigned so = (unsigned)r * 272 + c * 16;
        int sz = (r < rows_valid) ? 16 : 0;
        cp16(hB + so, G + (size_t)r * 128 + c * 8, sz);
    }
    cp_commit();
}

// ---- leaf staging: fp32 -> fp16 single plane (register path) ----
template <int NTHR>
__device__ __forceinline__ void stage_leaf(
    const float* __restrict__ F32, int grow0, int M, int nrows, char* buf, int tid)
{
    const int tot = nrows * 16;            // 16 chunks of 8 elems per row
    for (int i = tid; i < tot; i += NTHR) {
        int r = i >> 4, c = i & 15;
        int gr = grow0 + r;
        float4 a = make_float4(0.f,0.f,0.f,0.f), b = a;
        if (gr < M) {
            a = *(const float4*)(F32 + (size_t)gr * 128 + c * 8);
            b = *(const float4*)(F32 + (size_t)gr * 128 + c * 8 + 4);
        }
        *(uint4*)(buf + (size_t)r * 272 + c * 16) = pack8h(a, b);
    }
}

// final agg-panel: rows<bnd from fp16 plane, else leaf fp32 rows
__device__ __forceinline__ void stage_sel128(
    const __half* __restrict__ A, const float* __restrict__ INIT,
    int bnd, int grow0, int M, char* buf, int tid)
{
    unsigned hB = smem_u32(buf);
    for (int i = tid; i < 2048; i += 256) {
        int r = i >> 4, c = i & 15;
        int gr = grow0 + r;
        unsigned so = (unsigned)r * 272 + c * 16;
        if (gr < bnd) {
            cp16(hB + so, A + (size_t)gr * 128 + c * 8, 16);
        } else {
            float4 a = make_float4(0.f,0.f,0.f,0.f), b = a;
            if (gr < M) {
                a = *(const float4*)(INIT + (size_t)gr * 128 + c * 8);
                b = *(const float4*)(INIT + (size_t)gr * 128 + c * 8 + 4);
            }
            *(uint4*)(buf + so) = pack8h(a, b);
        }
    }
    cp_commit();
}

// ---- mainloop: fp16 2-pass (A single, W hi+lo), B fragments preloaded ----
__device__ __forceinline__ void panel_f16(
    const __half* sWhi, const __half* sWlo, const __half* sX,
    int warp, int lane, float C[16][4])
{
    const unsigned wh = smem_u32(sWhi), wl = smem_u32(sWlo);
    const unsigned xh = smem_u32(sX);
    const unsigned PB = SPITCH * 2;
    const unsigned aoff0 = (unsigned)(warp * 16 + (lane & 15)) * PB + (unsigned)((lane >> 4) & 1) * 16u;
    const unsigned boff0 = (unsigned)((lane & 7) + ((lane & 16) >> 1)) * PB + ((lane & 8) ? 16u : 0u);

    for (int kc = 0; kc < 8; kc++) {
        const unsigned ka = kc * 32;
        unsigned ah[4];
        ldsm4(ah, xh + aoff0 + ka);
        unsigned bhi[8][4];
#pragma unroll
        for (int p = 0; p < 8; p++) ldsm4(bhi[p], wh + boff0 + (unsigned)p * 16 * PB + ka);
#pragma unroll
        for (int p = 0; p < 8; p++) {
            mma_f16(C[2*p],   ah, bhi[p][0], bhi[p][1]);
            mma_f16(C[2*p+1], ah, bhi[p][2], bhi[p][3]);
        }
        unsigned blo[8][4];
#pragma unroll
        for (int p = 0; p < 8; p++) ldsm4(blo[p], wl + boff0 + (unsigned)p * 16 * PB + ka);
#pragma unroll
        for (int p = 0; p < 8; p++) {
            mma_f16(C[2*p],   ah, blo[p][0], blo[p][1]);
            mma_f16(C[2*p+1], ah, blo[p][2], blo[p][3]);
        }
    }
}

__device__ __forceinline__ void zero_C(float C[16][4])
{
#pragma unroll
    for (int t = 0; t < 16; t++) C[t][0] = C[t][1] = C[t][2] = C[t][3] = 0.f;
}

__device__ __forceinline__ void epilogue_to_smem(
    const float C[16][4], const float* __restrict__ bias, float* sE, int warp, int g, int tg)
{
    const int r0 = warp * 16 + g, r1 = r0 + 8;
#pragma unroll
    for (int t = 0; t < 16; t++) {
        int c = t * 8 + tg * 2;
        float2 bv = *(const float2*)(bias + c);
        sE[r0 * EPITCH + c]     = fmaxf(C[t][0] + bv.x, 0.f);
        sE[r0 * EPITCH + c + 1] = fmaxf(C[t][1] + bv.y, 0.f);
        sE[r1 * EPITCH + c]     = fmaxf(C[t][2] + bv.x, 0.f);
        sE[r1 * EPITCH + c + 1] = fmaxf(C[t][3] + bv.y, 0.f);
    }
}

// ---- reduce epilogues over sE, fp16 plane output ----
// 64-row variants (128 threads, col = tid)
__device__ __forceinline__ void mean4_red64(
    const float* sE, __half* __restrict__ T2, int og0, int G, int col)
{
#pragma unroll 4
    for (int q = 0; q < 16; q++) {
        int og = og0 + q;
        if (og < G) {
            float v = sE[(4*q)*EPITCH + col] + sE[(4*q+1)*EPITCH + col]
                    + sE[(4*q+2)*EPITCH + col] + sE[(4*q+3)*EPITCH + col];
            T2[(size_t)og * 128 + col] = __float2half_rn(0.25f * v);
        }
    }
}
__device__ __forceinline__ void pairadd_red64(
    const float* sE, const float* __restrict__ init,
    __half* __restrict__ A, int og0, int Mout, int col)
{
#pragma unroll 4
    for (int q = 0; q < 32; q++) {
        int og = og0 + q;
        if (og < Mout) {
            float v = sE[(2*q)*EPITCH + col] + sE[(2*q+1)*EPITCH + col];
            A[(size_t)og * 128 + col] =
                __float2half_rn(init[(size_t)og * 128 + col] + 0.5f * v);
        }
    }
}
__device__ __forceinline__ void combine_red64(
    const float* sE, const float* __restrict__ CTH,
    __half* __restrict__ O, int row0, int M1, int col)
{
#pragma unroll 2
    for (int q = 0; q < 16; q++) {
        int base = row0 + 4 * q;
        if (base < M1) {
            float s = sE[(4*q)*EPITCH + col] + sE[(4*q+1)*EPITCH + col]
                    + sE[(4*q+2)*EPITCH + col] + sE[(4*q+3)*EPITCH + col];
            float tot = CTH[(size_t)(base >> 3) * 128 + col] + s;
#pragma unroll
            for (int s4 = 0; s4 < 4; s4++)
                O[(size_t)(base + s4) * 128 + col] =
                    __float2half_rn(0.25f * (tot - sE[(4*q+s4)*EPITCH + col]));
        }
    }
}
// 128-row variants (256 threads)
__device__ __forceinline__ void mean4_red128(
    const float* sE, __half* __restrict__ T2, int og0, int G, int tid)
{
    int col = tid & 127;
    for (int q = tid >> 7; q < 32; q += 2) {
        int og = og0 + q;
        if (og < G) {
            float v = sE[(4*q)*EPITCH + col] + sE[(4*q+1)*EPITCH + col]
                    + sE[(4*q+2)*EPITCH + col] + sE[(4*q+3)*EPITCH + col];
            T2[(size_t)og * 128 + col] = __float2half_rn(0.25f * v);
        }
    }
}
__device__ __forceinline__ void pairadd_red128(
    const float* sE, const float* __restrict__ init,
    __half* __restrict__ A, int og0, int Mout, int tid)
{
    int col = tid & 127;
    for (int q = tid >> 7; q < 64; q += 2) {
        int og = og0 + q;
        if (og < Mout) {
            float v = sE[(2*q)*EPITCH + col] + sE[(2*q+1)*EPITCH + col];
            A[(size_t)og * 128 + col] =
                __float2half_rn(init[(size_t)og * 128 + col] + 0.5f * v);
        }
    }
}
__device__ __forceinline__ void combine_red128(
    const float* sE, const float* __restrict__ CTH,
    __half* __restrict__ O, int row0, int M1, int tid)
{
    int col = tid & 127;
    for (int q = tid >> 7; q < 32; q += 2) {
        int base = row0 + 4 * q;
        if (base < M1) {
            float s = sE[(4*q)*EPITCH + col] + sE[(4*q+1)*EPITCH + col]
                    + sE[(4*q+2)*EPITCH + col] + sE[(4*q+3)*EPITCH + col];
            float tot = CTH[(size_t)(base >> 3) * 128 + col] + s;
#pragma unroll
            for (int s4 = 0; s4 < 4; s4++)
                O[(size_t)(base + s4) * 128 + col] =
                    __float2half_rn(0.25f * (tot - sE[(4*q+s4)*EPITCH + col]));
        }
    }
}

// ================= 64-row-tile kernels: 128 threads, 2 blocks/SM =================

__global__ void __launch_bounds__(128, 2) up_mean4_64(
    const __half* __restrict__ X, const float* __restrict__ Xf32, int leaf,
    const float* __restrict__ W, const float* __restrict__ bias,
    __half* __restrict__ T2, int M1)
{
    extern __shared__ __align__(1024) char sm[];
    const int tid = threadIdx.x, lane = tid & 31, warp = tid >> 5;
    const int g = lane >> 2, tg = lane & 3;
    __half* sWhi = (__half*)sm;
    __half* sWlo = (__half*)(sm + WB);
    char* xb = sm + 2 * WB;
    stage_w<128>(W, 128, sWhi, sWlo, tid);

    const int ntiles = (M1 + 63) >> 6;
    for (int t = blockIdx.x; t < ntiles; t += gridDim.x) {
        if (leaf) stage_leaf<128>(Xf32, t * 64, M1, 64, xb, tid);
        else { stage_plane<64,128>(X + (size_t)t * 8192, M1 - t * 64, xb, tid); cp_wait<0>(); }
        __syncthreads();
        float C[16][4]; zero_C(C);
        panel_f16(sWhi, sWlo, (__half*)xb, warp, lane, C);
        __syncthreads();
        float* sE = (float*)xb;
        epilogue_to_smem(C, bias, sE, warp, g, tg);
        __syncthreads();
        mean4_red64(sE, T2, t * 16, M1 >> 2, tid);
        __syncthreads();
    }
}

__global__ void __launch_bounds__(128, 2) up_pairadd_64(
    const __half* __restrict__ X,
    const float* __restrict__ W, const float* __restrict__ bias,
    const float* __restrict__ init, __half* __restrict__ A, int G)
{
    extern __shared__ __align__(1024) char sm[];
    const int tid = threadIdx.x, lane = tid & 31, warp = tid >> 5;
    const int g = lane >> 2, tg = lane & 3;
    __half* sWhi = (__half*)sm;
    __half* sWlo = (__half*)(sm + WB);
    char* xb = sm + 2 * WB;
    stage_w<128>(W, 128, sWhi, sWlo, tid);

    const int ntiles = (G + 63) >> 6;
    for (int t = blockIdx.x; t < ntiles; t += gridDim.x) {
        stage_plane<64,128>(X + (size_t)t * 8192, G - t * 64, xb, tid);
        cp_wait<0>();
        __syncthreads();
        float C[16][4]; zero_C(C);
        panel_f16(sWhi, sWlo, (__half*)xb, warp, lane, C);
        __syncthreads();
        float* sE = (float*)xb;
        epilogue_to_smem(C, bias, sE, warp, g, tg);
        __syncthreads();
        pairadd_red64(sE, init, A, t * 32, G >> 1, tid);
        __syncthreads();
    }
}

__global__ void __launch_bounds__(128, 2) cth_64(
    const __half* __restrict__ X,
    const float* __restrict__ W, const float* __restrict__ bias,
    float* __restrict__ Y, int M)
{
    extern __shared__ __align__(1024) char sm[];
    const int tid = threadIdx.x, lane = tid & 31, warp = tid >> 5;
    const int g = lane >> 2, tg = lane & 3;
    __half* sWhi = (__half*)sm;
    __half* sWlo = (__half*)(sm + WB);
    char* xb = sm + 2 * WB;
    stage_w<128>(W, 128, sWhi, sWlo, tid);

    const int ntiles = (M + 63) >> 6;
    for (int t = blockIdx.x; t < ntiles; t += gridDim.x) {
        int rv = M - t * 64; if (rv > 64) rv = 64;
        stage_plane<64,128>(X + (size_t)t * 8192, rv, xb, tid);
        cp_wait<0>();
        __syncthreads();
        float C[16][4]; zero_C(C);
        panel_f16(sWhi, sWlo, (__half*)xb, warp, lane, C);
        const int r0g = t * 64 + warp * 16 + g, r1g = r0g + 8;
#pragma unroll
        for (int tt = 0; tt < 16; tt++) {
            int c = tt * 8 + tg * 2;
            float2 bv = *(const float2*)(bias + c);
            if (r0g < M) *(float2*)(Y + (size_t)r0g * 128 + c) =
                make_float2(fmaxf(C[tt][0] + bv.x, 0.f), fmaxf(C[tt][1] + bv.y, 0.f));
            if (r1g < M) *(float2*)(Y + (size_t)r1g * 128 + c) =
                make_float2(fmaxf(C[tt][2] + bv.x, 0.f), fmaxf(C[tt][3] + bv.y, 0.f));
        }
        __syncthreads();
    }
}

__global__ void __launch_bounds__(128, 2) down_combine_64(
    const __half* __restrict__ X, const float* __restrict__ Xf32, int leaf,
    const float* __restrict__ W, const float* __restrict__ bias,
    const float* __restrict__ CTH, __half* __restrict__ O, int M1)
{
    extern __shared__ __align__(1024) char sm[];
    const int tid = threadIdx.x, lane = tid & 31, warp = tid >> 5;
    const int g = lane >> 2, tg = lane & 3;
    __half* sWhi = (__half*)sm;
    __half* sWlo = (__half*)(sm + WB);
    char* xb = sm + 2 * WB;
    stage_w<128>(W, 128, sWhi, sWlo, tid);

    const int ntiles = (M1 + 63) >> 6;
    for (int t = blockIdx.x; t < ntiles; t += gridDim.x) {
        if (leaf) stage_leaf<128>(Xf32, t * 64, M1, 64, xb, tid);
        else { stage_plane<64,128>(X + (size_t)t * 8192, M1 - t * 64, xb, tid); cp_wait<0>(); }
        __syncthreads();
        float C[16][4]; zero_C(C);
        panel_f16(sWhi, sWlo, (__half*)xb, warp, lane, C);
        __syncthreads();
        float* sE = (float*)xb;
        epilogue_to_smem(C, bias, sE, warp, g, tg);
        __syncthreads();
        combine_red64(sE, CTH, O, t * 64, M1, tid);
        __syncthreads();
    }
}

// ================= final kernel (256 threads, 128-row tiles) =================
__global__ void __launch_bounds__(256, 1) final_pers(
    const __half* __restrict__ CTX, const __half* __restrict__ AGG,
    const float* __restrict__ INIT, int bnd,
    const float* __restrict__ Wf, const float* __restrict__ bf,
    const float* __restrict__ Wh, const float* __restrict__ bh,
    float* __restrict__ out, int M)
{
    extern __shared__ __align__(1024) char sm[];
    const int tid = threadIdx.x, lane = tid & 31, warp = tid >> 5;
    const int g = lane >> 2, tg = lane & 3;
    stage_w<256>(Wf,       256, (__half*)sm,            (__half*)(sm + WB),     tid);
    stage_w<256>(Wf + 128, 256, (__half*)(sm + 2 * WB), (__half*)(sm + 3 * WB), tid);
    char* xb = sm + 4 * WB;
    __half* sX = (__half*)xb;

    const int ntiles = (M + 127) >> 7;
    for (int t = blockIdx.x; t < ntiles; t += gridDim.x) {
        int row0 = t * 128;
        int rv = M - row0; if (rv > 128) rv = 128;
        stage_plane<128,256>(CTX + (size_t)row0 * 128, rv, xb, tid);
        cp_wait<0>();
        __syncthreads();
        float C[16][4]; zero_C(C);
        panel_f16((__half*)sm, (__half*)(sm + WB), sX, warp, lane, C);
        __syncthreads();
        stage_sel128(AGG, INIT, bnd, row0, M, xb, tid);
        cp_wait<0>();
        __syncthreads();
        panel_f16((__half*)(sm + 2 * WB), (__half*)(sm + 3 * WB), sX, warp, lane, C);
        float s0 = 0.f, s1 = 0.f;
#pragma unroll
        for (int tt = 0; tt < 16; tt++) {
            int c = tt * 8 + tg * 2;
            float2 bv = *(const float2*)(bf + c);
            float2 wv = *(const float2*)(Wh + c);
            s0 += fmaxf(C[tt][0] + bv.x, 0.f) * wv.x + fmaxf(C[tt][1] + bv.y, 0.f) * wv.y;
            s1 += fmaxf(C[tt][2] + bv.x, 0.f) * wv.x + fmaxf(C[tt][3] + bv.y, 0.f) * wv.y;
        }
        s0 += __shfl_xor_sync(0xffffffffu, s0, 1);
        s0 += __shfl_xor_sync(0xffffffffu, s0, 2);
        s1 += __shfl_xor_sync(0xffffffffu, s1, 1);
        s1 += __shfl_xor_sync(0xffffffffu, s1, 2);
        if (tg == 0) {
            int r0g = row0 + warp * 16 + g, r1g = r0g + 8;
            float bhv = bh[0];
            if (r0g < M) out[r0g] = s0 + bhv;
            if (r1g < M) out[r1g] = s1 + bhv;
        }
        __syncthreads();
    }
}

// ================= tiny-level kernels (256 threads, single block) =================
__global__ void __launch_bounds__(256) up_small(
    const __half* __restrict__ Xc, const float* __restrict__ init_l,
    __half* __restrict__ A,
    const float* __restrict__ Ws, const float* __restrict__ bs,
    const float* __restrict__ Wc, const float* __restrict__ bc,
    __half* __restrict__ T2, int M1)
{
    extern __shared__ __align__(1024) char sm[];
    __half *sWhi = (__half*)sm, *sWlo = (__half*)(sm + WB);
    char* xb = sm + 2 * WB;
    __half* sX = (__half*)xb;
    float* sE = (float*)xb;
    const int tid = threadIdx.x, lane = tid & 31, warp = tid >> 5;
    const int g = lane >> 2, tg = lane & 3;
    const int G = M1 >> 2, Mout = M1 >> 3;

    stage_w<256>(Ws, 128, sWhi, sWlo, tid);
    stage_plane<128,256>(Xc, M1, xb, tid);
    cp_wait<0>();
    __syncthreads();
    {
        float C[16][4]; zero_C(C);
        panel_f16(sWhi, sWlo, sX, warp, lane, C);
        __syncthreads();
        epilogue_to_smem(C, bs, sE, warp, g, tg);
        __syncthreads();
        mean4_red128(sE, T2, 0, G, tid);
    }
    __syncthreads();
    stage_w<256>(Wc, 128, sWhi, sWlo, tid);
    // T2 -> smem (sync)
    for (int i = tid; i < 128 * 16; i += 256) {
        int r = i >> 4, c = i & 15;
        uint4 v = make_uint4(0,0,0,0);
        if (r < G) v = *(const uint4*)(T2 + (size_t)r * 128 + c * 8);
        *(uint4*)(xb + (size_t)r * 272 + c * 16) = v;
    }
    __syncthreads();
    {
        float C[16][4]; zero_C(C);
        panel_f16(sWhi, sWlo, sX, warp, lane, C);
        __syncthreads();
        epilogue_to_smem(C, bc, sE, warp, g, tg);
        __syncthreads();
        pairadd_red128(sE, init_l, A, 0, Mout, tid);
    }
}

__global__ void __launch_bounds__(256) down_small(
    const __half* __restrict__ CTX, const __half* __restrict__ AC,
    const float* __restrict__ Wx, const float* __restrict__ bx,
    float* __restrict__ CTH, __half* __restrict__ O, int Ml, int M1)
{
    extern __shared__ __align__(1024) char sm[];
    __half *sWhi = (__half*)sm, *sWlo = (__half*)(sm + WB);
    char* xb = sm + 2 * WB;
    __half* sX = (__half*)xb;
    float* sE = (float*)xb;
    const int tid = threadIdx.x, lane = tid & 31, warp = tid >> 5;
    const int g = lane >> 2, tg = lane & 3;

    stage_w<256>(Wx, 128, sWhi, sWlo, tid);
    stage_plane<128,256>(CTX, Ml, xb, tid);
    cp_wait<0>();
    __syncthreads();
    {
        float C[16][4]; zero_C(C);
        panel_f16(sWhi, sWlo, sX, warp, lane, C);
        const int r0 = warp * 16 + g, r1 = r0 + 8;
#pragma unroll
        for (int t = 0; t < 16; t++) {
            int c = t * 8 + tg * 2;
            float2 bv = *(const float2*)(bx + c);
            if (r0 < Ml) *(float2*)(CTH + (size_t)r0 * 128 + c) =
                make_float2(fmaxf(C[t][0] + bv.x, 0.f), fmaxf(C[t][1] + bv.y, 0.f));
            if (r1 < Ml) *(float2*)(CTH + (size_t)r1 * 128 + c) =
                make_float2(fmaxf(C[t][2] + bv.x, 0.f), fmaxf(C[t][3] + bv.y, 0.f));
        }
    }
    __syncthreads();
    stage_plane<128,256>(AC, M1, xb, tid);
    cp_wait<0>();
    __syncthreads();
    {
        float C[16][4]; zero_C(C);
        panel_f16(sWhi, sWlo, sX, warp, lane, C);
        __syncthreads();
        epilogue_to_smem(C, bx, sE, warp, g, tg);
        __syncthreads();
        combine_red128(sE, CTH, O, 0, M1, tid);
    }
}

__global__ void set_ones_h(__half* p)
{
    p[threadIdx.x] = __float2half(1.0f);
}

// ---------------- launch ----------------
static inline int grid64(int rows) {
    int nt = (rows + 63) >> 6;
    return nt < 296 ? nt : 296;
}

extern "C" void kernel_launch(void* const* d_in, const int* in_sizes, int n_in,
                              void* d_out, int out_size)
{
    const float* initial = (const float*)d_in[0];
    const float* Ws = (const float*)d_in[1];
    const float* bs = (const float*)d_in[2];
    const float* Wc = (const float*)d_in[3];
    const float* bc = (const float*)d_in[4];
    const float* Wx = (const float*)d_in[5];
    const float* bx = (const float*)d_in[6];
    const float* Wf = (const float*)d_in[7];
    const float* bf = (const float*)d_in[8];
    const float* Wh = (const float*)d_in[9];
    const float* bh = (const float*)d_in[10];
    float* out = (float*)d_out;

    __half *agg, *ctx, *t2;
    float* cth;
    cudaGetSymbolAddress((void**)&agg, g_agg);
    cudaGetSymbolAddress((void**)&ctx, g_ctx);
    cudaGetSymbolAddress((void**)&t2,  g_t2);
    cudaGetSymbolAddress((void**)&cth, g_cth);

    cudaFuncSetAttribute(up_mean4_64,     cudaFuncAttributeMaxDynamicSharedMemorySize, SMEM_64);
    cudaFuncSetAttribute(up_pairadd_64,   cudaFuncAttributeMaxDynamicSharedMemorySize, SMEM_64);
    cudaFuncSetAttribute(cth_64,          cudaFuncAttributeMaxDynamicSharedMemorySize, SMEM_64);
    cudaFuncSetAttribute(down_combine_64, cudaFuncAttributeMaxDynamicSharedMemorySize, SMEM_64);
    cudaFuncSetAttribute(final_pers,      cudaFuncAttributeMaxDynamicSharedMemorySize, SMEM_FIN);
    cudaFuncSetAttribute(up_small,        cudaFuncAttributeMaxDynamicSharedMemorySize, SMEM_SMALL);
    cudaFuncSetAttribute(down_small,      cudaFuncAttributeMaxDynamicSharedMemorySize, SMEM_SMALL);

    const float* leaf_f32 = initial + (size_t)H_OFFS[6] * DIM;

    // ---- up pass ----
    for (int l = 5; l >= 2; l--) {
        int M1 = H_SIZES[l + 1];
        int G  = M1 >> 2;
        if (l == 5)
            up_mean4_64<<<grid64(M1), 128, SMEM_64>>>(
                nullptr, leaf_f32, 1, Ws, bs, t2, M1);
        else
            up_mean4_64<<<grid64(M1), 128, SMEM_64>>>(
                agg + (size_t)H_OFFS[l + 1] * DIM, nullptr, 0, Ws, bs, t2, M1);
        up_pairadd_64<<<grid64(G), 128, SMEM_64>>>(
            t2, Wc, bc, initial + (size_t)H_OFFS[l] * DIM,
            agg + (size_t)H_OFFS[l] * DIM, G);
    }
    for (int l = 1; l >= 0; l--) {
        up_small<<<1, 256, SMEM_SMALL>>>(
            agg + (size_t)H_OFFS[l + 1] * DIM,
            initial + (size_t)H_OFFS[l] * DIM,
            agg + (size_t)H_OFFS[l] * DIM,
            Ws, bs, Wc, bc, t2, H_SIZES[l + 1]);
    }

    // ---- down pass ----
    set_ones_h<<<1, 128>>>(ctx);
    for (int l = 0; l < 2; l++) {
        down_small<<<1, 256, SMEM_SMALL>>>(
            ctx + (size_t)H_OFFS[l] * DIM,
            agg + (size_t)H_OFFS[l + 1] * DIM,
            Wx, bx, cth,
            ctx + (size_t)H_OFFS[l + 1] * DIM, H_SIZES[l], H_SIZES[l + 1]);
    }
    for (int l = 2; l < 6; l++) {
        int Ml = H_SIZES[l], M1 = H_SIZES[l + 1];
        cth_64<<<grid64(Ml), 128, SMEM_64>>>(
            ctx + (size_t)H_OFFS[l] * DIM, Wx, bx, cth, Ml);
        if (l == 5)
            down_combine_64<<<grid64(M1), 128, SMEM_64>>>(
                nullptr, leaf_f32, 1, Wx, bx, cth,
                ctx + (size_t)H_OFFS[l + 1] * DIM, M1);
        else
            down_combine_64<<<grid64(M1), 128, SMEM_64>>>(
                agg + (size_t)H_OFFS[l + 1] * DIM, nullptr, 0, Wx, bx, cth,
                ctx + (size_t)H_OFFS[l + 1] * DIM, M1);
    }

    // ---- final ----
    final_pers<<<148, 256, SMEM_FIN>>>(
        ctx, agg, initial, NTOP,
        Wf, bf, Wh, bh, out, N_TOTAL);
}

// round 13
// speedup vs baseline: 2.0090x; 1.2892x over previous
#include <cuda_runtime.h>
#include <cuda_fp16.h>
#include <cstdint>

#define DIM 128
#define N_TOTAL 299593
#define NTOP 37449

static const int H_SIZES[7] = {1, 8, 64, 512, 4096, 32768, 262144};
static const int H_OFFS[8]  = {0, 1, 9, 73, 585, 4681, 37449, 299593};

// ---------------- scratch ----------------
__device__ __half g_agg[NTOP * DIM];
__device__ __half g_ctx[N_TOTAL * DIM];
__device__ __half g_t2 [65536 * DIM];
__device__ float  g_cth[32768 * DIM];
// weights pre-converted to fp16 (once per launch)
__device__ __half g_ws16[128 * 128];
__device__ __half g_wc16[128 * 128];
__device__ __half g_wx16[128 * 128];
__device__ __half g_wf16[128 * 256];

// ================= common =================
#define SPITCH 136                  // fp16 elems per smem row (272 B)
#define WB     34816                // 128-row fp16 pitched plane
#define XB64   17408                // 64-row fp16 pitched plane
#define EPITCH 132

#define SE64   33792                // 64 * 132 * 4
#define SE128  67584                // 128 * 132 * 4
#define SMEM_64   (WB + SE64)       // 68608  -> 3 blocks/SM
#define SMEM_FIN  (2 * WB + XB64)   // 87040  -> 2 blocks/SM
#define SMEM_SMALL (WB + SE128)     // 102400

__device__ __forceinline__ uint32_t smem_u32(const void* p) {
    return (uint32_t)__cvta_generic_to_shared(p);
}
__device__ __forceinline__ uint4 pack8h(float4 a, float4 b) {
    uint4 r;
    r.x = ((unsigned)__half_as_ushort(__float2half_rn(a.y))<<16) | __half_as_ushort(__float2half_rn(a.x));
    r.y = ((unsigned)__half_as_ushort(__float2half_rn(a.w))<<16) | __half_as_ushort(__float2half_rn(a.z));
    r.z = ((unsigned)__half_as_ushort(__float2half_rn(b.y))<<16) | __half_as_ushort(__float2half_rn(b.x));
    r.w = ((unsigned)__half_as_ushort(__float2half_rn(b.w))<<16) | __half_as_ushort(__float2half_rn(b.z));
    return r;
}
__device__ __forceinline__ void cp16(unsigned saddr, const void* gptr, int sz) {
    asm volatile("cp.async.cg.shared.global [%0], [%1], 16, %2;"
                 :: "r"(saddr), "l"(gptr), "r"(sz));
}
template<int N>
__device__ __forceinline__ void cp_wait() {
    asm volatile("cp.async.wait_group %0;" :: "n"(N) : "memory");
}
__device__ __forceinline__ void cp_commit() {
    asm volatile("cp.async.commit_group;");
}

__device__ __forceinline__ void mma_f16(float* c, const unsigned* a, unsigned b0, unsigned b1)
{
    asm volatile(
        "mma.sync.aligned.m16n8k16.row.col.f32.f16.f16.f32 "
        "{%0,%1,%2,%3},{%4,%5,%6,%7},{%8,%9},{%0,%1,%2,%3};\n"
        : "+f"(c[0]), "+f"(c[1]), "+f"(c[2]), "+f"(c[3])
        : "r"(a[0]), "r"(a[1]), "r"(a[2]), "r"(a[3]), "r"(b0), "r"(b1));
}
__device__ __forceinline__ void ldsm4(unsigned* r, unsigned addr)
{
    asm volatile("ldmatrix.sync.aligned.m8n8.x4.shared.b16 {%0,%1,%2,%3}, [%4];"
                 : "=r"(r[0]), "=r"(r[1]), "=r"(r[2]), "=r"(r[3]) : "r"(addr));
}

// ---- staging: fp16 plane (gstride halfs/row) -> pitched smem via cp.async ----
template <int NROWS, int NTHR>
__device__ __forceinline__ void stage_h16(
    const __half* __restrict__ G, int gstride, int rows_valid, char* buf, int tid)
{
    unsigned hB = smem_u32(buf);
#pragma unroll
    for (int i = tid; i < NROWS * 16; i += NTHR) {
        int r = i >> 4, c = i & 15;
        unsigned so = (unsigned)r * 272 + c * 16;
        int sz = (r < rows_valid) ? 16 : 0;
        cp16(hB + so, G + (size_t)r * gstride + c * 8, sz);
    }
    cp_commit();
}

// ---- leaf staging: fp32 -> fp16 pitched smem (register path) ----
template <int NTHR>
__device__ __forceinline__ void stage_leaf(
    const float* __restrict__ F32, int grow0, int M, int nrows, char* buf, int tid)
{
    const int tot = nrows * 16;
    for (int i = tid; i < tot; i += NTHR) {
        int r = i >> 4, c = i & 15;
        int gr = grow0 + r;
        float4 a = make_float4(0.f,0.f,0.f,0.f), b = a;
        if (gr < M) {
            a = *(const float4*)(F32 + (size_t)gr * 128 + c * 8);
            b = *(const float4*)(F32 + (size_t)gr * 128 + c * 8 + 4);
        }
        *(uint4*)(buf + (size_t)r * 272 + c * 16) = pack8h(a, b);
    }
}

// final agg panel (64 rows): rows<bnd from fp16 plane, else leaf fp32 rows
__device__ __forceinline__ void stage_sel64(
    const __half* __restrict__ A, const float* __restrict__ INIT,
    int bnd, int grow0, int M, char* buf, int tid)
{
    unsigned hB = smem_u32(buf);
    for (int i = tid; i < 1024; i += 128) {
        int r = i >> 4, c = i & 15;
        int gr = grow0 + r;
        unsigned so = (unsigned)r * 272 + c * 16;
        if (gr < bnd) {
            cp16(hB + so, A + (size_t)gr * 128 + c * 8, 16);
        } else {
            float4 a = make_float4(0.f,0.f,0.f,0.f), b = a;
            if (gr < M) {
                a = *(const float4*)(INIT + (size_t)gr * 128 + c * 8);
                b = *(const float4*)(INIT + (size_t)gr * 128 + c * 8 + 4);
            }
            *(uint4*)(buf + so) = pack8h(a, b);
        }
    }
    cp_commit();
}

// ---- mainloop: single-pass fp16, B fragments preloaded ----
__device__ __forceinline__ void panel_1p(
    const __half* sW, const __half* sX, int warp, int lane, float C[16][4])
{
    const unsigned wh = smem_u32(sW);
    const unsigned xh = smem_u32(sX);
    const unsigned PB = SPITCH * 2;
    const unsigned aoff0 = (unsigned)(warp * 16 + (lane & 15)) * PB + (unsigned)((lane >> 4) & 1) * 16u;
    const unsigned boff0 = (unsigned)((lane & 7) + ((lane & 16) >> 1)) * PB + ((lane & 8) ? 16u : 0u);

    for (int kc = 0; kc < 8; kc++) {
        const unsigned ka = kc * 32;
        unsigned ah[4];
        ldsm4(ah, xh + aoff0 + ka);
        unsigned bhi[8][4];
#pragma unroll
        for (int p = 0; p < 8; p++) ldsm4(bhi[p], wh + boff0 + (unsigned)p * 16 * PB + ka);
#pragma unroll
        for (int p = 0; p < 8; p++) {
            mma_f16(C[2*p],   ah, bhi[p][0], bhi[p][1]);
            mma_f16(C[2*p+1], ah, bhi[p][2], bhi[p][3]);
        }
    }
}

__device__ __forceinline__ void zero_C(float C[16][4])
{
#pragma unroll
    for (int t = 0; t < 16; t++) C[t][0] = C[t][1] = C[t][2] = C[t][3] = 0.f;
}

__device__ __forceinline__ void epilogue_to_smem(
    const float C[16][4], const float* __restrict__ bias, float* sE, int warp, int g, int tg)
{
    const int r0 = warp * 16 + g, r1 = r0 + 8;
#pragma unroll
    for (int t = 0; t < 16; t++) {
        int c = t * 8 + tg * 2;
        float2 bv = *(const float2*)(bias + c);
        sE[r0 * EPITCH + c]     = fmaxf(C[t][0] + bv.x, 0.f);
        sE[r0 * EPITCH + c + 1] = fmaxf(C[t][1] + bv.y, 0.f);
        sE[r1 * EPITCH + c]     = fmaxf(C[t][2] + bv.x, 0.f);
        sE[r1 * EPITCH + c + 1] = fmaxf(C[t][3] + bv.y, 0.f);
    }
}

// ---- reduce epilogues (64-row, 128 threads, col = tid) ----
__device__ __forceinline__ void mean4_red64(
    const float* sE, __half* __restrict__ T2, int og0, int G, int col)
{
#pragma unroll 4
    for (int q = 0; q < 16; q++) {
        int og = og0 + q;
        if (og < G) {
            float v = sE[(4*q)*EPITCH + col] + sE[(4*q+1)*EPITCH + col]
                    + sE[(4*q+2)*EPITCH + col] + sE[(4*q+3)*EPITCH + col];
            T2[(size_t)og * 128 + col] = __float2half_rn(0.25f * v);
        }
    }
}
__device__ __forceinline__ void pairadd_red64(
    const float* sE, const float* __restrict__ init,
    __half* __restrict__ A, int og0, int Mout, int col)
{
#pragma unroll 4
    for (int q = 0; q < 32; q++) {
        int og = og0 + q;
        if (og < Mout) {
            float v = sE[(2*q)*EPITCH + col] + sE[(2*q+1)*EPITCH + col];
            A[(size_t)og * 128 + col] =
                __float2half_rn(init[(size_t)og * 128 + col] + 0.5f * v);
        }
    }
}
__device__ __forceinline__ void combine_red64(
    const float* sE, const float* __restrict__ CTH,
    __half* __restrict__ O, int row0, int M1, int col)
{
#pragma unroll 2
    for (int q = 0; q < 16; q++) {
        int base = row0 + 4 * q;
        if (base < M1) {
            float s = sE[(4*q)*EPITCH + col] + sE[(4*q+1)*EPITCH + col]
                    + sE[(4*q+2)*EPITCH + col] + sE[(4*q+3)*EPITCH + col];
            float tot = CTH[(size_t)(base >> 3) * 128 + col] + s;
#pragma unroll
            for (int s4 = 0; s4 < 4; s4++)
                O[(size_t)(base + s4) * 128 + col] =
                    __float2half_rn(0.25f * (tot - sE[(4*q+s4)*EPITCH + col]));
        }
    }
}
// 128-row variants (256 threads)
__device__ __forceinline__ void mean4_red128(
    const float* sE, __half* __restrict__ T2, int og0, int G, int tid)
{
    int col = tid & 127;
    for (int q = tid >> 7; q < 32; q += 2) {
        int og = og0 + q;
        if (og < G) {
            float v = sE[(4*q)*EPITCH + col] + sE[(4*q+1)*EPITCH + col]
                    + sE[(4*q+2)*EPITCH + col] + sE[(4*q+3)*EPITCH + col];
            T2[(size_t)og * 128 + col] = __float2half_rn(0.25f * v);
        }
    }
}
__device__ __forceinline__ void pairadd_red128(
    const float* sE, const float* __restrict__ init,
    __half* __restrict__ A, int og0, int Mout, int tid)
{
    int col = tid & 127;
    for (int q = tid >> 7; q < 64; q += 2) {
        int og = og0 + q;
        if (og < Mout) {
            float v = sE[(2*q)*EPITCH + col] + sE[(2*q+1)*EPITCH + col];
            A[(size_t)og * 128 + col] =
                __float2half_rn(init[(size_t)og * 128 + col] + 0.5f * v);
        }
    }
}
__device__ __forceinline__ void combine_red128(
    const float* sE, const float* __restrict__ CTH,
    __half* __restrict__ O, int row0, int M1, int tid)
{
    int col = tid & 127;
    for (int q = tid >> 7; q < 32; q += 2) {
        int base = row0 + 4 * q;
        if (base < M1) {
            float s = sE[(4*q)*EPITCH + col] + sE[(4*q+1)*EPITCH + col]
                    + sE[(4*q+2)*EPITCH + col] + sE[(4*q+3)*EPITCH + col];
            float tot = CTH[(size_t)(base >> 3) * 128 + col] + s;
#pragma unroll
            for (int s4 = 0; s4 < 4; s4++)
                O[(size_t)(base + s4) * 128 + col] =
                    __float2half_rn(0.25f * (tot - sE[(4*q+s4)*EPITCH + col]));
        }
    }
}

// ================= 64-row-tile kernels: 128 threads, 3 blocks/SM =================

__global__ void __launch_bounds__(128, 3) up_mean4_64(
    const __half* __restrict__ X, const float* __restrict__ Xf32, int leaf,
    const __half* __restrict__ W16, const float* __restrict__ bias,
    __half* __restrict__ T2, int M1)
{
    extern __shared__ __align__(1024) char sm[];
    const int tid = threadIdx.x, lane = tid & 31, warp = tid >> 5;
    const int g = lane >> 2, tg = lane & 3;
    char* xb = sm + WB;
    stage_h16<128, 128>(W16, 128, 128, sm, tid);

    const int ntiles = (M1 + 63) >> 6;
    for (int t = blockIdx.x; t < ntiles; t += gridDim.x) {
        if (leaf) stage_leaf<128>(Xf32, t * 64, M1, 64, xb, tid);
        else stage_h16<64, 128>(X + (size_t)t * 8192, 128, M1 - t * 64, xb, tid);
        cp_wait<0>();
        __syncthreads();
        float C[16][4]; zero_C(C);
        panel_1p((__half*)sm, (__half*)xb, warp, lane, C);
        __syncthreads();
        float* sE = (float*)xb;
        epilogue_to_smem(C, bias, sE, warp, g, tg);
        __syncthreads();
        mean4_red64(sE, T2, t * 16, M1 >> 2, tid);
        __syncthreads();
    }
}

__global__ void __launch_bounds__(128, 3) up_pairadd_64(
    const __half* __restrict__ X,
    const __half* __restrict__ W16, const float* __restrict__ bias,
    const float* __restrict__ init, __half* __restrict__ A, int G)
{
    extern __shared__ __align__(1024) char sm[];
    const int tid = threadIdx.x, lane = tid & 31, warp = tid >> 5;
    const int g = lane >> 2, tg = lane & 3;
    char* xb = sm + WB;
    stage_h16<128, 128>(W16, 128, 128, sm, tid);

    const int ntiles = (G + 63) >> 6;
    for (int t = blockIdx.x; t < ntiles; t += gridDim.x) {
        stage_h16<64, 128>(X + (size_t)t * 8192, 128, G - t * 64, xb, tid);
        cp_wait<0>();
        __syncthreads();
        float C[16][4]; zero_C(C);
        panel_1p((__half*)sm, (__half*)xb, warp, lane, C);
        __syncthreads();
        float* sE = (float*)xb;
        epilogue_to_smem(C, bias, sE, warp, g, tg);
        __syncthreads();
        pairadd_red64(sE, init, A, t * 32, G >> 1, tid);
        __syncthreads();
    }
}

__global__ void __launch_bounds__(128, 3) cth_64(
    const __half* __restrict__ X,
    const __half* __restrict__ W16, const float* __restrict__ bias,
    float* __restrict__ Y, int M)
{
    extern __shared__ __align__(1024) char sm[];
    const int tid = threadIdx.x, lane = tid & 31, warp = tid >> 5;
    const int g = lane >> 2, tg = lane & 3;
    char* xb = sm + WB;
    stage_h16<128, 128>(W16, 128, 128, sm, tid);

    const int ntiles = (M + 63) >> 6;
    for (int t = blockIdx.x; t < ntiles; t += gridDim.x) {
        int rv = M - t * 64; if (rv > 64) rv = 64;
        stage_h16<64, 128>(X + (size_t)t * 8192, 128, rv, xb, tid);
        cp_wait<0>();
        __syncthreads();
        float C[16][4]; zero_C(C);
        panel_1p((__half*)sm, (__half*)xb, warp, lane, C);
        const int r0g = t * 64 + warp * 16 + g, r1g = r0g + 8;
#pragma unroll
        for (int tt = 0; tt < 16; tt++) {
            int c = tt * 8 + tg * 2;
            float2 bv = *(const float2*)(bias + c);
            if (r0g < M) *(float2*)(Y + (size_t)r0g * 128 + c) =
                make_float2(fmaxf(C[tt][0] + bv.x, 0.f), fmaxf(C[tt][1] + bv.y, 0.f));
            if (r1g < M) *(float2*)(Y + (size_t)r1g * 128 + c) =
                make_float2(fmaxf(C[tt][2] + bv.x, 0.f), fmaxf(C[tt][3] + bv.y, 0.f));
        }
        __syncthreads();
    }
}

__global__ void __launch_bounds__(128, 3) down_combine_64(
    const __half* __restrict__ X, const float* __restrict__ Xf32, int leaf,
    const __half* __restrict__ W16, const float* __restrict__ bias,
    const float* __restrict__ CTH, __half* __restrict__ O, int M1)
{
    extern __shared__ __align__(1024) char sm[];
    const int tid = threadIdx.x, lane = tid & 31, warp = tid >> 5;
    const int g = lane >> 2, tg = lane & 3;
    char* xb = sm + WB;
    stage_h16<128, 128>(W16, 128, 128, sm, tid);

    const int ntiles = (M1 + 63) >> 6;
    for (int t = blockIdx.x; t < ntiles; t += gridDim.x) {
        if (leaf) stage_leaf<128>(Xf32, t * 64, M1, 64, xb, tid);
        else stage_h16<64, 128>(X + (size_t)t * 8192, 128, M1 - t * 64, xb, tid);
        cp_wait<0>();
        __syncthreads();
        float C[16][4]; zero_C(C);
        panel_1p((__half*)sm, (__half*)xb, warp, lane, C);
        __syncthreads();
        float* sE = (float*)xb;
        epilogue_to_smem(C, bias, sE, warp, g, tg);
        __syncthreads();
        combine_red64(sE, CTH, O, t * 64, M1, tid);
        __syncthreads();
    }
}

// ================= final kernel (128 threads, 64-row tiles, 2 W panels) =================
__global__ void __launch_bounds__(128, 2) final_64(
    const __half* __restrict__ CTX, const __half* __restrict__ AGG,
    const float* __restrict__ INIT, int bnd,
    const __half* __restrict__ Wf16, const float* __restrict__ bf,
    const float* __restrict__ Wh, const float* __restrict__ bh,
    float* __restrict__ out, int M)
{
    extern __shared__ __align__(1024) char sm[];
    const int tid = threadIdx.x, lane = tid & 31, warp = tid >> 5;
    const int g = lane >> 2, tg = lane & 3;
    stage_h16<128, 128>(Wf16,       256, 128, sm,      tid);
    stage_h16<128, 128>(Wf16 + 128, 256, 128, sm + WB, tid);
    char* xb = sm + 2 * WB;

    const int ntiles = (M + 63) >> 6;
    for (int t = blockIdx.x; t < ntiles; t += gridDim.x) {
        int row0 = t * 64;
        int rv = M - row0; if (rv > 64) rv = 64;
        stage_h16<64, 128>(CTX + (size_t)row0 * 128, 128, rv, xb, tid);
        cp_wait<0>();
        __syncthreads();
        float C[16][4]; zero_C(C);
        panel_1p((__half*)sm, (__half*)xb, warp, lane, C);
        __syncthreads();
        stage_sel64(AGG, INIT, bnd, row0, M, xb, tid);
        cp_wait<0>();
        __syncthreads();
        panel_1p((__half*)(sm + WB), (__half*)xb, warp, lane, C);
        float s0 = 0.f, s1 = 0.f;
#pragma unroll
        for (int tt = 0; tt < 16; tt++) {
            int c = tt * 8 + tg * 2;
            float2 bv = *(const float2*)(bf + c);
            float2 wv = *(const float2*)(Wh + c);
            s0 += fmaxf(C[tt][0] + bv.x, 0.f) * wv.x + fmaxf(C[tt][1] + bv.y, 0.f) * wv.y;
            s1 += fmaxf(C[tt][2] + bv.x, 0.f) * wv.x + fmaxf(C[tt][3] + bv.y, 0.f) * wv.y;
        }
        s0 += __shfl_xor_sync(0xffffffffu, s0, 1);
        s0 += __shfl_xor_sync(0xffffffffu, s0, 2);
        s1 += __shfl_xor_sync(0xffffffffu, s1, 1);
        s1 += __shfl_xor_sync(0xffffffffu, s1, 2);
        if (tg == 0) {
            int r0g = row0 + warp * 16 + g, r1g = r0g + 8;
            float bhv = bh[0];
            if (r0g < M) out[r0g] = s0 + bhv;
            if (r1g < M) out[r1g] = s1 + bhv;
        }
        __syncthreads();
    }
}

// ================= tiny-level kernels (256 threads, single block) =================
__global__ void __launch_bounds__(256) up_small(
    const __half* __restrict__ Xc, const float* __restrict__ init_l,
    __half* __restrict__ A,
    const __half* __restrict__ Ws16, const float* __restrict__ bs,
    const __half* __restrict__ Wc16, const float* __restrict__ bc,
    __half* __restrict__ T2, int M1)
{
    extern __shared__ __align__(1024) char sm[];
    char* xb = sm + WB;
    __half* sX = (__half*)xb;
    float* sE = (float*)xb;
    const int tid = threadIdx.x, lane = tid & 31, warp = tid >> 5;
    const int g = lane >> 2, tg = lane & 3;
    const int G = M1 >> 2, Mout = M1 >> 3;

    stage_h16<128, 256>(Ws16, 128, 128, sm, tid);
    stage_h16<128, 256>(Xc, 128, M1, xb, tid);
    cp_wait<0>();
    __syncthreads();
    {
        float C[16][4]; zero_C(C);
        panel_1p((__half*)sm, sX, warp, lane, C);
        __syncthreads();
        epilogue_to_smem(C, bs, sE, warp, g, tg);
        __syncthreads();
        mean4_red128(sE, T2, 0, G, tid);
    }
    __syncthreads();
    stage_h16<128, 256>(Wc16, 128, 128, sm, tid);
    for (int i = tid; i < 128 * 16; i += 256) {
        int r = i >> 4, c = i & 15;
        uint4 v = make_uint4(0,0,0,0);
        if (r < G) v = *(const uint4*)(T2 + (size_t)r * 128 + c * 8);
        *(uint4*)(xb + (size_t)r * 272 + c * 16) = v;
    }
    cp_wait<0>();
    __syncthreads();
    {
        float C[16][4]; zero_C(C);
        panel_1p((__half*)sm, sX, warp, lane, C);
        __syncthreads();
        epilogue_to_smem(C, bc, sE, warp, g, tg);
        __syncthreads();
        pairadd_red128(sE, init_l, A, 0, Mout, tid);
    }
}

__global__ void __launch_bounds__(256) down_small(
    const __half* __restrict__ CTX, const __half* __restrict__ AC,
    const __half* __restrict__ Wx16, const float* __restrict__ bx,
    float* __restrict__ CTH, __half* __restrict__ O, int Ml, int M1)
{
    extern __shared__ __align__(1024) char sm[];
    char* xb = sm + WB;
    __half* sX = (__half*)xb;
    float* sE = (float*)xb;
    const int tid = threadIdx.x, lane = tid & 31, warp = tid >> 5;
    const int g = lane >> 2, tg = lane & 3;

    stage_h16<128, 256>(Wx16, 128, 128, sm, tid);
    stage_h16<128, 256>(CTX, 128, Ml, xb, tid);
    cp_wait<0>();
    __syncthreads();
    {
        float C[16][4]; zero_C(C);
        panel_1p((__half*)sm, sX, warp, lane, C);
        const int r0 = warp * 16 + g, r1 = r0 + 8;
#pragma unroll
        for (int t = 0; t < 16; t++) {
            int c = t * 8 + tg * 2;
            float2 bv = *(const float2*)(bx + c);
            if (r0 < Ml) *(float2*)(CTH + (size_t)r0 * 128 + c) =
                make_float2(fmaxf(C[t][0] + bv.x, 0.f), fmaxf(C[t][1] + bv.y, 0.f));
            if (r1 < Ml) *(float2*)(CTH + (size_t)r1 * 128 + c) =
                make_float2(fmaxf(C[t][2] + bv.x, 0.f), fmaxf(C[t][3] + bv.y, 0.f));
        }
    }
    __syncthreads();
    stage_h16<128, 256>(AC, 128, M1, xb, tid);
    cp_wait<0>();
    __syncthreads();
    {
        float C[16][4]; zero_C(C);
        panel_1p((__half*)sm, sX, warp, lane, C);
        __syncthreads();
        epilogue_to_smem(C, bx, sE, warp, g, tg);
        __syncthreads();
        combine_red128(sE, CTH, O, 0, M1, tid);
    }
}

// ================= utility kernels =================
__global__ void convert_weights(
    const float* __restrict__ Ws, const float* __restrict__ Wc,
    const float* __restrict__ Wx, const float* __restrict__ Wf)
{
    int i = blockIdx.x * blockDim.x + threadIdx.x;
    int stride = gridDim.x * blockDim.x;
    for (int k = i; k < 16384; k += stride) {
        g_ws16[k] = __float2half_rn(Ws[k]);
        g_wc16[k] = __float2half_rn(Wc[k]);
        g_wx16[k] = __float2half_rn(Wx[k]);
    }
    for (int k = i; k < 32768; k += stride) {
        g_wf16[k] = __float2half_rn(Wf[k]);
    }
}

__global__ void set_ones_h(__half* p)
{
    p[threadIdx.x] = __float2half(1.0f);
}

// ---------------- launch ----------------
static inline int grid64(int rows) {
    int nt = (rows + 63) >> 6;
    return nt < 444 ? nt : 444;
}

extern "C" void kernel_launch(void* const* d_in, const int* in_sizes, int n_in,
                              void* d_out, int out_size)
{
    const float* initial = (const float*)d_in[0];
    const float* Ws = (const float*)d_in[1];
    const float* bs = (const float*)d_in[2];
    const float* Wc = (const float*)d_in[3];
    const float* bc = (const float*)d_in[4];
    const float* Wx = (const float*)d_in[5];
    const float* bx = (const float*)d_in[6];
    const float* Wf = (const float*)d_in[7];
    const float* bf = (const float*)d_in[8];
    const float* Wh = (const float*)d_in[9];
    const float* bh = (const float*)d_in[10];
    float* out = (float*)d_out;

    __half *agg, *ctx, *t2, *ws16, *wc16, *wx16, *wf16;
    float* cth;
    cudaGetSymbolAddress((void**)&agg,  g_agg);
    cudaGetSymbolAddress((void**)&ctx,  g_ctx);
    cudaGetSymbolAddress((void**)&t2,   g_t2);
    cudaGetSymbolAddress((void**)&cth,  g_cth);
    cudaGetSymbolAddress((void**)&ws16, g_ws16);
    cudaGetSymbolAddress((void**)&wc16, g_wc16);
    cudaGetSymbolAddress((void**)&wx16, g_wx16);
    cudaGetSymbolAddress((void**)&wf16, g_wf16);

    cudaFuncSetAttribute(up_mean4_64,     cudaFuncAttributeMaxDynamicSharedMemorySize, SMEM_64);
    cudaFuncSetAttribute(up_pairadd_64,   cudaFuncAttributeMaxDynamicSharedMemorySize, SMEM_64);
    cudaFuncSetAttribute(cth_64,          cudaFuncAttributeMaxDynamicSharedMemorySize, SMEM_64);
    cudaFuncSetAttribute(down_combine_64, cudaFuncAttributeMaxDynamicSharedMemorySize, SMEM_64);
    cudaFuncSetAttribute(final_64,        cudaFuncAttributeMaxDynamicSharedMemorySize, SMEM_FIN);
    cudaFuncSetAttribute(up_small,        cudaFuncAttributeMaxDynamicSharedMemorySize, SMEM_SMALL);
    cudaFuncSetAttribute(down_small,      cudaFuncAttributeMaxDynamicSharedMemorySize, SMEM_SMALL);

    const float* leaf_f32 = initial + (size_t)H_OFFS[6] * DIM;

    convert_weights<<<64, 256>>>(Ws, Wc, Wx, Wf);

    // ---- up pass ----
    for (int l = 5; l >= 2; l--) {
        int M1 = H_SIZES[l + 1];
        int G  = M1 >> 2;
        if (l == 5)
            up_mean4_64<<<grid64(M1), 128, SMEM_64>>>(
                nullptr, leaf_f32, 1, ws16, bs, t2, M1);
        else
            up_mean4_64<<<grid64(M1), 128, SMEM_64>>>(
                agg + (size_t)H_OFFS[l + 1] * DIM, nullptr, 0, ws16, bs, t2, M1);
        up_pairadd_64<<<grid64(G), 128, SMEM_64>>>(
            t2, wc16, bc, initial + (size_t)H_OFFS[l] * DIM,
            agg + (size_t)H_OFFS[l] * DIM, G);
    }
    for (int l = 1; l >= 0; l--) {
        up_small<<<1, 256, SMEM_SMALL>>>(
            agg + (size_t)H_OFFS[l + 1] * DIM,
            initial + (size_t)H_OFFS[l] * DIM,
            agg + (size_t)H_OFFS[l] * DIM,
            ws16, bs, wc16, bc, t2, H_SIZES[l + 1]);
    }

    // ---- down pass ----
    set_ones_h<<<1, 128>>>(ctx);
    for (int l = 0; l < 2; l++) {
        down_small<<<1, 256, SMEM_SMALL>>>(
            ctx + (size_t)H_OFFS[l] * DIM,
            agg + (size_t)H_OFFS[l + 1] * DIM,
            wx16, bx, cth,
            ctx + (size_t)H_OFFS[l + 1] * DIM, H_SIZES[l], H_SIZES[l + 1]);
    }
    for (int l = 2; l < 6; l++) {
        int Ml = H_SIZES[l], M1 = H_SIZES[l + 1];
        cth_64<<<grid64(Ml), 128, SMEM_64>>>(
            ctx + (size_t)H_OFFS[l] * DIM, wx16, bx, cth, Ml);
        if (l == 5)
            down_combine_64<<<grid64(M1), 128, SMEM_64>>>(
                nullptr, leaf_f32, 1, wx16, bx, cth,
                ctx + (size_t)H_OFFS[l + 1] * DIM, M1);
        else
            down_combine_64<<<grid64(M1), 128, SMEM_64>>>(
                agg + (size_t)H_OFFS[l + 1] * DIM, nullptr, 0, wx16, bx, cth,
                ctx + (size_t)H_OFFS[l + 1] * DIM, M1);
    }

    // ---- final ----
    final_64<<<444, 128, SMEM_FIN>>>(
        ctx, agg, initial, NTOP,
        wf16, bf, Wh, bh, out, N_TOTAL);
}

// round 15
// speedup vs baseline: 2.7759x; 1.3817x over previous
#include <cuda_runtime.h>
#include <cuda_fp16.h>
#include <cstdint>

#define DIM 128
#define N_TOTAL 299593
#define NTOP 37449

static const int H_SIZES[7] = {1, 8, 64, 512, 4096, 32768, 262144};
static const int H_OFFS[8]  = {0, 1, 9, 73, 585, 4681, 37449, 299593};

// ---------------- scratch ----------------
__device__ __half g_act[N_TOTAL * DIM];   // agg rows 0..NTOP-1, leaves NTOP..
__device__ __half g_ctx[N_TOTAL * DIM];
__device__ __half g_t2 [65536 * DIM];
__device__ float  g_cth[32768 * DIM];
__device__ __half g_ws16[128 * 128];
__device__ __half g_wc16[128 * 128];
__device__ __half g_wx16[128 * 128];
__device__ __half g_wf16[128 * 256];

// ================= common =================
#define SPITCH 136
#define WB     34816                // 128-row fp16 pitched plane
#define XB64   17408                // 64-row fp16 pitched plane

#define SMEM_64    (WB + 2 * XB64)      // 69632  -> 3 blocks/SM
#define SMEM_FIN   (2 * WB + 2 * XB64)  // 104448 -> 2 blocks/SM
#define SMEM_SMALL (2 * WB)             // 69632

__device__ __forceinline__ uint32_t smem_u32(const void* p) {
    return (uint32_t)__cvta_generic_to_shared(p);
}
__device__ __forceinline__ void cp16(unsigned saddr, const void* gptr, int sz) {
    asm volatile("cp.async.cg.shared.global [%0], [%1], 16, %2;"
                 :: "r"(saddr), "l"(gptr), "r"(sz));
}
template<int N>
__device__ __forceinline__ void cp_wait() {
    asm volatile("cp.async.wait_group %0;" :: "n"(N) : "memory");
}
__device__ __forceinline__ void cp_commit() {
    asm volatile("cp.async.commit_group;");
}

__device__ __forceinline__ void mma_f16(float* c, const unsigned* a, unsigned b0, unsigned b1)
{
    asm volatile(
        "mma.sync.aligned.m16n8k16.row.col.f32.f16.f16.f32 "
        "{%0,%1,%2,%3},{%4,%5,%6,%7},{%8,%9},{%0,%1,%2,%3};\n"
        : "+f"(c[0]), "+f"(c[1]), "+f"(c[2]), "+f"(c[3])
        : "r"(a[0]), "r"(a[1]), "r"(a[2]), "r"(a[3]), "r"(b0), "r"(b1));
}
__device__ __forceinline__ void ldsm4(unsigned* r, unsigned addr)
{
    asm volatile("ldmatrix.sync.aligned.m8n8.x4.shared.b16 {%0,%1,%2,%3}, [%4];"
                 : "=r"(r[0]), "=r"(r[1]), "=r"(r[2]), "=r"(r[3]) : "r"(addr));
}

// ---- staging: fp16 global -> pitched smem via cp.async; commits a group ----
template <int NROWS, int NTHR>
__device__ __forceinline__ void stage_h16(
    const __half* __restrict__ G, int gstride, int rows_valid, char* buf, int tid)
{
    unsigned hB = smem_u32(buf);
#pragma unroll
    for (int i = tid; i < NROWS * 16; i += NTHR) {
        int r = i >> 4, c = i & 15;
        unsigned so = (unsigned)r * 272 + c * 16;
        int sz = (r < rows_valid) ? 16 : 0;
        cp16(hB + so, G + (size_t)r * gstride + c * 8, sz);
    }
    cp_commit();
}

// ---- mainloop: single-pass fp16, B fragments preloaded ----
__device__ __forceinline__ void panel_1p(
    const __half* sW, const __half* sX, int warp, int lane, float C[16][4])
{
    const unsigned wh = smem_u32(sW);
    const unsigned xh = smem_u32(sX);
    const unsigned PB = SPITCH * 2;
    const unsigned aoff0 = (unsigned)(warp * 16 + (lane & 15)) * PB + (unsigned)((lane >> 4) & 1) * 16u;
    const unsigned boff0 = (unsigned)((lane & 7) + ((lane & 16) >> 1)) * PB + ((lane & 8) ? 16u : 0u);

    for (int kc = 0; kc < 8; kc++) {
        const unsigned ka = kc * 32;
        unsigned ah[4];
        ldsm4(ah, xh + aoff0 + ka);
        unsigned bhi[8][4];
#pragma unroll
        for (int p = 0; p < 8; p++) ldsm4(bhi[p], wh + boff0 + (unsigned)p * 16 * PB + ka);
#pragma unroll
        for (int p = 0; p < 8; p++) {
            mma_f16(C[2*p],   ah, bhi[p][0], bhi[p][1]);
            mma_f16(C[2*p+1], ah, bhi[p][2], bhi[p][3]);
        }
    }
}

__device__ __forceinline__ void zero_C(float C[16][4])
{
#pragma unroll
    for (int t = 0; t < 16; t++) C[t][0] = C[t][1] = C[t][2] = C[t][3] = 0.f;
}

// ================= register-shuffle reduce epilogues =================
// warp owns rows row_base + warp*16 + {g, g+8}; lane = g*4+tg.

__device__ __forceinline__ void mean4_reg(
    const float C[16][4], const float* __restrict__ bias,
    __half* __restrict__ T2, int out_base, int G, int warp, int g, int tg)
{
    const unsigned F = 0xffffffffu;
    int og0 = out_base + warp * 4;
#pragma unroll
    for (int tt = 0; tt < 16; tt++) {
        int c = tt * 8 + tg * 2;
        float2 b = *(const float2*)(bias + c);
        float v0 = fmaxf(C[tt][0]+b.x,0.f), v1 = fmaxf(C[tt][1]+b.y,0.f);
        float w0 = fmaxf(C[tt][2]+b.x,0.f), w1 = fmaxf(C[tt][3]+b.y,0.f);
        v0 += __shfl_xor_sync(F,v0,4); v0 += __shfl_xor_sync(F,v0,8);
        v1 += __shfl_xor_sync(F,v1,4); v1 += __shfl_xor_sync(F,v1,8);
        w0 += __shfl_xor_sync(F,w0,4); w0 += __shfl_xor_sync(F,w0,8);
        w1 += __shfl_xor_sync(F,w1,4); w1 += __shfl_xor_sync(F,w1,8);
        if ((g & 3) == 0) {
            int q = g >> 2;
            if (og0 + q < G)
                *(__half2*)(T2 + (size_t)(og0+q)*128 + c) = __floats2half2_rn(0.25f*v0, 0.25f*v1);
            if (og0 + 2 + q < G)
                *(__half2*)(T2 + (size_t)(og0+2+q)*128 + c) = __floats2half2_rn(0.25f*w0, 0.25f*w1);
        }
    }
}

__device__ __forceinline__ void pairadd_reg(
    const float C[16][4], const float* __restrict__ bias,
    const float* __restrict__ init, __half* __restrict__ A,
    int out_base, int Mout, int warp, int g, int tg)
{
    const unsigned F = 0xffffffffu;
    int og0 = out_base + warp * 8;
#pragma unroll
    for (int tt = 0; tt < 16; tt++) {
        int c = tt * 8 + tg * 2;
        float2 b = *(const float2*)(bias + c);
        float v0 = fmaxf(C[tt][0]+b.x,0.f), v1 = fmaxf(C[tt][1]+b.y,0.f);
        float w0 = fmaxf(C[tt][2]+b.x,0.f), w1 = fmaxf(C[tt][3]+b.y,0.f);
        v0 += __shfl_xor_sync(F,v0,4);
        v1 += __shfl_xor_sync(F,v1,4);
        w0 += __shfl_xor_sync(F,w0,4);
        w1 += __shfl_xor_sync(F,w1,4);
        if ((g & 1) == 0) {
            int p = g >> 1;
            int og = og0 + p;
            if (og < Mout) {
                float2 iv = *(const float2*)(init + (size_t)og*128 + c);
                *(__half2*)(A + (size_t)og*128 + c) =
                    __floats2half2_rn(iv.x + 0.5f*v0, iv.y + 0.5f*v1);
            }
            int og2 = og0 + 4 + p;
            if (og2 < Mout) {
                float2 iv = *(const float2*)(init + (size_t)og2*128 + c);
                *(__half2*)(A + (size_t)og2*128 + c) =
                    __floats2half2_rn(iv.x + 0.5f*w0, iv.y + 0.5f*w1);
            }
        }
    }
}

__device__ __forceinline__ void combine_reg(
    const float C[16][4], const float* __restrict__ bias,
    const float* __restrict__ CTH, __half* __restrict__ O,
    int row_base, int M1, int warp, int g, int tg)
{
    const unsigned F = 0xffffffffu;
    int r0 = row_base + warp * 16 + g;
    int r1 = r0 + 8;
    int p0 = (row_base + warp * 16) >> 3;
#pragma unroll
    for (int tt = 0; tt < 16; tt++) {
        int c = tt * 8 + tg * 2;
        float2 b = *(const float2*)(bias + c);
        float v0 = fmaxf(C[tt][0]+b.x,0.f), v1 = fmaxf(C[tt][1]+b.y,0.f);
        float w0 = fmaxf(C[tt][2]+b.x,0.f), w1 = fmaxf(C[tt][3]+b.y,0.f);
        float s0 = v0 + __shfl_xor_sync(F,v0,4); s0 += __shfl_xor_sync(F,s0,8);
        float s1 = v1 + __shfl_xor_sync(F,v1,4); s1 += __shfl_xor_sync(F,s1,8);
        float u0 = w0 + __shfl_xor_sync(F,w0,4); u0 += __shfl_xor_sync(F,u0,8);
        float u1 = w1 + __shfl_xor_sync(F,w1,4); u1 += __shfl_xor_sync(F,u1,8);
        if (r0 < M1) {
            float2 cv = *(const float2*)(CTH + (size_t)p0*128 + c);
            *(__half2*)(O + (size_t)r0*128 + c) =
                __floats2half2_rn(0.25f*(cv.x + s0 - v0), 0.25f*(cv.y + s1 - v1));
        }
        if (r1 < M1) {
            float2 cv = *(const float2*)(CTH + (size_t)(p0+1)*128 + c);
            *(__half2*)(O + (size_t)r1*128 + c) =
                __floats2half2_rn(0.25f*(cv.x + u0 - w0), 0.25f*(cv.y + u1 - w1));
        }
    }
}

// ================= 64-row-tile level kernels: 128 threads, 3 blocks/SM =================
// smem: W @0 (WB), X0 @WB, X1 @WB+XB64. Double-buffered X.

__global__ void __launch_bounds__(128, 3) up_mean4_64(
    const __half* __restrict__ X, const __half* __restrict__ W16,
    const float* __restrict__ bias, __half* __restrict__ T2, int M1)
{
    extern __shared__ __align__(1024) char sm[];
    const int tid = threadIdx.x, lane = tid & 31, warp = tid >> 5;
    const int g = lane >> 2, tg = lane & 3;
    stage_h16<128,128>(W16, 128, 128, sm, tid);
    const int ntiles = M1 >> 6;
    int t = blockIdx.x;
    if (t < ntiles) stage_h16<64,128>(X + (size_t)t * 8192, 128, 64, sm + WB, tid);
    for (int phase = 0; t < ntiles; t += gridDim.x, phase++) {
        int cur = phase & 1;
        int tn = t + gridDim.x;
        if (tn < ntiles) {
            stage_h16<64,128>(X + (size_t)tn * 8192, 128, 64, sm + WB + (1 ^ cur) * XB64, tid);
            cp_wait<1>();
        } else cp_wait<0>();
        __syncthreads();
        float C[16][4]; zero_C(C);
        panel_1p((const __half*)sm, (const __half*)(sm + WB + cur * XB64), warp, lane, C);
        __syncthreads();
        mean4_reg(C, bias, T2, t * 16, M1 >> 2, warp, g, tg);
    }
}

__global__ void __launch_bounds__(128, 3) up_pairadd_64(
    const __half* __restrict__ X, const __half* __restrict__ W16,
    const float* __restrict__ bias, const float* __restrict__ init,
    __half* __restrict__ A, int G)
{
    extern __shared__ __align__(1024) char sm[];
    const int tid = threadIdx.x, lane = tid & 31, warp = tid >> 5;
    const int g = lane >> 2, tg = lane & 3;
    stage_h16<128,128>(W16, 128, 128, sm, tid);
    const int ntiles = G >> 6;
    int t = blockIdx.x;
    if (t < ntiles) stage_h16<64,128>(X + (size_t)t * 8192, 128, 64, sm + WB, tid);
    for (int phase = 0; t < ntiles; t += gridDim.x, phase++) {
        int cur = phase & 1;
        int tn = t + gridDim.x;
        if (tn < ntiles) {
            stage_h16<64,128>(X + (size_t)tn * 8192, 128, 64, sm + WB + (1 ^ cur) * XB64, tid);
            cp_wait<1>();
        } else cp_wait<0>();
        __syncthreads();
        float C[16][4]; zero_C(C);
        panel_1p((const __half*)sm, (const __half*)(sm + WB + cur * XB64), warp, lane, C);
        __syncthreads();
        pairadd_reg(C, bias, init, A, t * 32, G >> 1, warp, g, tg);
    }
}

__global__ void __launch_bounds__(128, 3) cth_64(
    const __half* __restrict__ X, const __half* __restrict__ W16,
    const float* __restrict__ bias, float* __restrict__ Y, int M)
{
    extern __shared__ __align__(1024) char sm[];
    const int tid = threadIdx.x, lane = tid & 31, warp = tid >> 5;
    const int g = lane >> 2, tg = lane & 3;
    stage_h16<128,128>(W16, 128, 128, sm, tid);
    const int ntiles = (M + 63) >> 6;
    int t = blockIdx.x;
    if (t < ntiles) {
        int rv = M - t * 64; if (rv > 64) rv = 64;
        stage_h16<64,128>(X + (size_t)t * 8192, 128, rv, sm + WB, tid);
    }
    for (int phase = 0; t < ntiles; t += gridDim.x, phase++) {
        int cur = phase & 1;
        int tn = t + gridDim.x;
        if (tn < ntiles) {
            int rv = M - tn * 64; if (rv > 64) rv = 64;
            stage_h16<64,128>(X + (size_t)tn * 8192, 128, rv, sm + WB + (1 ^ cur) * XB64, tid);
            cp_wait<1>();
        } else cp_wait<0>();
        __syncthreads();
        float C[16][4]; zero_C(C);
        panel_1p((const __half*)sm, (const __half*)(sm + WB + cur * XB64), warp, lane, C);
        __syncthreads();
        const int r0g = t * 64 + warp * 16 + g, r1g = r0g + 8;
#pragma unroll
        for (int tt = 0; tt < 16; tt++) {
            int c = tt * 8 + tg * 2;
            float2 bv = *(const float2*)(bias + c);
            if (r0g < M) {
                float2 o = make_float2(fmaxf(C[tt][0] + bv.x, 0.f), fmaxf(C[tt][1] + bv.y, 0.f));
                *(float2*)(Y + (size_t)r0g * 128 + c) = o;
            }
            if (r1g < M) {
                float2 o = make_float2(fmaxf(C[tt][2] + bv.x, 0.f), fmaxf(C[tt][3] + bv.y, 0.f));
                *(float2*)(Y + (size_t)r1g * 128 + c) = o;
            }
        }
    }
}

__global__ void __launch_bounds__(128, 3) down_combine_64(
    const __half* __restrict__ X, const __half* __restrict__ W16,
    const float* __restrict__ bias, const float* __restrict__ CTH,
    __half* __restrict__ O, int M1)
{
    extern __shared__ __align__(1024) char sm[];
    const int tid = threadIdx.x, lane = tid & 31, warp = tid >> 5;
    const int g = lane >> 2, tg = lane & 3;
    stage_h16<128,128>(W16, 128, 128, sm, tid);
    const int ntiles = M1 >> 6;
    int t = blockIdx.x;
    if (t < ntiles) stage_h16<64,128>(X + (size_t)t * 8192, 128, 64, sm + WB, tid);
    for (int phase = 0; t < ntiles; t += gridDim.x, phase++) {
        int cur = phase & 1;
        int tn = t + gridDim.x;
        if (tn < ntiles) {
            stage_h16<64,128>(X + (size_t)tn * 8192, 128, 64, sm + WB + (1 ^ cur) * XB64, tid);
            cp_wait<1>();
        } else cp_wait<0>();
        __syncthreads();
        float C[16][4]; zero_C(C);
        panel_1p((const __half*)sm, (const __half*)(sm + WB + cur * XB64), warp, lane, C);
        __syncthreads();
        combine_reg(C, bias, CTH, O, t * 64, M1, warp, g, tg);
    }
}

// ================= final kernel (128 threads, 2 blocks/SM, panel-pipelined) =================
__global__ void __launch_bounds__(128, 2) final_64(
    const __half* __restrict__ CTX, const __half* __restrict__ ACT,
    const __half* __restrict__ Wf16, const float* __restrict__ bf,
    const float* __restrict__ Wh, const float* __restrict__ bh,
    float* __restrict__ out, int M)
{
    extern __shared__ __align__(1024) char sm[];
    const int tid = threadIdx.x, lane = tid & 31, warp = tid >> 5;
    const int g = lane >> 2, tg = lane & 3;
    char* X0 = sm + 2 * WB;
    char* X1 = sm + 2 * WB + XB64;

    stage_h16<128, 128>(Wf16,       256, 128, sm,      tid);
    stage_h16<128, 128>(Wf16 + 128, 256, 128, sm + WB, tid);

    const int ntiles = (M + 63) >> 6;
    int t = blockIdx.x;
    if (t < ntiles) {
        int rv = M - t * 64; if (rv > 64) rv = 64;
        stage_h16<64, 128>(CTX + (size_t)t * 8192, 128, rv, X0, tid);
    }
    for (; t < ntiles; t += gridDim.x) {
        int rv = M - t * 64; if (rv > 64) rv = 64;
        stage_h16<64, 128>(ACT + (size_t)t * 8192, 128, rv, X1, tid);
        cp_wait<1>();
        __syncthreads();
        float C[16][4]; zero_C(C);
        panel_1p((const __half*)sm, (const __half*)X0, warp, lane, C);
        __syncthreads();
        int tn = t + gridDim.x;
        if (tn < ntiles) {
            int rv2 = M - tn * 64; if (rv2 > 64) rv2 = 64;
            stage_h16<64, 128>(CTX + (size_t)tn * 8192, 128, rv2, X0, tid);
            cp_wait<1>();
        } else cp_wait<0>();
        __syncthreads();
        panel_1p((const __half*)(sm + WB), (const __half*)X1, warp, lane, C);
        __syncthreads();
        float s0 = 0.f, s1 = 0.f;
#pragma unroll
        for (int tt = 0; tt < 16; tt++) {
            int c = tt * 8 + tg * 2;
            float2 bv = *(const float2*)(bf + c);
            float2 wv = *(const float2*)(Wh + c);
            s0 += fmaxf(C[tt][0] + bv.x, 0.f) * wv.x + fmaxf(C[tt][1] + bv.y, 0.f) * wv.y;
            s1 += fmaxf(C[tt][2] + bv.x, 0.f) * wv.x + fmaxf(C[tt][3] + bv.y, 0.f) * wv.y;
        }
        s0 += __shfl_xor_sync(0xffffffffu, s0, 1);
        s0 += __shfl_xor_sync(0xffffffffu, s0, 2);
        s1 += __shfl_xor_sync(0xffffffffu, s1, 1);
        s1 += __shfl_xor_sync(0xffffffffu, s1, 2);
        if (tg == 0) {
            int r0g = t * 64 + warp * 16 + g, r1g = r0g + 8;
            float bhv = bh[0];
            if (r0g < M) out[r0g] = s0 + bhv;
            if (r1g < M) out[r1g] = s1 + bhv;
        }
    }
}

// ================= tiny-level kernels (256 threads, single block) =================
__global__ void __launch_bounds__(256) up_small(
    const __half* __restrict__ Xc, const float* __restrict__ init_l,
    __half* __restrict__ A,
    const __half* __restrict__ Ws16, const float* __restrict__ bs,
    const __half* __restrict__ Wc16, const float* __restrict__ bc,
    __half* __restrict__ T2, int M1)
{
    extern __shared__ __align__(1024) char sm[];
    char* xb = sm + WB;
    const int tid = threadIdx.x, lane = tid & 31, warp = tid >> 5;
    const int g = lane >> 2, tg = lane & 3;
    const int G = M1 >> 2, Mout = M1 >> 3;

    stage_h16<128, 256>(Ws16, 128, 128, sm, tid);
    stage_h16<128, 256>(Xc, 128, M1, xb, tid);
    cp_wait<0>();
    __syncthreads();
    {
        float C[16][4]; zero_C(C);
        panel_1p((const __half*)sm, (const __half*)xb, warp, lane, C);
        __syncthreads();
        mean4_reg(C, bs, T2, 0, G, warp, g, tg);
        __threadfence_block();
        __syncthreads();
    }
    stage_h16<128, 256>(Wc16, 128, 128, sm, tid);
    stage_h16<128, 256>(T2, 128, G, xb, tid);
    cp_wait<0>();
    __syncthreads();
    {
        float C[16][4]; zero_C(C);
        panel_1p((const __half*)sm, (const __half*)xb, warp, lane, C);
        __syncthreads();
        pairadd_reg(C, bc, init_l, A, 0, Mout, warp, g, tg);
    }
}

__global__ void __launch_bounds__(256) down_small(
    const __half* __restrict__ CTX, const __half* __restrict__ AC,
    const __half* __restrict__ Wx16, const float* __restrict__ bx,
    float* __restrict__ CTH, __half* __restrict__ O, int Ml, int M1)
{
    extern __shared__ __align__(1024) char sm[];
    char* xb = sm + WB;
    const int tid = threadIdx.x, lane = tid & 31, warp = tid >> 5;
    const int g = lane >> 2, tg = lane & 3;

    stage_h16<128, 256>(Wx16, 128, 128, sm, tid);
    stage_h16<128, 256>(CTX, 128, Ml, xb, tid);
    cp_wait<0>();
    __syncthreads();
    {
        float C[16][4]; zero_C(C);
        panel_1p((const __half*)sm, (const __half*)xb, warp, lane, C);
        const int r0 = warp * 16 + g, r1 = r0 + 8;
#pragma unroll
        for (int t = 0; t < 16; t++) {
            int c = t * 8 + tg * 2;
            float2 bv = *(const float2*)(bx + c);
            if (r0 < Ml) {
                float2 o = make_float2(fmaxf(C[t][0] + bv.x, 0.f), fmaxf(C[t][1] + bv.y, 0.f));
                *(float2*)(CTH + (size_t)r0 * 128 + c) = o;
            }
            if (r1 < Ml) {
                float2 o = make_float2(fmaxf(C[t][2] + bv.x, 0.f), fmaxf(C[t][3] + bv.y, 0.f));
                *(float2*)(CTH + (size_t)r1 * 128 + c) = o;
            }
        }
        __threadfence_block();
        __syncthreads();
    }
    stage_h16<128, 256>(AC, 128, M1, xb, tid);
    cp_wait<0>();
    __syncthreads();
    {
        float C[16][4]; zero_C(C);
        panel_1p((const __half*)sm, (const __half*)xb, warp, lane, C);
        __syncthreads();
        combine_reg(C, bx, CTH, O, 0, M1, warp, g, tg);
    }
}

// ================= utility kernels =================
__global__ void convert_weights(
    const float* __restrict__ Ws, const float* __restrict__ Wc,
    const float* __restrict__ Wx, const float* __restrict__ Wf)
{
    int i = blockIdx.x * blockDim.x + threadIdx.x;
    int stride = gridDim.x * blockDim.x;
    for (int k = i; k < 16384; k += stride) {
        g_ws16[k] = __float2half_rn(Ws[k]);
        g_wc16[k] = __float2half_rn(Wc[k]);
        g_wx16[k] = __float2half_rn(Wx[k]);
    }
    for (int k = i; k < 32768; k += stride) {
        g_wf16[k] = __float2half_rn(Wf[k]);
    }
}

__global__ void leaf_convert(const float4* __restrict__ in, uint4* __restrict__ out8, long n8)
{
    long i = (long)blockIdx.x * blockDim.x + threadIdx.x;
    long stride = (long)gridDim.x * blockDim.x;
    for (; i < n8; i += stride) {
        float4 a = in[2 * i], b = in[2 * i + 1];
        uint4 r;
        r.x = ((unsigned)__half_as_ushort(__float2half_rn(a.y))<<16) | __half_as_ushort(__float2half_rn(a.x));
        r.y = ((unsigned)__half_as_ushort(__float2half_rn(a.w))<<16) | __half_as_ushort(__float2half_rn(a.z));
        r.z = ((unsigned)__half_as_ushort(__float2half_rn(b.y))<<16) | __half_as_ushort(__float2half_rn(b.x));
        r.w = ((unsigned)__half_as_ushort(__float2half_rn(b.w))<<16) | __half_as_ushort(__float2half_rn(b.z));
        out8[i] = r;
    }
}

__global__ void set_ones_h(__half* p)
{
    p[threadIdx.x] = __float2half(1.0f);
}

// ---------------- launch ----------------
static inline int grid64(int rows, int cap) {
    int nt = (rows + 63) >> 6;
    return nt < cap ? nt : cap;
}

extern "C" void kernel_launch(void* const* d_in, const int* in_sizes, int n_in,
                              void* d_out, int out_size)
{
    const float* initial = (const float*)d_in[0];
    const float* Ws = (const float*)d_in[1];
    const float* bs = (const float*)d_in[2];
    const float* Wc = (const float*)d_in[3];
    const float* bc = (const float*)d_in[4];
    const float* Wx = (const float*)d_in[5];
    const float* bx = (const float*)d_in[6];
    const float* Wf = (const float*)d_in[7];
    const float* bf = (const float*)d_in[8];
    const float* Wh = (const float*)d_in[9];
    const float* bh = (const float*)d_in[10];
    float* out = (float*)d_out;

    __half *act, *ctx, *t2, *ws16, *wc16, *wx16, *wf16;
    float* cth;
    cudaGetSymbolAddress((void**)&act,  g_act);
    cudaGetSymbolAddress((void**)&ctx,  g_ctx);
    cudaGetSymbolAddress((void**)&t2,   g_t2);
    cudaGetSymbolAddress((void**)&cth,  g_cth);
    cudaGetSymbolAddress((void**)&ws16, g_ws16);
    cudaGetSymbolAddress((void**)&wc16, g_wc16);
    cudaGetSymbolAddress((void**)&wx16, g_wx16);
    cudaGetSymbolAddress((void**)&wf16, g_wf16);

    cudaFuncSetAttribute(up_mean4_64,     cudaFuncAttributeMaxDynamicSharedMemorySize, SMEM_64);
    cudaFuncSetAttribute(up_pairadd_64,   cudaFuncAttributeMaxDynamicSharedMemorySize, SMEM_64);
    cudaFuncSetAttribute(cth_64,          cudaFuncAttributeMaxDynamicSharedMemorySize, SMEM_64);
    cudaFuncSetAttribute(down_combine_64, cudaFuncAttributeMaxDynamicSharedMemorySize, SMEM_64);
    cudaFuncSetAttribute(final_64,        cudaFuncAttributeMaxDynamicSharedMemorySize, SMEM_FIN);
    cudaFuncSetAttribute(up_small,        cudaFuncAttributeMaxDynamicSharedMemorySize, SMEM_SMALL);
    cudaFuncSetAttribute(down_small,      cudaFuncAttributeMaxDynamicSharedMemorySize, SMEM_SMALL);

    convert_weights<<<64, 256>>>(Ws, Wc, Wx, Wf);
    leaf_convert<<<2048, 256>>>(
        (const float4*)(initial + (size_t)NTOP * DIM),
        (uint4*)(act + (size_t)NTOP * DIM),
        (long)262144 * DIM / 8);

    // ---- up pass: levels 5..2 ----
    for (int l = 5; l >= 2; l--) {
        int M1 = H_SIZES[l + 1];
        int G  = M1 >> 2;
        up_mean4_64<<<grid64(M1, 444), 128, SMEM_64>>>(
            act + (size_t)H_OFFS[l + 1] * DIM, ws16, bs, t2, M1);
        up_pairadd_64<<<grid64(G, 444), 128, SMEM_64>>>(
            t2, wc16, bc, initial + (size_t)H_OFFS[l] * DIM,
            act + (size_t)H_OFFS[l] * DIM, G);
    }
    for (int l = 1; l >= 0; l--) {
        up_small<<<1, 256, SMEM_SMALL>>>(
            act + (size_t)H_OFFS[l + 1] * DIM,
            initial + (size_t)H_OFFS[l] * DIM,
            act + (size_t)H_OFFS[l] * DIM,
            ws16, bs, wc16, bc, t2, H_SIZES[l + 1]);
    }

    // ---- down pass ----
    set_ones_h<<<1, 128>>>(ctx);
    for (int l = 0; l < 2; l++) {
        down_small<<<1, 256, SMEM_SMALL>>>(
            ctx + (size_t)H_OFFS[l] * DIM,
            act + (size_t)H_OFFS[l + 1] * DIM,
            wx16, bx, cth,
            ctx + (size_t)H_OFFS[l + 1] * DIM, H_SIZES[l], H_SIZES[l + 1]);
    }
    for (int l = 2; l < 6; l++) {
        int Ml = H_SIZES[l], M1 = H_SIZES[l + 1];
        cth_64<<<grid64(Ml, 444), 128, SMEM_64>>>(
            ctx + (size_t)H_OFFS[l] * DIM, wx16, bx, cth, Ml);
        down_combine_64<<<grid64(M1, 444), 128, SMEM_64>>>(
            act + (size_t)H_OFFS[l + 1] * DIM, wx16, bx, cth,
            ctx + (size_t)H_OFFS[l + 1] * DIM, M1);
    }

    // ---- final ----
    final_64<<<296, 128, SMEM_FIN>>>(
        ctx, act, wf16, bf, Wh, bh, out, N_TOTAL);
}

// round 16
// speedup vs baseline: 2.9175x; 1.0510x over previous
#include <cuda_runtime.h>
#include <cuda_fp16.h>
#include <cstdint>

#define DIM 128
#define N_TOTAL 299593
#define NTOP 37449

static const int H_SIZES[7] = {1, 8, 64, 512, 4096, 32768, 262144};
static const int H_OFFS[8]  = {0, 1, 9, 73, 585, 4681, 37449, 299593};
// cth row offset for level l (levels 2..5 live in g_cth): H_OFFS[l] - H_OFFS[2]
static const int CTH_OFF[6] = {0, 0, 0, 64, 576, 4672};

// ---------------- scratch ----------------
__device__ __half g_act[N_TOTAL * DIM];     // agg rows 0..NTOP-1, leaves NTOP..
__device__ __half g_ctx[N_TOTAL * DIM];
__device__ __half g_t2 [65536 * DIM];
__device__ __half g_init16[NTOP * DIM];     // fp16 copy of initial (non-leaf rows)
__device__ float  g_cth[37440 * DIM];       // cth levels 2..5, level-indexed
__device__ __half g_ws16[128 * 128];
__device__ __half g_wc16[128 * 128];
__device__ __half g_wx16[128 * 128];
__device__ __half g_wf16[128 * 256];

// ================= common =================
#define SPITCH 136
#define WB     34816
#define XB64   17408

#define SMEM_64    (WB + 2 * XB64)      // 69632  -> 3 blocks/SM
#define SMEM_FIN   (2 * WB + 2 * XB64)  // 104448 -> 2 blocks/SM
#define SMEM_SMALL (2 * WB)             // 69632

__device__ __forceinline__ uint32_t smem_u32(const void* p) {
    return (uint32_t)__cvta_generic_to_shared(p);
}
__device__ __forceinline__ void cp16(unsigned saddr, const void* gptr, int sz) {
    asm volatile("cp.async.cg.shared.global [%0], [%1], 16, %2;"
                 :: "r"(saddr), "l"(gptr), "r"(sz));
}
template<int N>
__device__ __forceinline__ void cp_wait() {
    asm volatile("cp.async.wait_group %0;" :: "n"(N) : "memory");
}
__device__ __forceinline__ void cp_commit() {
    asm volatile("cp.async.commit_group;");
}

__device__ __forceinline__ void mma_f16(float* c, const unsigned* a, unsigned b0, unsigned b1)
{
    asm volatile(
        "mma.sync.aligned.m16n8k16.row.col.f32.f16.f16.f32 "
        "{%0,%1,%2,%3},{%4,%5,%6,%7},{%8,%9},{%0,%1,%2,%3};\n"
        : "+f"(c[0]), "+f"(c[1]), "+f"(c[2]), "+f"(c[3])
        : "r"(a[0]), "r"(a[1]), "r"(a[2]), "r"(a[3]), "r"(b0), "r"(b1));
}
__device__ __forceinline__ void ldsm4(unsigned* r, unsigned addr)
{
    asm volatile("ldmatrix.sync.aligned.m8n8.x4.shared.b16 {%0,%1,%2,%3}, [%4];"
                 : "=r"(r[0]), "=r"(r[1]), "=r"(r[2]), "=r"(r[3]) : "r"(addr));
}

// ---- staging: fp16 global -> pitched smem via cp.async; commits a group ----
template <int NROWS, int NTHR>
__device__ __forceinline__ void stage_h16(
    const __half* __restrict__ G, int gstride, int rows_valid, char* buf, int tid)
{
    unsigned hB = smem_u32(buf);
#pragma unroll
    for (int i = tid; i < NROWS * 16; i += NTHR) {
        int r = i >> 4, c = i & 15;
        unsigned so = (unsigned)r * 272 + c * 16;
        int sz = (r < rows_valid) ? 16 : 0;
        cp16(hB + so, G + (size_t)r * gstride + c * 8, sz);
    }
    cp_commit();
}

// ---- mainloop: single-pass fp16, B fragments preloaded ----
__device__ __forceinline__ void panel_1p(
    const __half* sW, const __half* sX, int warp, int lane, float C[16][4])
{
    const unsigned wh = smem_u32(sW);
    const unsigned xh = smem_u32(sX);
    const unsigned PB = SPITCH * 2;
    const unsigned aoff0 = (unsigned)(warp * 16 + (lane & 15)) * PB + (unsigned)((lane >> 4) & 1) * 16u;
    const unsigned boff0 = (unsigned)((lane & 7) + ((lane & 16) >> 1)) * PB + ((lane & 8) ? 16u : 0u);

    for (int kc = 0; kc < 8; kc++) {
        const unsigned ka = kc * 32;
        unsigned ah[4];
        ldsm4(ah, xh + aoff0 + ka);
        unsigned bhi[8][4];
#pragma unroll
        for (int p = 0; p < 8; p++) ldsm4(bhi[p], wh + boff0 + (unsigned)p * 16 * PB + ka);
#pragma unroll
        for (int p = 0; p < 8; p++) {
            mma_f16(C[2*p],   ah, bhi[p][0], bhi[p][1]);
            mma_f16(C[2*p+1], ah, bhi[p][2], bhi[p][3]);
        }
    }
}

__device__ __forceinline__ void zero_C(float C[16][4])
{
#pragma unroll
    for (int t = 0; t < 16; t++) C[t][0] = C[t][1] = C[t][2] = C[t][3] = 0.f;
}

// ================= register-shuffle reduce epilogues =================

__device__ __forceinline__ void mean4_reg(
    const float C[16][4], const float* __restrict__ bias,
    __half* __restrict__ T2, int out_base, int G, int warp, int g, int tg)
{
    const unsigned F = 0xffffffffu;
    int og0 = out_base + warp * 4;
#pragma unroll
    for (int tt = 0; tt < 16; tt++) {
        int c = tt * 8 + tg * 2;
        float2 b = *(const float2*)(bias + c);
        float v0 = fmaxf(C[tt][0]+b.x,0.f), v1 = fmaxf(C[tt][1]+b.y,0.f);
        float w0 = fmaxf(C[tt][2]+b.x,0.f), w1 = fmaxf(C[tt][3]+b.y,0.f);
        v0 += __shfl_xor_sync(F,v0,4); v0 += __shfl_xor_sync(F,v0,8);
        v1 += __shfl_xor_sync(F,v1,4); v1 += __shfl_xor_sync(F,v1,8);
        w0 += __shfl_xor_sync(F,w0,4); w0 += __shfl_xor_sync(F,w0,8);
        w1 += __shfl_xor_sync(F,w1,4); w1 += __shfl_xor_sync(F,w1,8);
        if ((g & 3) == 0) {
            int q = g >> 2;
            if (og0 + q < G)
                *(__half2*)(T2 + (size_t)(og0+q)*128 + c) = __floats2half2_rn(0.25f*v0, 0.25f*v1);
            if (og0 + 2 + q < G)
                *(__half2*)(T2 + (size_t)(og0+2+q)*128 + c) = __floats2half2_rn(0.25f*w0, 0.25f*w1);
        }
    }
}

// init now fp16
__device__ __forceinline__ void pairadd_reg(
    const float C[16][4], const float* __restrict__ bias,
    const __half* __restrict__ init16, __half* __restrict__ A,
    int out_base, int Mout, int warp, int g, int tg)
{
    const unsigned F = 0xffffffffu;
    int og0 = out_base + warp * 8;
#pragma unroll
    for (int tt = 0; tt < 16; tt++) {
        int c = tt * 8 + tg * 2;
        float2 b = *(const float2*)(bias + c);
        float v0 = fmaxf(C[tt][0]+b.x,0.f), v1 = fmaxf(C[tt][1]+b.y,0.f);
        float w0 = fmaxf(C[tt][2]+b.x,0.f), w1 = fmaxf(C[tt][3]+b.y,0.f);
        v0 += __shfl_xor_sync(F,v0,4);
        v1 += __shfl_xor_sync(F,v1,4);
        w0 += __shfl_xor_sync(F,w0,4);
        w1 += __shfl_xor_sync(F,w1,4);
        if ((g & 1) == 0) {
            int p = g >> 1;
            int og = og0 + p;
            if (og < Mout) {
                float2 iv = __half22float2(*(const __half2*)(init16 + (size_t)og*128 + c));
                *(__half2*)(A + (size_t)og*128 + c) =
                    __floats2half2_rn(iv.x + 0.5f*v0, iv.y + 0.5f*v1);
            }
            int og2 = og0 + 4 + p;
            if (og2 < Mout) {
                float2 iv = __half22float2(*(const __half2*)(init16 + (size_t)og2*128 + c));
                *(__half2*)(A + (size_t)og2*128 + c) =
                    __floats2half2_rn(iv.x + 0.5f*w0, iv.y + 0.5f*w1);
            }
        }
    }
}

// combine; optionally also write the result tile into pitched smem (for fused cth)
template <bool TO_SMEM>
__device__ __forceinline__ void combine_reg(
    const float C[16][4], const float* __restrict__ bias,
    const float* __restrict__ CTH, __half* __restrict__ O, char* Osm,
    int row_base, int M1, int warp, int g, int tg)
{
    const unsigned F = 0xffffffffu;
    int lr0 = warp * 16 + g, lr1 = lr0 + 8;
    int r0 = row_base + lr0, r1 = row_base + lr1;
    int p0 = (row_base + warp * 16) >> 3;
#pragma unroll
    for (int tt = 0; tt < 16; tt++) {
        int c = tt * 8 + tg * 2;
        float2 b = *(const float2*)(bias + c);
        float v0 = fmaxf(C[tt][0]+b.x,0.f), v1 = fmaxf(C[tt][1]+b.y,0.f);
        float w0 = fmaxf(C[tt][2]+b.x,0.f), w1 = fmaxf(C[tt][3]+b.y,0.f);
        float s0 = v0 + __shfl_xor_sync(F,v0,4); s0 += __shfl_xor_sync(F,s0,8);
        float s1 = v1 + __shfl_xor_sync(F,v1,4); s1 += __shfl_xor_sync(F,s1,8);
        float u0 = w0 + __shfl_xor_sync(F,w0,4); u0 += __shfl_xor_sync(F,u0,8);
        float u1 = w1 + __shfl_xor_sync(F,w1,4); u1 += __shfl_xor_sync(F,u1,8);
        if (r0 < M1) {
            float2 cv = *(const float2*)(CTH + (size_t)p0*128 + c);
            __half2 h = __floats2half2_rn(0.25f*(cv.x + s0 - v0), 0.25f*(cv.y + s1 - v1));
            *(__half2*)(O + (size_t)r0*128 + c) = h;
            if (TO_SMEM) *(__half2*)(Osm + (size_t)lr0*272 + c*2) = h;
        }
        if (r1 < M1) {
            float2 cv = *(const float2*)(CTH + (size_t)(p0+1)*128 + c);
            __half2 h = __floats2half2_rn(0.25f*(cv.x + u0 - w0), 0.25f*(cv.y + u1 - w1));
            *(__half2*)(O + (size_t)r1*128 + c) = h;
            if (TO_SMEM) *(__half2*)(Osm + (size_t)lr1*272 + c*2) = h;
        }
    }
}

// ================= 64-row-tile level kernels: 128 threads, 3 blocks/SM =================

__global__ void __launch_bounds__(128, 3) up_mean4_64(
    const __half* __restrict__ X, const __half* __restrict__ W16,
    const float* __restrict__ bias, __half* __restrict__ T2, int M1)
{
    extern __shared__ __align__(1024) char sm[];
    const int tid = threadIdx.x, lane = tid & 31, warp = tid >> 5;
    const int g = lane >> 2, tg = lane & 3;
    stage_h16<128,128>(W16, 128, 128, sm, tid);
    const int ntiles = M1 >> 6;
    int t = blockIdx.x;
    if (t < ntiles) stage_h16<64,128>(X + (size_t)t * 8192, 128, 64, sm + WB, tid);
    for (int phase = 0; t < ntiles; t += gridDim.x, phase++) {
        int cur = phase & 1;
        int tn = t + gridDim.x;
        if (tn < ntiles) {
            stage_h16<64,128>(X + (size_t)tn * 8192, 128, 64, sm + WB + (1 ^ cur) * XB64, tid);
            cp_wait<1>();
        } else cp_wait<0>();
        __syncthreads();
        float C[16][4]; zero_C(C);
        panel_1p((const __half*)sm, (const __half*)(sm + WB + cur * XB64), warp, lane, C);
        __syncthreads();
        mean4_reg(C, bias, T2, t * 16, M1 >> 2, warp, g, tg);
    }
}

__global__ void __launch_bounds__(128, 3) up_pairadd_64(
    const __half* __restrict__ X, const __half* __restrict__ W16,
    const float* __restrict__ bias, const __half* __restrict__ init16,
    __half* __restrict__ A, int G)
{
    extern __shared__ __align__(1024) char sm[];
    const int tid = threadIdx.x, lane = tid & 31, warp = tid >> 5;
    const int g = lane >> 2, tg = lane & 3;
    stage_h16<128,128>(W16, 128, 128, sm, tid);
    const int ntiles = G >> 6;
    int t = blockIdx.x;
    if (t < ntiles) stage_h16<64,128>(X + (size_t)t * 8192, 128, 64, sm + WB, tid);
    for (int phase = 0; t < ntiles; t += gridDim.x, phase++) {
        int cur = phase & 1;
        int tn = t + gridDim.x;
        if (tn < ntiles) {
            stage_h16<64,128>(X + (size_t)tn * 8192, 128, 64, sm + WB + (1 ^ cur) * XB64, tid);
            cp_wait<1>();
        } else cp_wait<0>();
        __syncthreads();
        float C[16][4]; zero_C(C);
        panel_1p((const __half*)sm, (const __half*)(sm + WB + cur * XB64), warp, lane, C);
        __syncthreads();
        pairadd_reg(C, bias, init16, A, t * 32, G >> 1, warp, g, tg);
    }
}

__global__ void __launch_bounds__(128, 3) cth_64(
    const __half* __restrict__ X, const __half* __restrict__ W16,
    const float* __restrict__ bias, float* __restrict__ Y, int M)
{
    extern __shared__ __align__(1024) char sm[];
    const int tid = threadIdx.x, lane = tid & 31, warp = tid >> 5;
    const int g = lane >> 2, tg = lane & 3;
    stage_h16<128,128>(W16, 128, 128, sm, tid);
    const int ntiles = (M + 63) >> 6;
    int t = blockIdx.x;
    if (t < ntiles) {
        int rv = M - t * 64; if (rv > 64) rv = 64;
        stage_h16<64,128>(X + (size_t)t * 8192, 128, rv, sm + WB, tid);
    }
    for (int phase = 0; t < ntiles; t += gridDim.x, phase++) {
        int cur = phase & 1;
        int tn = t + gridDim.x;
        if (tn < ntiles) {
            int rv = M - tn * 64; if (rv > 64) rv = 64;
            stage_h16<64,128>(X + (size_t)tn * 8192, 128, rv, sm + WB + (1 ^ cur) * XB64, tid);
            cp_wait<1>();
        } else cp_wait<0>();
        __syncthreads();
        float C[16][4]; zero_C(C);
        panel_1p((const __half*)sm, (const __half*)(sm + WB + cur * XB64), warp, lane, C);
        __syncthreads();
        const int r0g = t * 64 + warp * 16 + g, r1g = r0g + 8;
#pragma unroll
        for (int tt = 0; tt < 16; tt++) {
            int c = tt * 8 + tg * 2;
            float2 bv = *(const float2*)(bias + c);
            if (r0g < M) {
                float2 o = make_float2(fmaxf(C[tt][0] + bv.x, 0.f), fmaxf(C[tt][1] + bv.y, 0.f));
                *(float2*)(Y + (size_t)r0g * 128 + c) = o;
            }
            if (r1g < M) {
                float2 o = make_float2(fmaxf(C[tt][2] + bv.x, 0.f), fmaxf(C[tt][3] + bv.y, 0.f));
                *(float2*)(Y + (size_t)r1g * 128 + c) = o;
            }
        }
    }
}

// down-combine; EMIT_CTH: also compute cth(l+1) for the produced ctx rows via a
// second panel on the same Wx (already in smem) using the just-written tile.
template <bool EMIT_CTH>
__global__ void __launch_bounds__(128, 3) down_combine_f(
    const __half* __restrict__ X, const __half* __restrict__ W16,
    const float* __restrict__ bias, const float* __restrict__ CTH_in,
    __half* __restrict__ O, float* __restrict__ CTH_out, int M1)
{
    extern __shared__ __align__(1024) char sm[];
    const int tid = threadIdx.x, lane = tid & 31, warp = tid >> 5;
    const int g = lane >> 2, tg = lane & 3;
    stage_h16<128,128>(W16, 128, 128, sm, tid);
    const int ntiles = M1 >> 6;
    int t = blockIdx.x;
    if (t < ntiles) stage_h16<64,128>(X + (size_t)t * 8192, 128, 64, sm + WB, tid);
    for (int phase = 0; t < ntiles; t += gridDim.x, phase++) {
        int cur = phase & 1;
        char* Xc = sm + WB + cur * XB64;
        int tn = t + gridDim.x;
        if (tn < ntiles) {
            stage_h16<64,128>(X + (size_t)tn * 8192, 128, 64, sm + WB + (1 ^ cur) * XB64, tid);
            cp_wait<1>();
        } else cp_wait<0>();
        __syncthreads();
        float C[16][4]; zero_C(C);
        panel_1p((const __half*)sm, (const __half*)Xc, warp, lane, C);
        __syncthreads();
        combine_reg<EMIT_CTH>(C, bias, CTH_in, O, Xc, t * 64, M1, warp, g, tg);
        if (EMIT_CTH) {
            __syncthreads();   // O tile fully in smem
            float D[16][4]; zero_C(D);
            panel_1p((const __half*)sm, (const __half*)Xc, warp, lane, D);
            const int r0g = t * 64 + warp * 16 + g, r1g = r0g + 8;
#pragma unroll
            for (int tt = 0; tt < 16; tt++) {
                int c = tt * 8 + tg * 2;
                float2 bv = *(const float2*)(bias + c);
                float2 o0 = make_float2(fmaxf(D[tt][0] + bv.x, 0.f), fmaxf(D[tt][1] + bv.y, 0.f));
                float2 o1 = make_float2(fmaxf(D[tt][2] + bv.x, 0.f), fmaxf(D[tt][3] + bv.y, 0.f));
                if (r0g < M1) *(float2*)(CTH_out + (size_t)r0g * 128 + c) = o0;
                if (r1g < M1) *(float2*)(CTH_out + (size_t)r1g * 128 + c) = o1;
            }
            __syncthreads();   // panel2 reads done before next prefetch overwrites Xc
        }
    }
}

// ================= final kernel (128 threads, 2 blocks/SM, panel-pipelined) =================
__global__ void __launch_bounds__(128, 2) final_64(
    const __half* __restrict__ CTX, const __half* __restrict__ ACT,
    const __half* __restrict__ Wf16, const float* __restrict__ bf,
    const float* __restrict__ Wh, const float* __restrict__ bh,
    float* __restrict__ out, int M)
{
    extern __shared__ __align__(1024) char sm[];
    const int tid = threadIdx.x, lane = tid & 31, warp = tid >> 5;
    const int g = lane >> 2, tg = lane & 3;
    char* X0 = sm + 2 * WB;
    char* X1 = sm + 2 * WB + XB64;

    stage_h16<128, 128>(Wf16,       256, 128, sm,      tid);
    stage_h16<128, 128>(Wf16 + 128, 256, 128, sm + WB, tid);

    const int ntiles = (M + 63) >> 6;
    int t = blockIdx.x;
    if (t < ntiles) {
        int rv = M - t * 64; if (rv > 64) rv = 64;
        stage_h16<64, 128>(CTX + (size_t)t * 8192, 128, rv, X0, tid);
    }
    for (; t < ntiles; t += gridDim.x) {
        int rv = M - t * 64; if (rv > 64) rv = 64;
        stage_h16<64, 128>(ACT + (size_t)t * 8192, 128, rv, X1, tid);
        cp_wait<1>();
        __syncthreads();
        float C[16][4]; zero_C(C);
        panel_1p((const __half*)sm, (const __half*)X0, warp, lane, C);
        __syncthreads();
        int tn = t + gridDim.x;
        if (tn < ntiles) {
            int rv2 = M - tn * 64; if (rv2 > 64) rv2 = 64;
            stage_h16<64, 128>(CTX + (size_t)tn * 8192, 128, rv2, X0, tid);
            cp_wait<1>();
        } else cp_wait<0>();
        __syncthreads();
        panel_1p((const __half*)(sm + WB), (const __half*)X1, warp, lane, C);
        __syncthreads();
        float s0 = 0.f, s1 = 0.f;
#pragma unroll
        for (int tt = 0; tt < 16; tt++) {
            int c = tt * 8 + tg * 2;
            float2 bv = *(const float2*)(bf + c);
            float2 wv = *(const float2*)(Wh + c);
            s0 += fmaxf(C[tt][0] + bv.x, 0.f) * wv.x + fmaxf(C[tt][1] + bv.y, 0.f) * wv.y;
            s1 += fmaxf(C[tt][2] + bv.x, 0.f) * wv.x + fmaxf(C[tt][3] + bv.y, 0.f) * wv.y;
        }
        s0 += __shfl_xor_sync(0xffffffffu, s0, 1);
        s0 += __shfl_xor_sync(0xffffffffu, s0, 2);
        s1 += __shfl_xor_sync(0xffffffffu, s1, 1);
        s1 += __shfl_xor_sync(0xffffffffu, s1, 2);
        if (tg == 0) {
            int r0g = t * 64 + warp * 16 + g, r1g = r0g + 8;
            float bhv = bh[0];
            if (r0g < M) out[r0g] = s0 + bhv;
            if (r1g < M) out[r1g] = s1 + bhv;
        }
    }
}

// ================= tiny-level kernels (256 threads, single block) =================
__global__ void __launch_bounds__(256) up_small(
    const __half* __restrict__ Xc, const __half* __restrict__ init16,
    __half* __restrict__ A,
    const __half* __restrict__ Ws16, const float* __restrict__ bs,
    const __half* __restrict__ Wc16, const float* __restrict__ bc,
    __half* __restrict__ T2, int M1)
{
    extern __shared__ __align__(1024) char sm[];
    char* xb = sm + WB;
    const int tid = threadIdx.x, lane = tid & 31, warp = tid >> 5;
    const int g = lane >> 2, tg = lane & 3;
    const int G = M1 >> 2, Mout = M1 >> 3;

    stage_h16<128, 256>(Ws16, 128, 128, sm, tid);
    stage_h16<128, 256>(Xc, 128, M1, xb, tid);
    cp_wait<0>();
    __syncthreads();
    {
        float C[16][4]; zero_C(C);
        panel_1p((const __half*)sm, (const __half*)xb, warp, lane, C);
        __syncthreads();
        mean4_reg(C, bs, T2, 0, G, warp, g, tg);
        __threadfence_block();
        __syncthreads();
    }
    stage_h16<128, 256>(Wc16, 128, 128, sm, tid);
    stage_h16<128, 256>(T2, 128, G, xb, tid);
    cp_wait<0>();
    __syncthreads();
    {
        float C[16][4]; zero_C(C);
        panel_1p((const __half*)sm, (const __half*)xb, warp, lane, C);
        __syncthreads();
        pairadd_reg(C, bc, init16, A, 0, Mout, warp, g, tg);
    }
}

__global__ void __launch_bounds__(256) down_small(
    const __half* __restrict__ CTX, const __half* __restrict__ AC,
    const __half* __restrict__ Wx16, const float* __restrict__ bx,
    float* __restrict__ CTH, __half* __restrict__ O, int Ml, int M1)
{
    extern __shared__ __align__(1024) char sm[];
    char* xb = sm + WB;
    const int tid = threadIdx.x, lane = tid & 31, warp = tid >> 5;
    const int g = lane >> 2, tg = lane & 3;

    stage_h16<128, 256>(Wx16, 128, 128, sm, tid);
    stage_h16<128, 256>(CTX, 128, Ml, xb, tid);
    cp_wait<0>();
    __syncthreads();
    {
        float C[16][4]; zero_C(C);
        panel_1p((const __half*)sm, (const __half*)xb, warp, lane, C);
        const int r0 = warp * 16 + g, r1 = r0 + 8;
#pragma unroll
        for (int t = 0; t < 16; t++) {
            int c = t * 8 + tg * 2;
            float2 bv = *(const float2*)(bx + c);
            if (r0 < Ml) {
                float2 o = make_float2(fmaxf(C[t][0] + bv.x, 0.f), fmaxf(C[t][1] + bv.y, 0.f));
                *(float2*)(CTH + (size_t)r0 * 128 + c) = o;
            }
            if (r1 < Ml) {
                float2 o = make_float2(fmaxf(C[t][2] + bv.x, 0.f), fmaxf(C[t][3] + bv.y, 0.f));
                *(float2*)(CTH + (size_t)r1 * 128 + c) = o;
            }
        }
        __threadfence_block();
        __syncthreads();
    }
    stage_h16<128, 256>(AC, 128, M1, xb, tid);
    cp_wait<0>();
    __syncthreads();
    {
        float C[16][4]; zero_C(C);
        panel_1p((const __half*)sm, (const __half*)xb, warp, lane, C);
        __syncthreads();
        combine_reg<false>(C, bx, CTH, O, nullptr, 0, M1, warp, g, tg);
    }
}

// ================= utility kernels =================
__global__ void convert_weights(
    const float* __restrict__ Ws, const float* __restrict__ Wc,
    const float* __restrict__ Wx, const float* __restrict__ Wf)
{
    int i = blockIdx.x * blockDim.x + threadIdx.x;
    int stride = gridDim.x * blockDim.x;
    for (int k = i; k < 16384; k += stride) {
        g_ws16[k] = __float2half_rn(Ws[k]);
        g_wc16[k] = __float2half_rn(Wc[k]);
        g_wx16[k] = __float2half_rn(Wx[k]);
    }
    for (int k = i; k < 32768; k += stride) {
        g_wf16[k] = __float2half_rn(Wf[k]);
    }
}

// convert ALL of initial: rows < NTOP -> g_init16, rows >= NTOP -> g_act (leaves)
__global__ void convert_init(const float4* __restrict__ in, long n8)
{
    const long split = (long)NTOP * 16;   // 8-elem chunks in the top section
    long i = (long)blockIdx.x * blockDim.x + threadIdx.x;
    long stride = (long)gridDim.x * blockDim.x;
    for (; i < n8; i += stride) {
        float4 a = in[2 * i], b = in[2 * i + 1];
        uint4 r;
        r.x = ((unsigned)__half_as_ushort(__float2half_rn(a.y))<<16) | __half_as_ushort(__float2half_rn(a.x));
        r.y = ((unsigned)__half_as_ushort(__float2half_rn(a.w))<<16) | __half_as_ushort(__float2half_rn(a.z));
        r.z = ((unsigned)__half_as_ushort(__float2half_rn(b.y))<<16) | __half_as_ushort(__float2half_rn(b.x));
        r.w = ((unsigned)__half_as_ushort(__float2half_rn(b.w))<<16) | __half_as_ushort(__float2half_rn(b.z));
        if (i < split) ((uint4*)g_init16)[i] = r;
        else           ((uint4*)g_act)[i] = r;   // same global element index
    }
}

__global__ void set_ones_h(__half* p)
{
    p[threadIdx.x] = __float2half(1.0f);
}

// ---------------- launch ----------------
static inline int grid64(int rows, int cap) {
    int nt = (rows + 63) >> 6;
    return nt < cap ? nt : cap;
}

extern "C" void kernel_launch(void* const* d_in, const int* in_sizes, int n_in,
                              void* d_out, int out_size)
{
    const float* initial = (const float*)d_in[0];
    const float* Ws = (const float*)d_in[1];
    const float* bs = (const float*)d_in[2];
    const float* Wc = (const float*)d_in[3];
    const float* bc = (const float*)d_in[4];
    const float* Wx = (const float*)d_in[5];
    const float* bx = (const float*)d_in[6];
    const float* Wf = (const float*)d_in[7];
    const float* bf = (const float*)d_in[8];
    const float* Wh = (const float*)d_in[9];
    const float* bh = (const float*)d_in[10];
    float* out = (float*)d_out;

    __half *act, *ctx, *t2, *init16, *ws16, *wc16, *wx16, *wf16;
    float* cth;
    cudaGetSymbolAddress((void**)&act,   g_act);
    cudaGetSymbolAddress((void**)&ctx,   g_ctx);
    cudaGetSymbolAddress((void**)&t2,    g_t2);
    cudaGetSymbolAddress((void**)&init16,g_init16);
    cudaGetSymbolAddress((void**)&cth,   g_cth);
    cudaGetSymbolAddress((void**)&ws16,  g_ws16);
    cudaGetSymbolAddress((void**)&wc16,  g_wc16);
    cudaGetSymbolAddress((void**)&wx16,  g_wx16);
    cudaGetSymbolAddress((void**)&wf16,  g_wf16);

    cudaFuncSetAttribute(up_mean4_64,          cudaFuncAttributeMaxDynamicSharedMemorySize, SMEM_64);
    cudaFuncSetAttribute(up_pairadd_64,        cudaFuncAttributeMaxDynamicSharedMemorySize, SMEM_64);
    cudaFuncSetAttribute(cth_64,               cudaFuncAttributeMaxDynamicSharedMemorySize, SMEM_64);
    cudaFuncSetAttribute(down_combine_f<true>, cudaFuncAttributeMaxDynamicSharedMemorySize, SMEM_64);
    cudaFuncSetAttribute(down_combine_f<false>,cudaFuncAttributeMaxDynamicSharedMemorySize, SMEM_64);
    cudaFuncSetAttribute(final_64,             cudaFuncAttributeMaxDynamicSharedMemorySize, SMEM_FIN);
    cudaFuncSetAttribute(up_small,             cudaFuncAttributeMaxDynamicSharedMemorySize, SMEM_SMALL);
    cudaFuncSetAttribute(down_small,           cudaFuncAttributeMaxDynamicSharedMemorySize, SMEM_SMALL);

    convert_weights<<<64, 256>>>(Ws, Wc, Wx, Wf);
    convert_init<<<2048, 256>>>((const float4*)initial, (long)N_TOTAL * DIM / 8);

    // ---- up pass: levels 5..2 ----
    for (int l = 5; l >= 2; l--) {
        int M1 = H_SIZES[l + 1];
        int G  = M1 >> 2;
        up_mean4_64<<<grid64(M1, 444), 128, SMEM_64>>>(
            act + (size_t)H_OFFS[l + 1] * DIM, ws16, bs, t2, M1);
        up_pairadd_64<<<grid64(G, 444), 128, SMEM_64>>>(
            t2, wc16, bc, init16 + (size_t)H_OFFS[l] * DIM,
            act + (size_t)H_OFFS[l] * DIM, G);
    }
    for (int l = 1; l >= 0; l--) {
        up_small<<<1, 256, SMEM_SMALL>>>(
            act + (size_t)H_OFFS[l + 1] * DIM,
            init16 + (size_t)H_OFFS[l] * DIM,
            act + (size_t)H_OFFS[l] * DIM,
            ws16, bs, wc16, bc, t2, H_SIZES[l + 1]);
    }

    // ---- down pass ----
    set_ones_h<<<1, 128>>>(ctx);
    for (int l = 0; l < 2; l++) {
        down_small<<<1, 256, SMEM_SMALL>>>(
            ctx + (size_t)H_OFFS[l] * DIM,
            act + (size_t)H_OFFS[l + 1] * DIM,
            wx16, bx, cth + (size_t)CTH_OFF[l] * DIM /*scratch (l=0: 1 row; l=1: 8 rows)*/,
            ctx + (size_t)H_OFFS[l + 1] * DIM, H_SIZES[l], H_SIZES[l + 1]);
    }
    // cth(2) on ctx(2) rows (64 rows)
    cth_64<<<1, 128, SMEM_64>>>(
        ctx + (size_t)H_OFFS[2] * DIM, wx16, bx,
        cth + (size_t)CTH_OFF[2] * DIM, H_SIZES[2]);
    // l = 2..4: combine + fused cth(l+1); l = 5: combine only
    for (int l = 2; l < 6; l++) {
        int M1 = H_SIZES[l + 1];
        if (l < 5)
            down_combine_f<true><<<grid64(M1, 444), 128, SMEM_64>>>(
                act + (size_t)H_OFFS[l + 1] * DIM, wx16, bx,
                cth + (size_t)CTH_OFF[l] * DIM,
                ctx + (size_t)H_OFFS[l + 1] * DIM,
                cth + (size_t)CTH_OFF[l + 1] * DIM, M1);
        else
            down_combine_f<false><<<grid64(M1, 444), 128, SMEM_64>>>(
                act + (size_t)H_OFFS[l + 1] * DIM, wx16, bx,
                cth + (size_t)CTH_OFF[l] * DIM,
                ctx + (size_t)H_OFFS[l + 1] * DIM,
                nullptr, M1);
    }

    // ---- final ----
    final_64<<<296, 128, SMEM_FIN>>>(
        ctx, act, wf16, bf, Wh, bh, out, N_TOTAL);
}

// round 17
// speedup vs baseline: 3.0420x; 1.0427x over previous
#include <cuda_runtime.h>
#include <cuda_fp16.h>
#include <cstdint>

#define DIM 128
#define N_TOTAL 299593
#define NTOP 37449
#define NLEAF 262144

static const int H_SIZES[7] = {1, 8, 64, 512, 4096, 32768, 262144};
static const int H_OFFS[8]  = {0, 1, 9, 73, 585, 4681, 37449, 299593};
static const int CTH_OFF[6] = {0, 0, 0, 64, 576, 4672};

// ---------------- scratch ----------------
__device__ __half g_act[N_TOTAL * DIM];
__device__ __half g_ctx[NTOP * DIM];        // ctx only for non-leaf rows now
__device__ __half g_t2 [65536 * DIM];
__device__ __half g_init16[NTOP * DIM];
__device__ float  g_cth[37440 * DIM];
__device__ __half g_ws16[128 * 128];
__device__ __half g_wc16[128 * 128];
__device__ __half g_wx16[128 * 128];
__device__ __half g_wf16[128 * 256];

// ================= common =================
#define SPITCH 136
#define WB     34816
#define XB64   17408

#define SMEM_64    (WB + 2 * XB64)      // 69632  -> 3 blocks/SM
#define SMEM_FIN   (2 * WB + 2 * XB64)  // 104448 -> 2 blocks/SM
#define SMEM_SMALL (2 * WB)             // 69632
#define SMEM_LF    (6 * WB)             // 208896 -> 1 block/SM (256 thr)

__device__ __forceinline__ uint32_t smem_u32(const void* p) {
    return (uint32_t)__cvta_generic_to_shared(p);
}
__device__ __forceinline__ uint4 pack8h(float4 a, float4 b) {
    uint4 r;
    r.x = ((unsigned)__half_as_ushort(__float2half_rn(a.y))<<16) | __half_as_ushort(__float2half_rn(a.x));
    r.y = ((unsigned)__half_as_ushort(__float2half_rn(a.w))<<16) | __half_as_ushort(__float2half_rn(a.z));
    r.z = ((unsigned)__half_as_ushort(__float2half_rn(b.y))<<16) | __half_as_ushort(__float2half_rn(b.x));
    r.w = ((unsigned)__half_as_ushort(__float2half_rn(b.w))<<16) | __half_as_ushort(__float2half_rn(b.z));
    return r;
}
__device__ __forceinline__ void cp16(unsigned saddr, const void* gptr, int sz) {
    asm volatile("cp.async.cg.shared.global [%0], [%1], 16, %2;"
                 :: "r"(saddr), "l"(gptr), "r"(sz));
}
template<int N>
__device__ __forceinline__ void cp_wait() {
    asm volatile("cp.async.wait_group %0;" :: "n"(N) : "memory");
}
__device__ __forceinline__ void cp_commit() {
    asm volatile("cp.async.commit_group;");
}

__device__ __forceinline__ void mma_f16(float* c, const unsigned* a, unsigned b0, unsigned b1)
{
    asm volatile(
        "mma.sync.aligned.m16n8k16.row.col.f32.f16.f16.f32 "
        "{%0,%1,%2,%3},{%4,%5,%6,%7},{%8,%9},{%0,%1,%2,%3};\n"
        : "+f"(c[0]), "+f"(c[1]), "+f"(c[2]), "+f"(c[3])
        : "r"(a[0]), "r"(a[1]), "r"(a[2]), "r"(a[3]), "r"(b0), "r"(b1));
}
__device__ __forceinline__ void ldsm4(unsigned* r, unsigned addr)
{
    asm volatile("ldmatrix.sync.aligned.m8n8.x4.shared.b16 {%0,%1,%2,%3}, [%4];"
                 : "=r"(r[0]), "=r"(r[1]), "=r"(r[2]), "=r"(r[3]) : "r"(addr));
}

template <int NROWS, int NTHR>
__device__ __forceinline__ void stage_h16(
    const __half* __restrict__ G, int gstride, int rows_valid, char* buf, int tid)
{
    unsigned hB = smem_u32(buf);
#pragma unroll
    for (int i = tid; i < NROWS * 16; i += NTHR) {
        int r = i >> 4, c = i & 15;
        unsigned so = (unsigned)r * 272 + c * 16;
        int sz = (r < rows_valid) ? 16 : 0;
        cp16(hB + so, G + (size_t)r * gstride + c * 8, sz);
    }
    cp_commit();
}

// leaf staging: fp32 -> pitched smem AND fp16 global plane (64 rows, 128 thr)
__device__ __forceinline__ void stage_leaf_store(
    const float* __restrict__ F32, int grow0, __half* __restrict__ actout,
    char* buf, int tid)
{
#pragma unroll
    for (int i = tid; i < 1024; i += 128) {
        int r = i >> 4, c = i & 15;
        int gr = grow0 + r;
        float4 a = *(const float4*)(F32 + (size_t)gr * 128 + c * 8);
        float4 b = *(const float4*)(F32 + (size_t)gr * 128 + c * 8 + 4);
        uint4 p = pack8h(a, b);
        *(uint4*)(buf + (size_t)r * 272 + c * 16) = p;
        *(uint4*)((char*)(actout + (size_t)gr * 128 + c * 8)) = p;
    }
}

// ---- mainloop: single-pass fp16, B fragments preloaded ----
__device__ __forceinline__ void panel_1p(
    const __half* sW, const __half* sX, int warp, int lane, float C[16][4])
{
    const unsigned wh = smem_u32(sW);
    const unsigned xh = smem_u32(sX);
    const unsigned PB = SPITCH * 2;
    const unsigned aoff0 = (unsigned)(warp * 16 + (lane & 15)) * PB + (unsigned)((lane >> 4) & 1) * 16u;
    const unsigned boff0 = (unsigned)((lane & 7) + ((lane & 16) >> 1)) * PB + ((lane & 8) ? 16u : 0u);

    for (int kc = 0; kc < 8; kc++) {
        const unsigned ka = kc * 32;
        unsigned ah[4];
        ldsm4(ah, xh + aoff0 + ka);
        unsigned bhi[8][4];
#pragma unroll
        for (int p = 0; p < 8; p++) ldsm4(bhi[p], wh + boff0 + (unsigned)p * 16 * PB + ka);
#pragma unroll
        for (int p = 0; p < 8; p++) {
            mma_f16(C[2*p],   ah, bhi[p][0], bhi[p][1]);
            mma_f16(C[2*p+1], ah, bhi[p][2], bhi[p][3]);
        }
    }
}

__device__ __forceinline__ void zero_C(float C[16][4])
{
#pragma unroll
    for (int t = 0; t < 16; t++) C[t][0] = C[t][1] = C[t][2] = C[t][3] = 0.f;
}

// ================= register-shuffle reduce epilogues =================

__device__ __forceinline__ void mean4_reg(
    const float C[16][4], const float* __restrict__ bias,
    __half* __restrict__ T2, int out_base, int G, int warp, int g, int tg)
{
    const unsigned F = 0xffffffffu;
    int og0 = out_base + warp * 4;
#pragma unroll
    for (int tt = 0; tt < 16; tt++) {
        int c = tt * 8 + tg * 2;
        float2 b = *(const float2*)(bias + c);
        float v0 = fmaxf(C[tt][0]+b.x,0.f), v1 = fmaxf(C[tt][1]+b.y,0.f);
        float w0 = fmaxf(C[tt][2]+b.x,0.f), w1 = fmaxf(C[tt][3]+b.y,0.f);
        v0 += __shfl_xor_sync(F,v0,4); v0 += __shfl_xor_sync(F,v0,8);
        v1 += __shfl_xor_sync(F,v1,4); v1 += __shfl_xor_sync(F,v1,8);
        w0 += __shfl_xor_sync(F,w0,4); w0 += __shfl_xor_sync(F,w0,8);
        w1 += __shfl_xor_sync(F,w1,4); w1 += __shfl_xor_sync(F,w1,8);
        if ((g & 3) == 0) {
            int q = g >> 2;
            if (og0 + q < G)
                *(__half2*)(T2 + (size_t)(og0+q)*128 + c) = __floats2half2_rn(0.25f*v0, 0.25f*v1);
            if (og0 + 2 + q < G)
                *(__half2*)(T2 + (size_t)(og0+2+q)*128 + c) = __floats2half2_rn(0.25f*w0, 0.25f*w1);
        }
    }
}

__device__ __forceinline__ void pairadd_reg(
    const float C[16][4], const float* __restrict__ bias,
    const __half* __restrict__ init16, __half* __restrict__ A,
    int out_base, int Mout, int warp, int g, int tg)
{
    const unsigned F = 0xffffffffu;
    int og0 = out_base + warp * 8;
#pragma unroll
    for (int tt = 0; tt < 16; tt++) {
        int c = tt * 8 + tg * 2;
        float2 b = *(const float2*)(bias + c);
        float v0 = fmaxf(C[tt][0]+b.x,0.f), v1 = fmaxf(C[tt][1]+b.y,0.f);
        float w0 = fmaxf(C[tt][2]+b.x,0.f), w1 = fmaxf(C[tt][3]+b.y,0.f);
        v0 += __shfl_xor_sync(F,v0,4);
        v1 += __shfl_xor_sync(F,v1,4);
        w0 += __shfl_xor_sync(F,w0,4);
        w1 += __shfl_xor_sync(F,w1,4);
        if ((g & 1) == 0) {
            int p = g >> 1;
            int og = og0 + p;
            if (og < Mout) {
                float2 iv = __half22float2(*(const __half2*)(init16 + (size_t)og*128 + c));
                *(__half2*)(A + (size_t)og*128 + c) =
                    __floats2half2_rn(iv.x + 0.5f*v0, iv.y + 0.5f*v1);
            }
            int og2 = og0 + 4 + p;
            if (og2 < Mout) {
                float2 iv = __half22float2(*(const __half2*)(init16 + (size_t)og2*128 + c));
                *(__half2*)(A + (size_t)og2*128 + c) =
                    __floats2half2_rn(iv.x + 0.5f*w0, iv.y + 0.5f*w1);
            }
        }
    }
}

// combine with optional global / smem outputs (either pointer may be null-like via flags)
template <bool TO_GLOBAL, bool TO_SMEM>
__device__ __forceinline__ void combine_reg(
    const float C[16][4], const float* __restrict__ bias,
    const float* __restrict__ CTH, __half* __restrict__ O, char* Osm,
    int row_base, int M1, int warp, int g, int tg)
{
    const unsigned F = 0xffffffffu;
    int lr0 = warp * 16 + g, lr1 = lr0 + 8;
    int r0 = row_base + lr0, r1 = row_base + lr1;
    int p0 = (row_base + warp * 16) >> 3;
#pragma unroll
    for (int tt = 0; tt < 16; tt++) {
        int c = tt * 8 + tg * 2;
        float2 b = *(const float2*)(bias + c);
        float v0 = fmaxf(C[tt][0]+b.x,0.f), v1 = fmaxf(C[tt][1]+b.y,0.f);
        float w0 = fmaxf(C[tt][2]+b.x,0.f), w1 = fmaxf(C[tt][3]+b.y,0.f);
        float s0 = v0 + __shfl_xor_sync(F,v0,4); s0 += __shfl_xor_sync(F,s0,8);
        float s1 = v1 + __shfl_xor_sync(F,v1,4); s1 += __shfl_xor_sync(F,s1,8);
        float u0 = w0 + __shfl_xor_sync(F,w0,4); u0 += __shfl_xor_sync(F,u0,8);
        float u1 = w1 + __shfl_xor_sync(F,w1,4); u1 += __shfl_xor_sync(F,u1,8);
        if (r0 < M1) {
            float2 cv = *(const float2*)(CTH + (size_t)p0*128 + c);
            __half2 h = __floats2half2_rn(0.25f*(cv.x + s0 - v0), 0.25f*(cv.y + s1 - v1));
            if (TO_GLOBAL) *(__half2*)(O + (size_t)r0*128 + c) = h;
            if (TO_SMEM)   *(__half2*)(Osm + (size_t)lr0*272 + c*2) = h;
        }
        if (r1 < M1) {
            float2 cv = *(const float2*)(CTH + (size_t)(p0+1)*128 + c);
            __half2 h = __floats2half2_rn(0.25f*(cv.x + u0 - w0), 0.25f*(cv.y + u1 - w1));
            if (TO_GLOBAL) *(__half2*)(O + (size_t)r1*128 + c) = h;
            if (TO_SMEM)   *(__half2*)(Osm + (size_t)lr1*272 + c*2) = h;
        }
    }
}

// ================= 64-row-tile level kernels =================

template <bool LEAF>
__global__ void __launch_bounds__(128, 3) up_mean4_64(
    const __half* __restrict__ X, const float* __restrict__ Xf32,
    __half* __restrict__ actout,
    const __half* __restrict__ W16, const float* __restrict__ bias,
    __half* __restrict__ T2, int M1)
{
    extern __shared__ __align__(1024) char sm[];
    const int tid = threadIdx.x, lane = tid & 31, warp = tid >> 5;
    const int g = lane >> 2, tg = lane & 3;
    stage_h16<128,128>(W16, 128, 128, sm, tid);
    const int ntiles = M1 >> 6;
    int t = blockIdx.x;
    if (!LEAF && t < ntiles) stage_h16<64,128>(X + (size_t)t * 8192, 128, 64, sm + WB, tid);
    for (int phase = 0; t < ntiles; t += gridDim.x, phase++) {
        int cur = 0;
        if (LEAF) {
            stage_leaf_store(Xf32, t * 64, actout, sm + WB, tid);
            cp_wait<0>();
        } else {
            cur = phase & 1;
            int tn = t + gridDim.x;
            if (tn < ntiles) {
                stage_h16<64,128>(X + (size_t)tn * 8192, 128, 64, sm + WB + (1 ^ cur) * XB64, tid);
                cp_wait<1>();
            } else cp_wait<0>();
        }
        __syncthreads();
        float C[16][4]; zero_C(C);
        panel_1p((const __half*)sm, (const __half*)(sm + WB + cur * XB64), warp, lane, C);
        __syncthreads();
        mean4_reg(C, bias, T2, t * 16, M1 >> 2, warp, g, tg);
    }
}

__global__ void __launch_bounds__(128, 3) up_pairadd_64(
    const __half* __restrict__ X, const __half* __restrict__ W16,
    const float* __restrict__ bias, const __half* __restrict__ init16,
    __half* __restrict__ A, int G)
{
    extern __shared__ __align__(1024) char sm[];
    const int tid = threadIdx.x, lane = tid & 31, warp = tid >> 5;
    const int g = lane >> 2, tg = lane & 3;
    stage_h16<128,128>(W16, 128, 128, sm, tid);
    const int ntiles = G >> 6;
    int t = blockIdx.x;
    if (t < ntiles) stage_h16<64,128>(X + (size_t)t * 8192, 128, 64, sm + WB, tid);
    for (int phase = 0; t < ntiles; t += gridDim.x, phase++) {
        int cur = phase & 1;
        int tn = t + gridDim.x;
        if (tn < ntiles) {
            stage_h16<64,128>(X + (size_t)tn * 8192, 128, 64, sm + WB + (1 ^ cur) * XB64, tid);
            cp_wait<1>();
        } else cp_wait<0>();
        __syncthreads();
        float C[16][4]; zero_C(C);
        panel_1p((const __half*)sm, (const __half*)(sm + WB + cur * XB64), warp, lane, C);
        __syncthreads();
        pairadd_reg(C, bias, init16, A, t * 32, G >> 1, warp, g, tg);
    }
}

__global__ void __launch_bounds__(128, 3) cth_64(
    const __half* __restrict__ X, const __half* __restrict__ W16,
    const float* __restrict__ bias, float* __restrict__ Y, int M)
{
    extern __shared__ __align__(1024) char sm[];
    const int tid = threadIdx.x, lane = tid & 31, warp = tid >> 5;
    const int g = lane >> 2, tg = lane & 3;
    stage_h16<128,128>(W16, 128, 128, sm, tid);
    const int ntiles = (M + 63) >> 6;
    int t = blockIdx.x;
    if (t < ntiles) {
        int rv = M - t * 64; if (rv > 64) rv = 64;
        stage_h16<64,128>(X + (size_t)t * 8192, 128, rv, sm + WB, tid);
    }
    for (int phase = 0; t < ntiles; t += gridDim.x, phase++) {
        int cur = phase & 1;
        int tn = t + gridDim.x;
        if (tn < ntiles) {
            int rv = M - tn * 64; if (rv > 64) rv = 64;
            stage_h16<64,128>(X + (size_t)tn * 8192, 128, rv, sm + WB + (1 ^ cur) * XB64, tid);
            cp_wait<1>();
        } else cp_wait<0>();
        __syncthreads();
        float C[16][4]; zero_C(C);
        panel_1p((const __half*)sm, (const __half*)(sm + WB + cur * XB64), warp, lane, C);
        __syncthreads();
        const int r0g = t * 64 + warp * 16 + g, r1g = r0g + 8;
#pragma unroll
        for (int tt = 0; tt < 16; tt++) {
            int c = tt * 8 + tg * 2;
            float2 bv = *(const float2*)(bias + c);
            if (r0g < M) {
                float2 o = make_float2(fmaxf(C[tt][0] + bv.x, 0.f), fmaxf(C[tt][1] + bv.y, 0.f));
                *(float2*)(Y + (size_t)r0g * 128 + c) = o;
            }
            if (r1g < M) {
                float2 o = make_float2(fmaxf(C[tt][2] + bv.x, 0.f), fmaxf(C[tt][3] + bv.y, 0.f));
                *(float2*)(Y + (size_t)r1g * 128 + c) = o;
            }
        }
    }
}

// down-combine for mid levels; always emits cth(l+1) via a second panel.
__global__ void __launch_bounds__(128, 3) down_combine_f(
    const __half* __restrict__ X, const __half* __restrict__ W16,
    const float* __restrict__ bias, const float* __restrict__ CTH_in,
    __half* __restrict__ O, float* __restrict__ CTH_out, int M1)
{
    extern __shared__ __align__(1024) char sm[];
    const int tid = threadIdx.x, lane = tid & 31, warp = tid >> 5;
    const int g = lane >> 2, tg = lane & 3;
    stage_h16<128,128>(W16, 128, 128, sm, tid);
    const int ntiles = M1 >> 6;
    int t = blockIdx.x;
    if (t < ntiles) stage_h16<64,128>(X + (size_t)t * 8192, 128, 64, sm + WB, tid);
    for (int phase = 0; t < ntiles; t += gridDim.x, phase++) {
        int cur = phase & 1;
        char* Xc = sm + WB + cur * XB64;
        int tn = t + gridDim.x;
        if (tn < ntiles) {
            stage_h16<64,128>(X + (size_t)tn * 8192, 128, 64, sm + WB + (1 ^ cur) * XB64, tid);
            cp_wait<1>();
        } else cp_wait<0>();
        __syncthreads();
        float C[16][4]; zero_C(C);
        panel_1p((const __half*)sm, (const __half*)Xc, warp, lane, C);
        __syncthreads();
        combine_reg<true, true>(C, bias, CTH_in, O, Xc, t * 64, M1, warp, g, tg);
        __syncthreads();
        float D[16][4]; zero_C(D);
        panel_1p((const __half*)sm, (const __half*)Xc, warp, lane, D);
        const int r0g = t * 64 + warp * 16 + g, r1g = r0g + 8;
#pragma unroll
        for (int tt = 0; tt < 16; tt++) {
            int c = tt * 8 + tg * 2;
            float2 bv = *(const float2*)(bias + c);
            float2 o0 = make_float2(fmaxf(D[tt][0] + bv.x, 0.f), fmaxf(D[tt][1] + bv.y, 0.f));
            float2 o1 = make_float2(fmaxf(D[tt][2] + bv.x, 0.f), fmaxf(D[tt][3] + bv.y, 0.f));
            if (r0g < M1) *(float2*)(CTH_out + (size_t)r0g * 128 + c) = o0;
            if (r1g < M1) *(float2*)(CTH_out + (size_t)r1g * 128 + c) = o1;
        }
        __syncthreads();
    }
}

// ================= leaf mega-kernel: combine + final fused (256 thr, 1 blk/SM) =================
// smem: Wx @0, Wf0 @WB, Wf1 @2WB, X0 @3WB, X1 @4WB, CT @5WB
__global__ void __launch_bounds__(256, 1) leaf_fused(
    const __half* __restrict__ ACT_LEAF, const __half* __restrict__ Wx16,
    const __half* __restrict__ Wf16,
    const float* __restrict__ bx, const float* __restrict__ bf,
    const float* __restrict__ Wh, const float* __restrict__ bh,
    const float* __restrict__ CTH, float* __restrict__ out)
{
    extern __shared__ __align__(1024) char sm[];
    const int tid = threadIdx.x, lane = tid & 31, warp = tid >> 5;
    const int g = lane >> 2, tg = lane & 3;
    char* X0 = sm + 3 * WB;
    char* X1 = sm + 4 * WB;
    char* CT = sm + 5 * WB;

    stage_h16<128,256>(Wx16,        128, 128, sm,          tid);
    stage_h16<128,256>(Wf16,        256, 128, sm + WB,     tid);
    stage_h16<128,256>(Wf16 + 128,  256, 128, sm + 2 * WB, tid);

    const int ntiles = NLEAF >> 7;   // 2048
    int t = blockIdx.x;
    if (t < ntiles) stage_h16<128,256>(ACT_LEAF + (size_t)t * 16384, 128, 128, X0, tid);
    for (int phase = 0; t < ntiles; t += gridDim.x, phase++) {
        int cur = phase & 1;
        char* Xc = cur ? X1 : X0;
        int tn = t + gridDim.x;
        if (tn < ntiles) {
            stage_h16<128,256>(ACT_LEAF + (size_t)tn * 16384, 128, 128, cur ? X0 : X1, tid);
            cp_wait<1>();
        } else cp_wait<0>();
        __syncthreads();
        // 1. combine: ctx tile -> CT (smem only)
        float C[16][4]; zero_C(C);
        panel_1p((const __half*)sm, (const __half*)Xc, warp, lane, C);
        combine_reg<false, true>(C, bx, CTH, nullptr, CT, t * 128, NLEAF, warp, g, tg);
        __syncthreads();
        // 2. final: Wf0 @ ctx + Wf1 @ act, then dot with Wh
        float D[16][4]; zero_C(D);
        panel_1p((const __half*)(sm + WB),     (const __half*)CT, warp, lane, D);
        panel_1p((const __half*)(sm + 2 * WB), (const __half*)Xc, warp, lane, D);
        float s0 = 0.f, s1 = 0.f;
#pragma unroll
        for (int tt = 0; tt < 16; tt++) {
            int c = tt * 8 + tg * 2;
            float2 bv = *(const float2*)(bf + c);
            float2 wv = *(const float2*)(Wh + c);
            s0 += fmaxf(D[tt][0] + bv.x, 0.f) * wv.x + fmaxf(D[tt][1] + bv.y, 0.f) * wv.y;
            s1 += fmaxf(D[tt][2] + bv.x, 0.f) * wv.x + fmaxf(D[tt][3] + bv.y, 0.f) * wv.y;
        }
        s0 += __shfl_xor_sync(0xffffffffu, s0, 1);
        s0 += __shfl_xor_sync(0xffffffffu, s0, 2);
        s1 += __shfl_xor_sync(0xffffffffu, s1, 1);
        s1 += __shfl_xor_sync(0xffffffffu, s1, 2);
        if (tg == 0) {
            int r0g = t * 128 + warp * 16 + g, r1g = r0g + 8;
            float bhv = bh[0];
            out[NTOP + r0g] = s0 + bhv;
            out[NTOP + r1g] = s1 + bhv;
        }
        __syncthreads();
    }
}

// ================= final kernel for top rows (128 thr, 2 blk/SM) =================
__global__ void __launch_bounds__(128, 2) final_64(
    const __half* __restrict__ CTX, const __half* __restrict__ ACT,
    const __half* __restrict__ Wf16, const float* __restrict__ bf,
    const float* __restrict__ Wh, const float* __restrict__ bh,
    float* __restrict__ out, int M)
{
    extern __shared__ __align__(1024) char sm[];
    const int tid = threadIdx.x, lane = tid & 31, warp = tid >> 5;
    const int g = lane >> 2, tg = lane & 3;
    char* X0 = sm + 2 * WB;
    char* X1 = sm + 2 * WB + XB64;

    stage_h16<128, 128>(Wf16,       256, 128, sm,      tid);
    stage_h16<128, 128>(Wf16 + 128, 256, 128, sm + WB, tid);

    const int ntiles = (M + 63) >> 6;
    int t = blockIdx.x;
    if (t < ntiles) {
        int rv = M - t * 64; if (rv > 64) rv = 64;
        stage_h16<64, 128>(CTX + (size_t)t * 8192, 128, rv, X0, tid);
    }
    for (; t < ntiles; t += gridDim.x) {
        int rv = M - t * 64; if (rv > 64) rv = 64;
        stage_h16<64, 128>(ACT + (size_t)t * 8192, 128, rv, X1, tid);
        cp_wait<1>();
        __syncthreads();
        float C[16][4]; zero_C(C);
        panel_1p((const __half*)sm, (const __half*)X0, warp, lane, C);
        __syncthreads();
        int tn = t + gridDim.x;
        if (tn < ntiles) {
            int rv2 = M - tn * 64; if (rv2 > 64) rv2 = 64;
            stage_h16<64, 128>(CTX + (size_t)tn * 8192, 128, rv2, X0, tid);
            cp_wait<1>();
        } else cp_wait<0>();
        __syncthreads();
        panel_1p((const __half*)(sm + WB), (const __half*)X1, warp, lane, C);
        __syncthreads();
        float s0 = 0.f, s1 = 0.f;
#pragma unroll
        for (int tt = 0; tt < 16; tt++) {
            int c = tt * 8 + tg * 2;
            float2 bv = *(const float2*)(bf + c);
            float2 wv = *(const float2*)(Wh + c);
            s0 += fmaxf(C[tt][0] + bv.x, 0.f) * wv.x + fmaxf(C[tt][1] + bv.y, 0.f) * wv.y;
            s1 += fmaxf(C[tt][2] + bv.x, 0.f) * wv.x + fmaxf(C[tt][3] + bv.y, 0.f) * wv.y;
        }
        s0 += __shfl_xor_sync(0xffffffffu, s0, 1);
        s0 += __shfl_xor_sync(0xffffffffu, s0, 2);
        s1 += __shfl_xor_sync(0xffffffffu, s1, 1);
        s1 += __shfl_xor_sync(0xffffffffu, s1, 2);
        if (tg == 0) {
            int r0g = t * 64 + warp * 16 + g, r1g = r0g + 8;
            float bhv = bh[0];
            if (r0g < M) out[r0g] = s0 + bhv;
            if (r1g < M) out[r1g] = s1 + bhv;
        }
    }
}

// ================= tiny-level kernels (256 threads, single block) =================
__global__ void __launch_bounds__(256) up_small(
    const __half* __restrict__ Xc, const __half* __restrict__ init16,
    __half* __restrict__ A,
    const __half* __restrict__ Ws16, const float* __restrict__ bs,
    const __half* __restrict__ Wc16, const float* __restrict__ bc,
    __half* __restrict__ T2, int M1)
{
    extern __shared__ __align__(1024) char sm[];
    char* xb = sm + WB;
    const int tid = threadIdx.x, lane = tid & 31, warp = tid >> 5;
    const int g = lane >> 2, tg = lane & 3;
    const int G = M1 >> 2, Mout = M1 >> 3;

    stage_h16<128, 256>(Ws16, 128, 128, sm, tid);
    stage_h16<128, 256>(Xc, 128, M1, xb, tid);
    cp_wait<0>();
    __syncthreads();
    {
        float C[16][4]; zero_C(C);
        panel_1p((const __half*)sm, (const __half*)xb, warp, lane, C);
        __syncthreads();
        mean4_reg(C, bs, T2, 0, G, warp, g, tg);
        __threadfence_block();
        __syncthreads();
    }
    stage_h16<128, 256>(Wc16, 128, 128, sm, tid);
    stage_h16<128, 256>(T2, 128, G, xb, tid);
    cp_wait<0>();
    __syncthreads();
    {
        float C[16][4]; zero_C(C);
        panel_1p((const __half*)sm, (const __half*)xb, warp, lane, C);
        __syncthreads();
        pairadd_reg(C, bc, init16, A, 0, Mout, warp, g, tg);
    }
}

__global__ void __launch_bounds__(256) down_small(
    const __half* __restrict__ CTX, const __half* __restrict__ AC,
    const __half* __restrict__ Wx16, const float* __restrict__ bx,
    float* __restrict__ CTH, __half* __restrict__ O, int Ml, int M1)
{
    extern __shared__ __align__(1024) char sm[];
    char* xb = sm + WB;
    const int tid = threadIdx.x, lane = tid & 31, warp = tid >> 5;
    const int g = lane >> 2, tg = lane & 3;

    stage_h16<128, 256>(Wx16, 128, 128, sm, tid);
    stage_h16<128, 256>(CTX, 128, Ml, xb, tid);
    cp_wait<0>();
    __syncthreads();
    {
        float C[16][4]; zero_C(C);
        panel_1p((const __half*)sm, (const __half*)xb, warp, lane, C);
        const int r0 = warp * 16 + g, r1 = r0 + 8;
#pragma unroll
        for (int t = 0; t < 16; t++) {
            int c = t * 8 + tg * 2;
            float2 bv = *(const float2*)(bx + c);
            if (r0 < Ml) {
                float2 o = make_float2(fmaxf(C[t][0] + bv.x, 0.f), fmaxf(C[t][1] + bv.y, 0.f));
                *(float2*)(CTH + (size_t)r0 * 128 + c) = o;
            }
            if (r1 < Ml) {
                float2 o = make_float2(fmaxf(C[t][2] + bv.x, 0.f), fmaxf(C[t][3] + bv.y, 0.f));
                *(float2*)(CTH + (size_t)r1 * 128 + c) = o;
            }
        }
        __threadfence_block();
        __syncthreads();
    }
    stage_h16<128, 256>(AC, 128, M1, xb, tid);
    cp_wait<0>();
    __syncthreads();
    {
        float C[16][4]; zero_C(C);
        panel_1p((const __half*)sm, (const __half*)xb, warp, lane, C);
        __syncthreads();
        combine_reg<true, false>(C, bx, CTH, O, nullptr, 0, M1, warp, g, tg);
    }
}

// ================= utility kernels =================
__global__ void convert_weights(
    const float* __restrict__ Ws, const float* __restrict__ Wc,
    const float* __restrict__ Wx, const float* __restrict__ Wf)
{
    int i = blockIdx.x * blockDim.x + threadIdx.x;
    int stride = gridDim.x * blockDim.x;
    for (int k = i; k < 16384; k += stride) {
        g_ws16[k] = __float2half_rn(Ws[k]);
        g_wc16[k] = __float2half_rn(Wc[k]);
        g_wx16[k] = __float2half_rn(Wx[k]);
    }
    for (int k = i; k < 32768; k += stride) {
        g_wf16[k] = __float2half_rn(Wf[k]);
    }
}

// convert top (non-leaf) init rows only
__global__ void convert_init_top(const float4* __restrict__ in, long n8)
{
    long i = (long)blockIdx.x * blockDim.x + threadIdx.x;
    long stride = (long)gridDim.x * blockDim.x;
    for (; i < n8; i += stride) {
        float4 a = in[2 * i], b = in[2 * i + 1];
        ((uint4*)g_init16)[i] = pack8h(a, b);
    }
}

__global__ void set_ones_h(__half* p)
{
    p[threadIdx.x] = __float2half(1.0f);
}

// ---------------- launch ----------------
static inline int grid64(int rows, int cap) {
    int nt = (rows + 63) >> 6;
    return nt < cap ? nt : cap;
}

extern "C" void kernel_launch(void* const* d_in, const int* in_sizes, int n_in,
                              void* d_out, int out_size)
{
    const float* initial = (const float*)d_in[0];
    const float* Ws = (const float*)d_in[1];
    const float* bs = (const float*)d_in[2];
    const float* Wc = (const float*)d_in[3];
    const float* bc = (const float*)d_in[4];
    const float* Wx = (const float*)d_in[5];
    const float* bx = (const float*)d_in[6];
    const float* Wf = (const float*)d_in[7];
    const float* bf = (const float*)d_in[8];
    const float* Wh = (const float*)d_in[9];
    const float* bh = (const float*)d_in[10];
    float* out = (float*)d_out;

    __half *act, *ctx, *t2, *init16, *ws16, *wc16, *wx16, *wf16;
    float* cth;
    cudaGetSymbolAddress((void**)&act,    g_act);
    cudaGetSymbolAddress((void**)&ctx,    g_ctx);
    cudaGetSymbolAddress((void**)&t2,     g_t2);
    cudaGetSymbolAddress((void**)&init16, g_init16);
    cudaGetSymbolAddress((void**)&cth,    g_cth);
    cudaGetSymbolAddress((void**)&ws16,   g_ws16);
    cudaGetSymbolAddress((void**)&wc16,   g_wc16);
    cudaGetSymbolAddress((void**)&wx16,   g_wx16);
    cudaGetSymbolAddress((void**)&wf16,   g_wf16);

    cudaFuncSetAttribute(up_mean4_64<true>,  cudaFuncAttributeMaxDynamicSharedMemorySize, SMEM_64);
    cudaFuncSetAttribute(up_mean4_64<false>, cudaFuncAttributeMaxDynamicSharedMemorySize, SMEM_64);
    cudaFuncSetAttribute(up_pairadd_64,      cudaFuncAttributeMaxDynamicSharedMemorySize, SMEM_64);
    cudaFuncSetAttribute(cth_64,             cudaFuncAttributeMaxDynamicSharedMemorySize, SMEM_64);
    cudaFuncSetAttribute(down_combine_f,     cudaFuncAttributeMaxDynamicSharedMemorySize, SMEM_64);
    cudaFuncSetAttribute(leaf_fused,         cudaFuncAttributeMaxDynamicSharedMemorySize, SMEM_LF);
    cudaFuncSetAttribute(final_64,           cudaFuncAttributeMaxDynamicSharedMemorySize, SMEM_FIN);
    cudaFuncSetAttribute(up_small,           cudaFuncAttributeMaxDynamicSharedMemorySize, SMEM_SMALL);
    cudaFuncSetAttribute(down_small,         cudaFuncAttributeMaxDynamicSharedMemorySize, SMEM_SMALL);

    convert_weights<<<64, 256>>>(Ws, Wc, Wx, Wf);
    convert_init_top<<<1024, 256>>>((const float4*)initial, (long)NTOP * 16);

    // ---- up pass: l=5 converts leaves on the fly ----
    up_mean4_64<true><<<grid64(NLEAF, 444), 128, SMEM_64>>>(
        nullptr, initial + (size_t)NTOP * DIM, act + (size_t)NTOP * DIM,
        ws16, bs, t2, NLEAF);
    up_pairadd_64<<<grid64(NLEAF >> 2, 444), 128, SMEM_64>>>(
        t2, wc16, bc, init16 + (size_t)H_OFFS[5] * DIM,
        act + (size_t)H_OFFS[5] * DIM, NLEAF >> 2);
    for (int l = 4; l >= 2; l--) {
        int M1 = H_SIZES[l + 1];
        int G  = M1 >> 2;
        up_mean4_64<false><<<grid64(M1, 444), 128, SMEM_64>>>(
            act + (size_t)H_OFFS[l + 1] * DIM, nullptr, nullptr, ws16, bs, t2, M1);
        up_pairadd_64<<<grid64(G, 444), 128, SMEM_64>>>(
            t2, wc16, bc, init16 + (size_t)H_OFFS[l] * DIM,
            act + (size_t)H_OFFS[l] * DIM, G);
    }
    for (int l = 1; l >= 0; l--) {
        up_small<<<1, 256, SMEM_SMALL>>>(
            act + (size_t)H_OFFS[l + 1] * DIM,
            init16 + (size_t)H_OFFS[l] * DIM,
            act + (size_t)H_OFFS[l] * DIM,
            ws16, bs, wc16, bc, t2, H_SIZES[l + 1]);
    }

    // ---- down pass ----
    set_ones_h<<<1, 128>>>(ctx);
    for (int l = 0; l < 2; l++) {
        down_small<<<1, 256, SMEM_SMALL>>>(
            ctx + (size_t)H_OFFS[l] * DIM,
            act + (size_t)H_OFFS[l + 1] * DIM,
            wx16, bx, cth + (size_t)CTH_OFF[l] * DIM,
            ctx + (size_t)H_OFFS[l + 1] * DIM, H_SIZES[l], H_SIZES[l + 1]);
    }
    cth_64<<<1, 128, SMEM_64>>>(
        ctx + (size_t)H_OFFS[2] * DIM, wx16, bx,
        cth + (size_t)CTH_OFF[2] * DIM, H_SIZES[2]);
    for (int l = 2; l < 5; l++) {
        int M1 = H_SIZES[l + 1];
        down_combine_f<<<grid64(M1, 444), 128, SMEM_64>>>(
            act + (size_t)H_OFFS[l + 1] * DIM, wx16, bx,
            cth + (size_t)CTH_OFF[l] * DIM,
            ctx + (size_t)H_OFFS[l + 1] * DIM,
            cth + (size_t)CTH_OFF[l + 1] * DIM, M1);
    }

    // ---- leaves: combine + final fused (ctx never hits global) ----
    leaf_fused<<<148, 256, SMEM_LF>>>(
        act + (size_t)NTOP * DIM, wx16, wf16,
        bx, bf, Wh, bh,
        cth + (size_t)CTH_OFF[5] * DIM, out);

    // ---- final for top rows ----
    final_64<<<296, 128, SMEM_FIN>>>(
        ctx, act, wf16, bf, Wh, bh, out, NTOP);
}